// round 1
// baseline (speedup 1.0000x reference)
#include <cuda_runtime.h>

#define Bv 4
#define Hh 16
#define Ss 1024
#define Dd 1024
#define HDd 64
#define NP 257          // 2*128+1 relative buckets
#define NROW (Bv*Ss)    // 4096
#define BHS (Bv*Hh*Ss)  // 65536

// ---------------- scratch (device globals: allocation-free) ----------------
__device__ float g_q[BHS * HDd];
__device__ float g_k[BHS * HDd];
__device__ float g_v[BHS * HDd];
__device__ float g_qr[(size_t)BHS * NP];
__device__ float g_attn[(size_t)NROW * Dd];

// ---------------------------------------------------------------------------
// Generic NT GEMM: C = A @ B^T (+bias). A:[M,K] row-major, B:[N,K] row-major.
// 64x64 tile, BK=16, 256 threads, 4x4 register microtile.
// mode 0: C[m*N + n]          (plain)
// mode 1: headed store into [B,H,S,hd]:  n = h*64+d, m = b*1024+s
// N-bound predication supported (for N=257). M, K must be multiples of 64/16.
// ---------------------------------------------------------------------------
__global__ void gemm_nt(const float* __restrict__ A, const float* __restrict__ Bm,
                        const float* __restrict__ bias, float* __restrict__ C,
                        int M, int N, int K, int mode)
{
    __shared__ float As[16][68];
    __shared__ float Bs[16][68];
    const int m0 = blockIdx.y * 64;
    const int n0 = blockIdx.x * 64;
    const int t  = threadIdx.x;
    const int tx = t & 15, ty = t >> 4;
    const int lr = t >> 2;          // 0..63 row within tile
    const int lc = (t & 3) * 4;     // 0,4,8,12 col within BK

    float acc[4][4];
#pragma unroll
    for (int i = 0; i < 4; i++)
#pragma unroll
        for (int j = 0; j < 4; j++) acc[i][j] = 0.f;

    for (int k0 = 0; k0 < K; k0 += 16) {
        float4 a = *(const float4*)(A + (size_t)(m0 + lr) * K + k0 + lc);
        float4 b = make_float4(0.f, 0.f, 0.f, 0.f);
        if (n0 + lr < N)
            b = *(const float4*)(Bm + (size_t)(n0 + lr) * K + k0 + lc);
        As[lc + 0][lr] = a.x; As[lc + 1][lr] = a.y; As[lc + 2][lr] = a.z; As[lc + 3][lr] = a.w;
        Bs[lc + 0][lr] = b.x; Bs[lc + 1][lr] = b.y; Bs[lc + 2][lr] = b.z; Bs[lc + 3][lr] = b.w;
        __syncthreads();
#pragma unroll
        for (int kk = 0; kk < 16; kk++) {
            float4 af = *(const float4*)&As[kk][ty * 4];
            float4 bf = *(const float4*)&Bs[kk][tx * 4];
            float av[4] = {af.x, af.y, af.z, af.w};
            float bv[4] = {bf.x, bf.y, bf.z, bf.w};
#pragma unroll
            for (int i = 0; i < 4; i++)
#pragma unroll
                for (int j = 0; j < 4; j++) acc[i][j] += av[i] * bv[j];
        }
        __syncthreads();
    }

#pragma unroll
    for (int i = 0; i < 4; i++) {
        int m = m0 + ty * 4 + i;
#pragma unroll
        for (int j = 0; j < 4; j++) {
            int n = n0 + tx * 4 + j;
            if (n >= N) continue;
            float v = acc[i][j] + (bias ? bias[n] : 0.f);
            if (mode == 0) {
                C[(size_t)m * N + n] = v;
            } else {
                int bb = m >> 10, s = m & 1023;
                int h = n >> 6, d = n & 63;
                C[((((size_t)bb * Hh + h) << 10) + s) * HDd + d] = v;
            }
        }
    }
}

// ---------------------------------------------------------------------------
// Attention: one block per (b*H+h, 8 query rows). 256 threads.
// smem: qs[8][64] | ss[8][1024] | kt[64][68] | wr[8][257]   = 60448 B dynamic
// ---------------------------------------------------------------------------
__global__ void attn_kernel(const float* __restrict__ rel_v)
{
    extern __shared__ float sm[];
    float* qs = sm;                // 512
    float* ss = sm + 512;          // 8192
    float* kt = ss + 8192;         // 4352 (64 rows x 68)
    float* wr = kt + 4352;         // 2056

    const int t  = threadIdx.x;
    const int bh = blockIdx.y;          // 0..63
    const int i0 = blockIdx.x * 8;      // query row base
    const float* qbase = g_q + (size_t)bh * Ss * HDd;
    const float* kbase = g_k + (size_t)bh * Ss * HDd;
    const float* vbase = g_v + (size_t)bh * Ss * HDd;

    // load 8 q rows (contiguous 512 floats)
#pragma unroll
    for (int k = 0; k < 2; k++) {
        int idx = t + k * 256;
        qs[idx] = qbase[(size_t)i0 * HDd + idx];
    }

    // ---- scores: ss[r][j] = q_r . k_j ----
    const int jj = t & 63;
    const int rr = t >> 6;              // 0..3 (handles rows rr and rr+4)
    for (int kt0 = 0; kt0 < Ss; kt0 += 64) {
        __syncthreads();                // protects kt reuse + first-iter q visibility
#pragma unroll
        for (int k = 0; k < 4; k++) {
            int idx4 = t + k * 256;     // float4 units: 1024 total
            int row = idx4 >> 4;
            int c4  = (idx4 & 15) * 4;
            *(float4*)&kt[row * 68 + c4] =
                *(const float4*)(kbase + (size_t)(kt0 + row) * HDd + c4);
        }
        __syncthreads();
        float a0 = 0.f, a1 = 0.f;
#pragma unroll
        for (int d = 0; d < 64; d += 4) {
            float4 kv = *(const float4*)&kt[jj * 68 + d];
            float4 q0 = *(const float4*)&qs[rr * 64 + d];
            float4 q1 = *(const float4*)&qs[(rr + 4) * 64 + d];
            a0 += q0.x * kv.x + q0.y * kv.y + q0.z * kv.z + q0.w * kv.w;
            a1 += q1.x * kv.x + q1.y * kv.y + q1.z * kv.z + q1.w * kv.w;
        }
        ss[rr * 1024 + kt0 + jj]       = a0;
        ss[(rr + 4) * 1024 + kt0 + jj] = a1;
    }
    __syncthreads();

    // ---- add relative bias (gather from precomputed qr) + scale ----
    const float* qrb = g_qr + (size_t)bh * Ss * NP;
    for (int k = 0; k < 32; k++) {
        int idx = t + k * 256;
        int r = idx >> 10, j = idx & 1023;
        int i = i0 + r;
        int rel = j - i;
        rel = rel < -128 ? -128 : (rel > 128 ? 128 : rel);
        ss[idx] = (ss[idx] + qrb[(size_t)i * NP + rel + 128]) * 0.125f;
    }
    __syncthreads();

    // ---- softmax + wr histogram (one warp per row) ----
    {
        int r = t >> 5, lane = t & 31;
        float* row = ss + r * 1024;
        float mx = -1e30f;
        for (int j = lane; j < 1024; j += 32) mx = fmaxf(mx, row[j]);
#pragma unroll
        for (int o = 16; o > 0; o >>= 1) mx = fmaxf(mx, __shfl_xor_sync(0xffffffffu, mx, o));
        float sum = 0.f;
        for (int j = lane; j < 1024; j += 32) { float e = __expf(row[j] - mx); row[j] = e; sum += e; }
#pragma unroll
        for (int o = 16; o > 0; o >>= 1) sum += __shfl_xor_sync(0xffffffffu, sum, o);
        float inv = 1.f / sum;
        for (int j = lane; j < 1024; j += 32) row[j] *= inv;
        __syncwarp();

        // wr[r][p]: interior p -> single shifted weight; p=0 / p=256 -> clipped tail sums
        int i = i0 + r;
        float* wrow = wr + r * NP;
        for (int p = 1 + lane; p < 256; p += 32) {
            int j = i + p - 128;
            wrow[p] = (j >= 0 && j < 1024) ? row[j] : 0.f;
        }
        float s0 = 0.f;
        for (int j = lane; j <= i - 128; j += 32) s0 += row[j];
#pragma unroll
        for (int o = 16; o > 0; o >>= 1) s0 += __shfl_xor_sync(0xffffffffu, s0, o);
        float s2 = 0.f;
        for (int j = i + 128 + lane; j < 1024; j += 32) s2 += row[j];
#pragma unroll
        for (int o = 16; o > 0; o >>= 1) s2 += __shfl_xor_sync(0xffffffffu, s2, o);
        if (lane == 0) { wrow[0] = s0; wrow[256] = s2; }
    }

    // ---- out = w @ v  (accumulate 2 rows per thread) ----
    const int d  = t & 63;
    const int r2 = t >> 6;
    float a0 = 0.f, a1 = 0.f;
    for (int vt0 = 0; vt0 < Ss; vt0 += 64) {
        __syncthreads();
#pragma unroll
        for (int k = 0; k < 4; k++) {
            int idx4 = t + k * 256;
            int row = idx4 >> 4;
            int c4  = (idx4 & 15) * 4;
            *(float4*)&kt[row * 68 + c4] =
                *(const float4*)(vbase + (size_t)(vt0 + row) * HDd + c4);
        }
        __syncthreads();
#pragma unroll
        for (int j = 0; j < 64; j++) {
            float vv = kt[j * 68 + d];
            a0 += ss[r2 * 1024 + vt0 + j] * vv;
            a1 += ss[(r2 + 4) * 1024 + vt0 + j] * vv;
        }
    }

    // ---- out += wr @ rel_v ----
#pragma unroll 4
    for (int p = 0; p < NP; p++) {
        float rv = rel_v[p * 64 + d];
        a0 += wr[r2 * NP + p] * rv;
        a1 += wr[(r2 + 4) * NP + p] * rv;
    }

    const int bb = bh >> 4, h = bh & 15;
    g_attn[((size_t)bb * 1024 + i0 + r2) * 1024 + h * 64 + d]       = a0;
    g_attn[((size_t)bb * 1024 + i0 + r2 + 4) * 1024 + h * 64 + d]   = a1;
}

// ---------------------------------------------------------------------------
extern "C" void kernel_launch(void* const* d_in, const int* in_sizes, int n_in,
                              void* d_out, int out_size)
{
    const float* x     = (const float*)d_in[0];
    const float* Wq    = (const float*)d_in[1];
    const float* bq    = (const float*)d_in[2];
    const float* Wk    = (const float*)d_in[3];
    const float* bk    = (const float*)d_in[4];
    const float* Wv    = (const float*)d_in[5];
    const float* bv    = (const float*)d_in[6];
    const float* Wo    = (const float*)d_in[7];
    const float* bo    = (const float*)d_in[8];
    const float* rel_k = (const float*)d_in[9];
    const float* rel_v = (const float*)d_in[10];

    float *q, *k, *v, *qr, *attn;
    cudaGetSymbolAddress((void**)&q,    g_q);
    cudaGetSymbolAddress((void**)&k,    g_k);
    cudaGetSymbolAddress((void**)&v,    g_v);
    cudaGetSymbolAddress((void**)&qr,   g_qr);
    cudaGetSymbolAddress((void**)&attn, g_attn);

    const int SMEM_ATTN = 60448;
    cudaFuncSetAttribute(attn_kernel, cudaFuncAttributeMaxDynamicSharedMemorySize, SMEM_ATTN);

    dim3 blk(256);

    // Q/K/V projections -> headed layout [B,H,S,hd]
    dim3 gproj(Dd / 64, NROW / 64);                  // (16, 64)
    gemm_nt<<<gproj, blk>>>(x, Wq, bq, q, NROW, Dd, Dd, 1);
    gemm_nt<<<gproj, blk>>>(x, Wk, bk, k, NROW, Dd, Dd, 1);
    gemm_nt<<<gproj, blk>>>(x, Wv, bv, v, NROW, Dd, Dd, 1);

    // qr[b,h,i,p] = q_i . rel_k[p]   (N=257 predicated)
    dim3 gqr((NP + 63) / 64, BHS / 64);              // (5, 1024)
    gemm_nt<<<gqr, blk>>>(q, rel_k, nullptr, qr, BHS, NP, HDd, 0);

    // attention core
    attn_kernel<<<dim3(Ss / 8, Bv * Hh), blk, SMEM_ATTN>>>(rel_v);

    // output projection -> d_out
    dim3 gout(Dd / 64, NROW / 64);
    gemm_nt<<<gout, blk>>>(attn, Wo, bo, (float*)d_out, NROW, Dd, Dd, 0);
}

// round 3
// speedup vs baseline: 1.3273x; 1.3273x over previous
#include <cuda_runtime.h>
#include <cuda_bf16.h>
#include <cstdint>

#define Bv 4
#define Hh 16
#define Ss 1024
#define Dd 1024
#define HDd 64
#define NP 257          // 2*128+1 relative buckets
#define NROW (Bv*Ss)    // 4096
#define BHS (Bv*Hh*Ss)  // 65536

// ---------------- scratch (device globals: allocation-free) ----------------
__device__ float g_q[BHS * HDd];
__device__ float g_k[BHS * HDd];
__device__ float g_v[BHS * HDd];
__device__ float g_qr[(size_t)BHS * NP];
__device__ float g_attn[(size_t)NROW * Dd];
__device__ __nv_bfloat16 g_xh[(size_t)NROW * Dd];
__device__ __nv_bfloat16 g_xl[(size_t)NROW * Dd];
__device__ __nv_bfloat16 g_wh[(size_t)Dd * Dd];
__device__ __nv_bfloat16 g_wl[(size_t)Dd * Dd];

// ====================== PTX helpers (family-portable only) ======================
__device__ __forceinline__ uint32_t smem_u32(const void* p) {
    uint32_t a;
    asm("{ .reg .u64 t; cvta.to.shared.u64 t, %1; cvt.u32.u64 %0, t; }" : "=r"(a) : "l"(p));
    return a;
}

#define LDMX4(r0, r1, r2, r3, addr) \
    asm volatile("ldmatrix.sync.aligned.m8n8.x4.shared.b16 {%0,%1,%2,%3}, [%4];" \
                 : "=r"(r0), "=r"(r1), "=r"(r2), "=r"(r3) : "r"(addr))

#define MMA16816(c, a, b) \
    asm volatile("mma.sync.aligned.m16n8k16.row.col.f32.bf16.bf16.f32 " \
                 "{%0,%1,%2,%3}, {%4,%5,%6,%7}, {%8,%9}, {%0,%1,%2,%3};" \
                 : "+f"((c)[0]), "+f"((c)[1]), "+f"((c)[2]), "+f"((c)[3]) \
                 : "r"((a)[0]), "r"((a)[1]), "r"((a)[2]), "r"((a)[3]), \
                   "r"((b)[0]), "r"((b)[1]))

#define CP_ASYNC16(s, g) \
    asm volatile("cp.async.cg.shared.global [%0], [%1], 16;" :: "r"(s), "l"(g))
#define CP_COMMIT() asm volatile("cp.async.commit_group;" ::: "memory")
#define CP_WAIT(n)  asm volatile("cp.async.wait_group %0;" :: "n"(n) : "memory")

// ---------------------------------------------------------------------------
// split f32 -> (hi bf16, lo bf16):  hi = bf16(x), lo = bf16(x - hi)
// ---------------------------------------------------------------------------
__global__ void split_bf16_kernel(const float* __restrict__ in,
                                  __nv_bfloat16* __restrict__ hi,
                                  __nv_bfloat16* __restrict__ lo, int n4)
{
    int i = blockIdx.x * 256 + threadIdx.x;
    if (i >= n4) return;
    float4 v = ((const float4*)in)[i];
    float vv[4] = {v.x, v.y, v.z, v.w};
    __nv_bfloat16 h[4], l[4];
#pragma unroll
    for (int j = 0; j < 4; j++) {
        h[j] = __float2bfloat16(vv[j]);
        l[j] = __float2bfloat16(vv[j] - __bfloat162float(h[j]));
    }
    ((__nv_bfloat162*)hi)[i * 2 + 0] = __nv_bfloat162(h[0], h[1]);
    ((__nv_bfloat162*)hi)[i * 2 + 1] = __nv_bfloat162(h[2], h[3]);
    ((__nv_bfloat162*)lo)[i * 2 + 0] = __nv_bfloat162(l[0], l[1]);
    ((__nv_bfloat162*)lo)[i * 2 + 1] = __nv_bfloat162(l[2], l[3]);
}

// ---------------------------------------------------------------------------
// Warp-MMA split-bf16 NT GEMM: C[M,1024] = A[M,1024] @ W[1024,1024]^T + bias
// 128x128 CTA tile, BK=32, cp.async double-buffered, 256 threads (8 warps 2x4).
// Each warp: 64x32 via m16n8k16, 3 products per frag pair (bf16x3).
// SMEM rows padded to 80B -> conflict-free ldmatrix / cp.async.
// mode 0: plain row-major store.  mode 1: headed store [B,H,S,hd].
// ---------------------------------------------------------------------------
#define SPB 80                      // smem row pitch, bytes (32 halves + pad)
#define MAT_SM (128 * SPB)          // 10240 B per matrix tile
#define BUF_SM (4 * MAT_SM)         // 40960 B per buffer (Ah|Al|Bh|Bl)
#define GEMM_SMEM (2 * BUF_SM)      // 81920 B

__global__ __launch_bounds__(256)
void gemm_mma(const __nv_bfloat16* __restrict__ Ah_, const __nv_bfloat16* __restrict__ Al_,
              const __nv_bfloat16* __restrict__ Bh_, const __nv_bfloat16* __restrict__ Bl_,
              const float* __restrict__ bias, float* __restrict__ C, int mode)
{
    extern __shared__ char sm[];
    const uint32_t sb = smem_u32(sm);
    const int t    = threadIdx.x;
    const int wid  = t >> 5;
    const int lane = t & 31;
    const int m0 = blockIdx.y * 128;
    const int n0 = blockIdx.x * 128;
    const int wm = wid >> 2;        // 0..1 -> m offset wm*64
    const int wn = wid & 3;         // 0..3 -> n offset wn*32

    const char* gb0 = (const char*)(Ah_ + (size_t)m0 * 1024);
    const char* gb1 = (const char*)(Al_ + (size_t)m0 * 1024);
    const char* gb2 = (const char*)(Bh_ + (size_t)n0 * 1024);
    const char* gb3 = (const char*)(Bl_ + (size_t)n0 * 1024);

    // per-thread cp.async mapping: 8 x 16B per chunk
    // id = t + it*256 ; mat = id>>9 ; row = (id>>2)&127 ; c16 = id&3
    auto issue = [&](int chunk, int buf) {
#pragma unroll
        for (int it = 0; it < 8; it++) {
            int id  = t + it * 256;
            int mat = id >> 9;
            int row = (id >> 2) & 127;
            int c16 = id & 3;
            const char* g = (mat == 0 ? gb0 : mat == 1 ? gb1 : mat == 2 ? gb2 : gb3);
            uint32_t sa = sb + buf * BUF_SM + mat * MAT_SM + row * SPB + c16 * 16;
            CP_ASYNC16(sa, g + (size_t)row * 2048 + chunk * 64 + c16 * 16);
        }
        CP_COMMIT();
    };

    float acc[4][4][4];
#pragma unroll
    for (int i = 0; i < 4; i++)
#pragma unroll
        for (int j = 0; j < 4; j++)
#pragma unroll
            for (int r = 0; r < 4; r++) acc[i][j][r] = 0.f;

    issue(0, 0);
    for (int c = 0; c < 32; c++) {
        const int buf = c & 1;
        if (c + 1 < 32) { issue(c + 1, buf ^ 1); CP_WAIT(1); }
        else            { CP_WAIT(0); }
        __syncthreads();

        const uint32_t Ahb = sb + buf * BUF_SM;
        const uint32_t Alb = Ahb + MAT_SM;
        const uint32_t Bhb = Ahb + 2 * MAT_SM;
        const uint32_t Blb = Ahb + 3 * MAT_SM;

#pragma unroll
        for (int s = 0; s < 2; s++) {               // two k16 steps per BK=32
            uint32_t ah[4][4], al[4][4];
            const int arow = wm * 64 + (lane & 15);
            const int acolB = (((lane >> 4) << 3) + s * 16) * 2;   // bytes
#pragma unroll
            for (int mf = 0; mf < 4; mf++) {
                uint32_t ad = Ahb + (uint32_t)(arow + mf * 16) * SPB + acolB;
                LDMX4(ah[mf][0], ah[mf][1], ah[mf][2], ah[mf][3], ad);
                ad = Alb + (uint32_t)(arow + mf * 16) * SPB + acolB;
                LDMX4(al[mf][0], al[mf][1], al[mf][2], al[mf][3], ad);
            }
            uint32_t bh[4][2], bl[4][2];
            const int brow = wn * 32 + (lane & 7) + ((lane >> 4) << 3);
            const int bcolB = ((((lane >> 3) & 1) << 3) + s * 16) * 2;
#pragma unroll
            for (int g = 0; g < 2; g++) {
                uint32_t r0, r1, r2, r3;
                uint32_t bd = Bhb + (uint32_t)(brow + g * 16) * SPB + bcolB;
                LDMX4(r0, r1, r2, r3, bd);
                bh[g * 2][0] = r0; bh[g * 2][1] = r1;
                bh[g * 2 + 1][0] = r2; bh[g * 2 + 1][1] = r3;
                bd = Blb + (uint32_t)(brow + g * 16) * SPB + bcolB;
                LDMX4(r0, r1, r2, r3, bd);
                bl[g * 2][0] = r0; bl[g * 2][1] = r1;
                bl[g * 2 + 1][0] = r2; bl[g * 2 + 1][1] = r3;
            }
#pragma unroll
            for (int mf = 0; mf < 4; mf++)
#pragma unroll
                for (int nf = 0; nf < 4; nf++) {
                    MMA16816(acc[mf][nf], ah[mf], bh[nf]);
                    MMA16816(acc[mf][nf], ah[mf], bl[nf]);
                    MMA16816(acc[mf][nf], al[mf], bh[nf]);
                }
        }
        __syncthreads();
    }

    // epilogue: fragment -> global (float2 pairs), + bias
#pragma unroll
    for (int mf = 0; mf < 4; mf++) {
#pragma unroll
        for (int nf = 0; nf < 4; nf++) {
            int m = m0 + wm * 64 + mf * 16 + (lane >> 2);
            int n = n0 + wn * 32 + nf * 8 + (lane & 3) * 2;
            float2 v0 = make_float2(acc[mf][nf][0] + bias[n],
                                    acc[mf][nf][1] + bias[n + 1]);
            float2 v1 = make_float2(acc[mf][nf][2] + bias[n],
                                    acc[mf][nf][3] + bias[n + 1]);
            if (mode == 0) {
                *(float2*)(C + (size_t)m * 1024 + n)       = v0;
                *(float2*)(C + (size_t)(m + 8) * 1024 + n) = v1;
            } else {
                int h = n >> 6, d = n & 63;
                int bb = m >> 10, s1 = m & 1023;
                *(float2*)(C + ((((size_t)bb * Hh + h) << 10) + s1) * HDd + d)     = v0;
                *(float2*)(C + ((((size_t)bb * Hh + h) << 10) + s1 + 8) * HDd + d) = v1;
            }
        }
    }
}

// ---------------------------------------------------------------------------
// SIMT NT GEMM (kept only for qr: M=65536, N=257, K=64)
// ---------------------------------------------------------------------------
__global__ void gemm_nt(const float* __restrict__ A, const float* __restrict__ Bm,
                        const float* __restrict__ bias, float* __restrict__ C,
                        int M, int N, int K, int mode)
{
    __shared__ float As[16][68];
    __shared__ float Bs[16][68];
    const int m0 = blockIdx.y * 64;
    const int n0 = blockIdx.x * 64;
    const int t  = threadIdx.x;
    const int tx = t & 15, ty = t >> 4;
    const int lr = t >> 2;
    const int lc = (t & 3) * 4;

    float acc[4][4];
#pragma unroll
    for (int i = 0; i < 4; i++)
#pragma unroll
        for (int j = 0; j < 4; j++) acc[i][j] = 0.f;

    for (int k0 = 0; k0 < K; k0 += 16) {
        float4 a = *(const float4*)(A + (size_t)(m0 + lr) * K + k0 + lc);
        float4 b = make_float4(0.f, 0.f, 0.f, 0.f);
        if (n0 + lr < N)
            b = *(const float4*)(Bm + (size_t)(n0 + lr) * K + k0 + lc);
        As[lc + 0][lr] = a.x; As[lc + 1][lr] = a.y; As[lc + 2][lr] = a.z; As[lc + 3][lr] = a.w;
        Bs[lc + 0][lr] = b.x; Bs[lc + 1][lr] = b.y; Bs[lc + 2][lr] = b.z; Bs[lc + 3][lr] = b.w;
        __syncthreads();
#pragma unroll
        for (int kk = 0; kk < 16; kk++) {
            float4 af = *(const float4*)&As[kk][ty * 4];
            float4 bf = *(const float4*)&Bs[kk][tx * 4];
            float av[4] = {af.x, af.y, af.z, af.w};
            float bv[4] = {bf.x, bf.y, bf.z, bf.w};
#pragma unroll
            for (int i = 0; i < 4; i++)
#pragma unroll
                for (int j = 0; j < 4; j++) acc[i][j] += av[i] * bv[j];
        }
        __syncthreads();
    }

#pragma unroll
    for (int i = 0; i < 4; i++) {
        int m = m0 + ty * 4 + i;
#pragma unroll
        for (int j = 0; j < 4; j++) {
            int n = n0 + tx * 4 + j;
            if (n >= N) continue;
            float v = acc[i][j] + (bias ? bias[n] : 0.f);
            if (mode == 0) {
                C[(size_t)m * N + n] = v;
            } else {
                int bb = m >> 10, s = m & 1023;
                int h = n >> 6, d = n & 63;
                C[((((size_t)bb * Hh + h) << 10) + s) * HDd + d] = v;
            }
        }
    }
}

// ---------------------------------------------------------------------------
// Attention: one block per (b*H+h, 8 query rows). 256 threads.
// ---------------------------------------------------------------------------
__global__ void attn_kernel(const float* __restrict__ rel_v)
{
    extern __shared__ float smf[];
    float* qs = smf;               // 512
    float* ss = smf + 512;         // 8192
    float* kt = ss + 8192;         // 4352 (64 rows x 68)
    float* wr = kt + 4352;         // 2056

    const int t  = threadIdx.x;
    const int bh = blockIdx.y;
    const int i0 = blockIdx.x * 8;
    const float* qbase = g_q + (size_t)bh * Ss * HDd;
    const float* kbase = g_k + (size_t)bh * Ss * HDd;
    const float* vbase = g_v + (size_t)bh * Ss * HDd;

#pragma unroll
    for (int k = 0; k < 2; k++) {
        int idx = t + k * 256;
        qs[idx] = qbase[(size_t)i0 * HDd + idx];
    }

    const int jj = t & 63;
    const int rr = t >> 6;
    for (int kt0 = 0; kt0 < Ss; kt0 += 64) {
        __syncthreads();
#pragma unroll
        for (int k = 0; k < 4; k++) {
            int idx4 = t + k * 256;
            int row = idx4 >> 4;
            int c4  = (idx4 & 15) * 4;
            *(float4*)&kt[row * 68 + c4] =
                *(const float4*)(kbase + (size_t)(kt0 + row) * HDd + c4);
        }
        __syncthreads();
        float a0 = 0.f, a1 = 0.f;
#pragma unroll
        for (int d = 0; d < 64; d += 4) {
            float4 kv = *(const float4*)&kt[jj * 68 + d];
            float4 q0 = *(const float4*)&qs[rr * 64 + d];
            float4 q1 = *(const float4*)&qs[(rr + 4) * 64 + d];
            a0 += q0.x * kv.x + q0.y * kv.y + q0.z * kv.z + q0.w * kv.w;
            a1 += q1.x * kv.x + q1.y * kv.y + q1.z * kv.z + q1.w * kv.w;
        }
        ss[rr * 1024 + kt0 + jj]       = a0;
        ss[(rr + 4) * 1024 + kt0 + jj] = a1;
    }
    __syncthreads();

    const float* qrb = g_qr + (size_t)bh * Ss * NP;
    for (int k = 0; k < 32; k++) {
        int idx = t + k * 256;
        int r = idx >> 10, j = idx & 1023;
        int i = i0 + r;
        int rel = j - i;
        rel = rel < -128 ? -128 : (rel > 128 ? 128 : rel);
        ss[idx] = (ss[idx] + qrb[(size_t)i * NP + rel + 128]) * 0.125f;
    }
    __syncthreads();

    {
        int r = t >> 5, lane = t & 31;
        float* row = ss + r * 1024;
        float mx = -1e30f;
        for (int j = lane; j < 1024; j += 32) mx = fmaxf(mx, row[j]);
#pragma unroll
        for (int o = 16; o > 0; o >>= 1) mx = fmaxf(mx, __shfl_xor_sync(0xffffffffu, mx, o));
        float sum = 0.f;
        for (int j = lane; j < 1024; j += 32) { float e = __expf(row[j] - mx); row[j] = e; sum += e; }
#pragma unroll
        for (int o = 16; o > 0; o >>= 1) sum += __shfl_xor_sync(0xffffffffu, sum, o);
        float inv = 1.f / sum;
        for (int j = lane; j < 1024; j += 32) row[j] *= inv;
        __syncwarp();

        int i = i0 + r;
        float* wrow = wr + r * NP;
        for (int p = 1 + lane; p < 256; p += 32) {
            int j = i + p - 128;
            wrow[p] = (j >= 0 && j < 1024) ? row[j] : 0.f;
        }
        float s0 = 0.f;
        for (int j = lane; j <= i - 128; j += 32) s0 += row[j];
#pragma unroll
        for (int o = 16; o > 0; o >>= 1) s0 += __shfl_xor_sync(0xffffffffu, s0, o);
        float s2 = 0.f;
        for (int j = i + 128 + lane; j < 1024; j += 32) s2 += row[j];
#pragma unroll
        for (int o = 16; o > 0; o >>= 1) s2 += __shfl_xor_sync(0xffffffffu, s2, o);
        if (lane == 0) { wrow[0] = s0; wrow[256] = s2; }
    }

    const int d  = t & 63;
    const int r2 = t >> 6;
    float a0 = 0.f, a1 = 0.f;
    for (int vt0 = 0; vt0 < Ss; vt0 += 64) {
        __syncthreads();
#pragma unroll
        for (int k = 0; k < 4; k++) {
            int idx4 = t + k * 256;
            int row = idx4 >> 4;
            int c4  = (idx4 & 15) * 4;
            *(float4*)&kt[row * 68 + c4] =
                *(const float4*)(vbase + (size_t)(vt0 + row) * HDd + c4);
        }
        __syncthreads();
#pragma unroll
        for (int j = 0; j < 64; j++) {
            float vv = kt[j * 68 + d];
            a0 += ss[r2 * 1024 + vt0 + j] * vv;
            a1 += ss[(r2 + 4) * 1024 + vt0 + j] * vv;
        }
    }

#pragma unroll 4
    for (int p = 0; p < NP; p++) {
        float rv = rel_v[p * 64 + d];
        a0 += wr[r2 * NP + p] * rv;
        a1 += wr[(r2 + 4) * NP + p] * rv;
    }

    const int bb = bh >> 4, h = bh & 15;
    g_attn[((size_t)bb * 1024 + i0 + r2) * 1024 + h * 64 + d]     = a0;
    g_attn[((size_t)bb * 1024 + i0 + r2 + 4) * 1024 + h * 64 + d] = a1;
}

// ---------------------------------------------------------------------------
extern "C" void kernel_launch(void* const* d_in, const int* in_sizes, int n_in,
                              void* d_out, int out_size)
{
    const float* x     = (const float*)d_in[0];
    const float* Wq    = (const float*)d_in[1];
    const float* bq    = (const float*)d_in[2];
    const float* Wk    = (const float*)d_in[3];
    const float* bk    = (const float*)d_in[4];
    const float* Wv    = (const float*)d_in[5];
    const float* bv    = (const float*)d_in[6];
    const float* Wo    = (const float*)d_in[7];
    const float* bo    = (const float*)d_in[8];
    const float* rel_k = (const float*)d_in[9];
    const float* rel_v = (const float*)d_in[10];

    float *q, *k, *v, *qr, *attn;
    __nv_bfloat16 *xh, *xl, *wh, *wl;
    cudaGetSymbolAddress((void**)&q,    g_q);
    cudaGetSymbolAddress((void**)&k,    g_k);
    cudaGetSymbolAddress((void**)&v,    g_v);
    cudaGetSymbolAddress((void**)&qr,   g_qr);
    cudaGetSymbolAddress((void**)&attn, g_attn);
    cudaGetSymbolAddress((void**)&xh,   g_xh);
    cudaGetSymbolAddress((void**)&xl,   g_xl);
    cudaGetSymbolAddress((void**)&wh,   g_wh);
    cudaGetSymbolAddress((void**)&wl,   g_wl);

    const int SMEM_ATTN = 60448;
    cudaFuncSetAttribute(attn_kernel, cudaFuncAttributeMaxDynamicSharedMemorySize, SMEM_ATTN);
    cudaFuncSetAttribute(gemm_mma, cudaFuncAttributeMaxDynamicSharedMemorySize, GEMM_SMEM);

    dim3 blk(256);
    dim3 gtc(Dd / 128, NROW / 128);                  // (8, 32)

    // x -> split bf16
    split_bf16_kernel<<<4096, blk>>>(x, xh, xl, (NROW * Dd) / 4);

    // Q/K/V projections (warp-MMA bf16x3) -> headed layout [B,H,S,hd]
    split_bf16_kernel<<<1024, blk>>>(Wq, wh, wl, (Dd * Dd) / 4);
    gemm_mma<<<gtc, blk, GEMM_SMEM>>>(xh, xl, wh, wl, bq, q, 1);
    split_bf16_kernel<<<1024, blk>>>(Wk, wh, wl, (Dd * Dd) / 4);
    gemm_mma<<<gtc, blk, GEMM_SMEM>>>(xh, xl, wh, wl, bk, k, 1);
    split_bf16_kernel<<<1024, blk>>>(Wv, wh, wl, (Dd * Dd) / 4);
    gemm_mma<<<gtc, blk, GEMM_SMEM>>>(xh, xl, wh, wl, bv, v, 1);

    // qr[b,h,i,p] = q_i . rel_k[p]   (SIMT, N=257 predicated)
    dim3 gqr((NP + 63) / 64, BHS / 64);
    gemm_nt<<<gqr, blk>>>(q, rel_k, nullptr, qr, BHS, NP, HDd, 0);

    // attention core
    attn_kernel<<<dim3(Ss / 8, Bv * Hh), blk, SMEM_ATTN>>>(rel_v);

    // output projection (warp-MMA) -> d_out
    split_bf16_kernel<<<4096, blk>>>(attn, xh, xl, (NROW * Dd) / 4);
    split_bf16_kernel<<<1024, blk>>>(Wo, wh, wl, (Dd * Dd) / 4);
    gemm_mma<<<gtc, blk, GEMM_SMEM>>>(xh, xl, wh, wl, bo, (float*)d_out, 0);
}

// round 4
// speedup vs baseline: 2.4273x; 1.8287x over previous
#include <cuda_runtime.h>
#include <cuda_bf16.h>
#include <cstdint>

#define Bv 4
#define Hh 16
#define Ss 1024
#define Dd 1024
#define HDd 64
#define NP 257          // 2*128+1 relative buckets
#define NROW (Bv*Ss)    // 4096
#define BHS (Bv*Hh*Ss)  // 65536

// ---------------- scratch (device globals: allocation-free) ----------------
__device__ float g_q[BHS * HDd];                   // fp32 q (for qr gemm)
__device__ float g_qr[(size_t)BHS * NP];
__device__ float g_attn[(size_t)NROW * Dd];
__device__ __nv_bfloat16 g_qh[BHS * HDd];
__device__ __nv_bfloat16 g_ql[BHS * HDd];
__device__ __nv_bfloat16 g_kh[BHS * HDd];
__device__ __nv_bfloat16 g_kl[BHS * HDd];
__device__ __nv_bfloat16 g_vh[BHS * HDd];
__device__ __nv_bfloat16 g_vl[BHS * HDd];
__device__ __nv_bfloat16 g_rvh[272 * 64];
__device__ __nv_bfloat16 g_rvl[272 * 64];
__device__ __nv_bfloat16 g_xh[(size_t)NROW * Dd];
__device__ __nv_bfloat16 g_xl[(size_t)NROW * Dd];
__device__ __nv_bfloat16 g_wh[(size_t)Dd * Dd];
__device__ __nv_bfloat16 g_wl[(size_t)Dd * Dd];

// ====================== PTX helpers (family-portable only) ======================
__device__ __forceinline__ uint32_t smem_u32(const void* p) {
    uint32_t a;
    asm("{ .reg .u64 t; cvta.to.shared.u64 t, %1; cvt.u32.u64 %0, t; }" : "=r"(a) : "l"(p));
    return a;
}

#define LDMX4(r0, r1, r2, r3, addr) \
    asm volatile("ldmatrix.sync.aligned.m8n8.x4.shared.b16 {%0,%1,%2,%3}, [%4];" \
                 : "=r"(r0), "=r"(r1), "=r"(r2), "=r"(r3) : "r"(addr))

#define LDMX2(r0, r1, addr) \
    asm volatile("ldmatrix.sync.aligned.m8n8.x2.shared.b16 {%0,%1}, [%2];" \
                 : "=r"(r0), "=r"(r1) : "r"(addr))

#define LDMX4T(r0, r1, r2, r3, addr) \
    asm volatile("ldmatrix.sync.aligned.m8n8.x4.trans.shared.b16 {%0,%1,%2,%3}, [%4];" \
                 : "=r"(r0), "=r"(r1), "=r"(r2), "=r"(r3) : "r"(addr))

#define MMA16816(c, a, b) \
    asm volatile("mma.sync.aligned.m16n8k16.row.col.f32.bf16.bf16.f32 " \
                 "{%0,%1,%2,%3}, {%4,%5,%6,%7}, {%8,%9}, {%0,%1,%2,%3};" \
                 : "+f"((c)[0]), "+f"((c)[1]), "+f"((c)[2]), "+f"((c)[3]) \
                 : "r"((a)[0]), "r"((a)[1]), "r"((a)[2]), "r"((a)[3]), \
                   "r"((b)[0]), "r"((b)[1]))

#define CP_ASYNC16(s, g) \
    asm volatile("cp.async.cg.shared.global [%0], [%1], 16;" :: "r"(s), "l"(g))
#define CP_COMMIT() asm volatile("cp.async.commit_group;" ::: "memory")
#define CP_WAIT(n)  asm volatile("cp.async.wait_group %0;" :: "n"(n) : "memory")

// ---------------------------------------------------------------------------
// split f32 -> (hi bf16, lo bf16)
// ---------------------------------------------------------------------------
__global__ void split_bf16_kernel(const float* __restrict__ in,
                                  __nv_bfloat16* __restrict__ hi,
                                  __nv_bfloat16* __restrict__ lo, int n4)
{
    int i = blockIdx.x * 256 + threadIdx.x;
    if (i >= n4) return;
    float4 v = ((const float4*)in)[i];
    float vv[4] = {v.x, v.y, v.z, v.w};
    __nv_bfloat16 h[4], l[4];
#pragma unroll
    for (int j = 0; j < 4; j++) {
        h[j] = __float2bfloat16(vv[j]);
        l[j] = __float2bfloat16(vv[j] - __bfloat162float(h[j]));
    }
    ((__nv_bfloat162*)hi)[i * 2 + 0] = __nv_bfloat162(h[0], h[1]);
    ((__nv_bfloat162*)hi)[i * 2 + 1] = __nv_bfloat162(h[2], h[3]);
    ((__nv_bfloat162*)lo)[i * 2 + 0] = __nv_bfloat162(l[0], l[1]);
    ((__nv_bfloat162*)lo)[i * 2 + 1] = __nv_bfloat162(l[2], l[3]);
}

// rel_v -> split bf16, padded to 272 rows (rows >=257 zero)
__global__ void relv_prep(const float* __restrict__ rel_v)
{
    int idx = blockIdx.x * 256 + threadIdx.x;
    if (idx >= 272 * 64) return;
    int p = idx >> 6, d = idx & 63;
    float v = (p < NP) ? rel_v[p * 64 + d] : 0.f;
    __nv_bfloat16 h = __float2bfloat16(v);
    __nv_bfloat16 l = __float2bfloat16(v - __bfloat162float(h));
    g_rvh[idx] = h; g_rvl[idx] = l;
}

// ---------------------------------------------------------------------------
// Warp-MMA split-bf16 NT GEMM (as round 3), epilogue extended:
// optional fp32 output Cf, optional split-bf16 outputs Ch/Cl; headed flag.
// ---------------------------------------------------------------------------
#define SPB 80
#define MAT_SM (128 * SPB)
#define BUF_SM (4 * MAT_SM)
#define GEMM_SMEM (2 * BUF_SM)

__global__ __launch_bounds__(256)
void gemm_mma(const __nv_bfloat16* __restrict__ Ah_, const __nv_bfloat16* __restrict__ Al_,
              const __nv_bfloat16* __restrict__ Bh_, const __nv_bfloat16* __restrict__ Bl_,
              const float* __restrict__ bias, float* __restrict__ Cf,
              __nv_bfloat16* __restrict__ Ch, __nv_bfloat16* __restrict__ Cl, int headed)
{
    extern __shared__ char sm[];
    const uint32_t sb = smem_u32(sm);
    const int t    = threadIdx.x;
    const int wid  = t >> 5;
    const int lane = t & 31;
    const int m0 = blockIdx.y * 128;
    const int n0 = blockIdx.x * 128;
    const int wm = wid >> 2;
    const int wn = wid & 3;

    const char* gb0 = (const char*)(Ah_ + (size_t)m0 * 1024);
    const char* gb1 = (const char*)(Al_ + (size_t)m0 * 1024);
    const char* gb2 = (const char*)(Bh_ + (size_t)n0 * 1024);
    const char* gb3 = (const char*)(Bl_ + (size_t)n0 * 1024);

    auto issue = [&](int chunk, int buf) {
#pragma unroll
        for (int it = 0; it < 8; it++) {
            int id  = t + it * 256;
            int mat = id >> 9;
            int row = (id >> 2) & 127;
            int c16 = id & 3;
            const char* g = (mat == 0 ? gb0 : mat == 1 ? gb1 : mat == 2 ? gb2 : gb3);
            uint32_t sa = sb + buf * BUF_SM + mat * MAT_SM + row * SPB + c16 * 16;
            CP_ASYNC16(sa, g + (size_t)row * 2048 + chunk * 64 + c16 * 16);
        }
        CP_COMMIT();
    };

    float acc[4][4][4];
#pragma unroll
    for (int i = 0; i < 4; i++)
#pragma unroll
        for (int j = 0; j < 4; j++)
#pragma unroll
            for (int r = 0; r < 4; r++) acc[i][j][r] = 0.f;

    issue(0, 0);
    for (int c = 0; c < 32; c++) {
        const int buf = c & 1;
        if (c + 1 < 32) { issue(c + 1, buf ^ 1); CP_WAIT(1); }
        else            { CP_WAIT(0); }
        __syncthreads();

        const uint32_t Ahb = sb + buf * BUF_SM;
        const uint32_t Alb = Ahb + MAT_SM;
        const uint32_t Bhb = Ahb + 2 * MAT_SM;
        const uint32_t Blb = Ahb + 3 * MAT_SM;

#pragma unroll
        for (int s = 0; s < 2; s++) {
            uint32_t ah[4][4], al[4][4];
            const int arow = wm * 64 + (lane & 15);
            const int acolB = (((lane >> 4) << 3) + s * 16) * 2;
#pragma unroll
            for (int mf = 0; mf < 4; mf++) {
                uint32_t ad = Ahb + (uint32_t)(arow + mf * 16) * SPB + acolB;
                LDMX4(ah[mf][0], ah[mf][1], ah[mf][2], ah[mf][3], ad);
                ad = Alb + (uint32_t)(arow + mf * 16) * SPB + acolB;
                LDMX4(al[mf][0], al[mf][1], al[mf][2], al[mf][3], ad);
            }
            uint32_t bh[4][2], bl[4][2];
            const int brow = wn * 32 + (lane & 7) + ((lane >> 4) << 3);
            const int bcolB = ((((lane >> 3) & 1) << 3) + s * 16) * 2;
#pragma unroll
            for (int g = 0; g < 2; g++) {
                uint32_t r0, r1, r2, r3;
                uint32_t bd = Bhb + (uint32_t)(brow + g * 16) * SPB + bcolB;
                LDMX4(r0, r1, r2, r3, bd);
                bh[g * 2][0] = r0; bh[g * 2][1] = r1;
                bh[g * 2 + 1][0] = r2; bh[g * 2 + 1][1] = r3;
                bd = Blb + (uint32_t)(brow + g * 16) * SPB + bcolB;
                LDMX4(r0, r1, r2, r3, bd);
                bl[g * 2][0] = r0; bl[g * 2][1] = r1;
                bl[g * 2 + 1][0] = r2; bl[g * 2 + 1][1] = r3;
            }
#pragma unroll
            for (int mf = 0; mf < 4; mf++)
#pragma unroll
                for (int nf = 0; nf < 4; nf++) {
                    MMA16816(acc[mf][nf], ah[mf], bh[nf]);
                    MMA16816(acc[mf][nf], ah[mf], bl[nf]);
                    MMA16816(acc[mf][nf], al[mf], bh[nf]);
                }
        }
        __syncthreads();
    }

#pragma unroll
    for (int mf = 0; mf < 4; mf++) {
#pragma unroll
        for (int nf = 0; nf < 4; nf++) {
            int m = m0 + wm * 64 + mf * 16 + (lane >> 2);
            int n = n0 + wn * 32 + nf * 8 + (lane & 3) * 2;
            float p0 = acc[mf][nf][0] + bias[n];
            float p1 = acc[mf][nf][1] + bias[n + 1];
            float p2 = acc[mf][nf][2] + bias[n];
            float p3 = acc[mf][nf][3] + bias[n + 1];
            size_t off0, off1;
            if (headed) {
                int h = n >> 6, d = n & 63;
                int bb = m >> 10, s1 = m & 1023;
                off0 = ((((size_t)bb * Hh + h) << 10) + s1) * HDd + d;
                off1 = ((((size_t)bb * Hh + h) << 10) + s1 + 8) * HDd + d;
            } else {
                off0 = (size_t)m * 1024 + n;
                off1 = (size_t)(m + 8) * 1024 + n;
            }
            if (Cf) {
                *(float2*)(Cf + off0) = make_float2(p0, p1);
                *(float2*)(Cf + off1) = make_float2(p2, p3);
            }
            if (Ch) {
                __nv_bfloat16 h0 = __float2bfloat16(p0), h1 = __float2bfloat16(p1);
                __nv_bfloat16 h2 = __float2bfloat16(p2), h3 = __float2bfloat16(p3);
                *(__nv_bfloat162*)(Ch + off0) = __nv_bfloat162(h0, h1);
                *(__nv_bfloat162*)(Ch + off1) = __nv_bfloat162(h2, h3);
                __nv_bfloat16 l0 = __float2bfloat16(p0 - __bfloat162float(h0));
                __nv_bfloat16 l1 = __float2bfloat16(p1 - __bfloat162float(h1));
                __nv_bfloat16 l2 = __float2bfloat16(p2 - __bfloat162float(h2));
                __nv_bfloat16 l3 = __float2bfloat16(p3 - __bfloat162float(h3));
                *(__nv_bfloat162*)(Cl + off0) = __nv_bfloat162(l0, l1);
                *(__nv_bfloat162*)(Cl + off1) = __nv_bfloat162(l2, l3);
            }
        }
    }
}

// ---------------------------------------------------------------------------
// SIMT NT GEMM (qr only: M=65536, N=257, K=64)
// ---------------------------------------------------------------------------
__global__ void gemm_nt(const float* __restrict__ A, const float* __restrict__ Bm,
                        float* __restrict__ C, int N, int K)
{
    __shared__ float As[16][68];
    __shared__ float Bs[16][68];
    const int m0 = blockIdx.y * 64;
    const int n0 = blockIdx.x * 64;
    const int t  = threadIdx.x;
    const int tx = t & 15, ty = t >> 4;
    const int lr = t >> 2;
    const int lc = (t & 3) * 4;

    float acc[4][4];
#pragma unroll
    for (int i = 0; i < 4; i++)
#pragma unroll
        for (int j = 0; j < 4; j++) acc[i][j] = 0.f;

    for (int k0 = 0; k0 < K; k0 += 16) {
        float4 a = *(const float4*)(A + (size_t)(m0 + lr) * K + k0 + lc);
        float4 b = make_float4(0.f, 0.f, 0.f, 0.f);
        if (n0 + lr < N)
            b = *(const float4*)(Bm + (size_t)(n0 + lr) * K + k0 + lc);
        As[lc + 0][lr] = a.x; As[lc + 1][lr] = a.y; As[lc + 2][lr] = a.z; As[lc + 3][lr] = a.w;
        Bs[lc + 0][lr] = b.x; Bs[lc + 1][lr] = b.y; Bs[lc + 2][lr] = b.z; Bs[lc + 3][lr] = b.w;
        __syncthreads();
#pragma unroll
        for (int kk = 0; kk < 16; kk++) {
            float4 af = *(const float4*)&As[kk][ty * 4];
            float4 bf = *(const float4*)&Bs[kk][tx * 4];
            float av[4] = {af.x, af.y, af.z, af.w};
            float bv[4] = {bf.x, bf.y, bf.z, bf.w};
#pragma unroll
            for (int i = 0; i < 4; i++)
#pragma unroll
                for (int j = 0; j < 4; j++) acc[i][j] += av[i] * bv[j];
        }
        __syncthreads();
    }

#pragma unroll
    for (int i = 0; i < 4; i++) {
        int m = m0 + ty * 4 + i;
#pragma unroll
        for (int j = 0; j < 4; j++) {
            int n = n0 + tx * 4 + j;
            if (n >= N) continue;
            C[(size_t)m * N + n] = acc[i][j];
        }
    }
}

// ---------------------------------------------------------------------------
// MMA attention core. Block = (bh, 32 query rows). 256 threads, 8 warps.
// smem layout (bytes):
//   q    [0, 9216)            : 32 rows x 144B (hi) + 32 x 144B (lo)
//   kv   [9216, 46080)        : 2 buffers x (64x144 hi + 64x144 lo)
//   ss   [46080, 178176)      : 32 row-slots x 4128B  (fp32 scores -> wh|wl bf16)
//   wrh  [178176, 195584)     : 32 x 272 bf16 (pitch 544B)
//   wrl  [195584, 212992)
// ---------------------------------------------------------------------------
#define Q_OFF   0u
#define KV_OFF  9216u
#define KV_BUF  18432u
#define SS_OFF  46080u
#define WRH_OFF 178176u
#define WRL_OFF 195584u
#define ATTN_SMEM 212992

__global__ __launch_bounds__(256, 1)
void attn_mma()
{
    extern __shared__ char sm[];
    const uint32_t sb = smem_u32(sm);
    const int t = threadIdx.x, lane = t & 31, wid = t >> 5;
    const int bh = blockIdx.y;
    const int i0 = blockIdx.x * 32;
    const int wm = wid >> 2, wn = wid & 3;

    auto issue_tile = [&](const __nv_bfloat16* sh, const __nv_bfloat16* sl,
                          size_t row0, int nrows, uint32_t dst) {
#pragma unroll
        for (int it = 0; it < 4; it++) {
            int id = t + it * 256;
            int sel = id / (nrows * 8);
            if (sel < 2) {
                int rid = id % (nrows * 8);
                int row = rid >> 3, c16 = rid & 7;
                const __nv_bfloat16* s = (sel ? sl : sh) + (row0 + row) * 64 + c16 * 8;
                CP_ASYNC16(dst + (uint32_t)sel * (nrows * 144) + row * 144 + c16 * 16, s);
            }
        }
        CP_COMMIT();
    };

    const size_t bhrow = (size_t)bh * 1024;

    issue_tile(g_qh, g_ql, bhrow + i0, 32, sb + Q_OFF);
    issue_tile(g_kh, g_kl, bhrow, 64, sb + KV_OFF);

    uint32_t qh_f[2][4][4], ql_f[2][4][4];

    // ================= scores =================
    for (int kt = 0; kt < 16; kt++) {
        const int buf = kt & 1;
        if (kt < 15) {
            issue_tile(g_kh, g_kl, bhrow + (kt + 1) * 64, 64, sb + KV_OFF + (buf ^ 1) * KV_BUF);
            CP_WAIT(1);
        } else {
            CP_WAIT(0);
        }
        __syncthreads();

        if (kt == 0) {
#pragma unroll
            for (int mf = 0; mf < 2; mf++)
#pragma unroll
                for (int s = 0; s < 4; s++) {
                    uint32_t a = sb + Q_OFF + (uint32_t)(mf * 16 + (lane & 15)) * 144
                               + (((lane >> 4) << 3) + s * 16) * 2;
                    LDMX4(qh_f[mf][s][0], qh_f[mf][s][1], qh_f[mf][s][2], qh_f[mf][s][3], a);
                    LDMX4(ql_f[mf][s][0], ql_f[mf][s][1], ql_f[mf][s][2], ql_f[mf][s][3], a + 4608);
                }
        }

        float acc[2][4] = {{0.f,0.f,0.f,0.f},{0.f,0.f,0.f,0.f}};
        const uint32_t kb = sb + KV_OFF + buf * KV_BUF;
#pragma unroll
        for (int s = 0; s < 4; s++) {
            uint32_t addr = kb + (uint32_t)(wid * 8 + (lane & 7)) * 144
                          + ((((lane >> 3) & 1) * 8) + s * 16) * 2;
            uint32_t bh2[2], bl2[2];
            LDMX2(bh2[0], bh2[1], addr);
            LDMX2(bl2[0], bl2[1], addr + 9216);
#pragma unroll
            for (int mf = 0; mf < 2; mf++) {
                MMA16816(acc[mf], qh_f[mf][s], bh2);
                MMA16816(acc[mf], qh_f[mf][s], bl2);
                MMA16816(acc[mf], ql_f[mf][s], bh2);
            }
        }
#pragma unroll
        for (int mf = 0; mf < 2; mf++) {
            int row = mf * 16 + (lane >> 2);
            int col = kt * 64 + wid * 8 + (lane & 3) * 2;
            *(float2*)(sm + SS_OFF + (uint32_t)row * 4128 + col * 4) =
                make_float2(acc[mf][0], acc[mf][1]);
            *(float2*)(sm + SS_OFF + (uint32_t)(row + 8) * 4128 + col * 4) =
                make_float2(acc[mf][2], acc[mf][3]);
        }
        __syncthreads();
    }

    // ================= relative bias + scale =================
    {
        const float* qrb = g_qr + (size_t)bh * Ss * NP;
#pragma unroll 8
        for (int kk = 0; kk < 128; kk++) {
            int v = kk * 256 + t;
            int row = v >> 10, col = v & 1023;
            int i = i0 + row;
            int rel = col - i;
            rel = rel < -128 ? -128 : (rel > 128 ? 128 : rel);
            float* p = (float*)(sm + SS_OFF + (uint32_t)row * 4128 + col * 4);
            *p = (*p + qrb[(size_t)i * NP + rel + 128]) * 0.125f;
        }
    }
    __syncthreads();

    // ================= softmax + wr extraction (4 rows per warp) =================
    for (int rr = 0; rr < 4; rr++) {
        const int row = wid * 4 + rr;
        float* rp = (float*)(sm + SS_OFF + (uint32_t)row * 4128);
        float mx = -1e30f;
        for (int j = lane; j < 1024; j += 32) mx = fmaxf(mx, rp[j]);
#pragma unroll
        for (int o = 16; o > 0; o >>= 1) mx = fmaxf(mx, __shfl_xor_sync(0xffffffffu, mx, o));
        float sum = 0.f;
        for (int j = lane; j < 1024; j += 32) { float e = __expf(rp[j] - mx); rp[j] = e; sum += e; }
#pragma unroll
        for (int o = 16; o > 0; o >>= 1) sum += __shfl_xor_sync(0xffffffffu, sum, o);
        float inv = 1.f / sum;
        for (int j = lane; j < 1024; j += 32) rp[j] *= inv;
        __syncwarp();

        const int i = i0 + row;
        __nv_bfloat16* wh_ = (__nv_bfloat16*)(sm + WRH_OFF + (uint32_t)row * 544);
        __nv_bfloat16* wl_ = (__nv_bfloat16*)(sm + WRL_OFF + (uint32_t)row * 544);
        for (int p = 1 + lane; p < 256; p += 32) {
            int j = i + p - 128;
            float val = (j >= 0 && j < 1024) ? rp[j] : 0.f;
            __nv_bfloat16 h = __float2bfloat16(val);
            wh_[p] = h;
            wl_[p] = __float2bfloat16(val - __bfloat162float(h));
        }
        float s0 = 0.f;
        for (int j = lane; j <= i - 128; j += 32) s0 += rp[j];
#pragma unroll
        for (int o = 16; o > 0; o >>= 1) s0 += __shfl_xor_sync(0xffffffffu, s0, o);
        float s2 = 0.f;
        for (int j = i + 128 + lane; j < 1024; j += 32) s2 += rp[j];
#pragma unroll
        for (int o = 16; o > 0; o >>= 1) s2 += __shfl_xor_sync(0xffffffffu, s2, o);
        if (lane == 0) {
            __nv_bfloat16 h0 = __float2bfloat16(s0);
            wh_[0] = h0; wl_[0] = __float2bfloat16(s0 - __bfloat162float(h0));
            __nv_bfloat16 h2 = __float2bfloat16(s2);
            wh_[256] = h2; wl_[256] = __float2bfloat16(s2 - __bfloat162float(h2));
        }
        if (lane < 15) { wh_[257 + lane] = __float2bfloat16(0.f);
                         wl_[257 + lane] = __float2bfloat16(0.f); }
    }
    __syncthreads();

    // ================= in-place fp32 w -> (hi,lo) bf16 per row slot =================
    for (int g = 0; g < 4; g++) {
        float tmp[32];
#pragma unroll
        for (int kk = 0; kk < 32; kk++) {
            int v = g * 8192 + kk * 256 + t;
            int row = v >> 10, col = v & 1023;
            tmp[kk] = *(const float*)(sm + SS_OFF + (uint32_t)row * 4128 + col * 4);
        }
        __syncthreads();
#pragma unroll
        for (int kk = 0; kk < 32; kk++) {
            int v = g * 8192 + kk * 256 + t;
            int row = v >> 10, col = v & 1023;
            __nv_bfloat16 h = __float2bfloat16(tmp[kk]);
            __nv_bfloat16 l = __float2bfloat16(tmp[kk] - __bfloat162float(h));
            *(__nv_bfloat16*)(sm + SS_OFF + (uint32_t)row * 4128 + col * 2) = h;
            *(__nv_bfloat16*)(sm + SS_OFF + (uint32_t)row * 4128 + 2064 + col * 2) = l;
        }
        __syncthreads();
    }

    // ================= PV (w @ v) + relative-V (wr @ rel_v) =================
    float oacc[2][4] = {{0.f,0.f,0.f,0.f},{0.f,0.f,0.f,0.f}};

    issue_tile(g_vh, g_vl, bhrow, 64, sb + KV_OFF);
    for (int vt = 0; vt < 16; vt++) {
        const int buf = vt & 1;
        if (vt < 15) issue_tile(g_vh, g_vl, bhrow + (vt + 1) * 64, 64, sb + KV_OFF + (buf ^ 1) * KV_BUF);
        else         issue_tile(g_rvh, g_rvl, 0, 64, sb + KV_OFF + (buf ^ 1) * KV_BUF);
        CP_WAIT(1);
        __syncthreads();

        const uint32_t vb = sb + KV_OFF + buf * KV_BUF;
#pragma unroll
        for (int s = 0; s < 4; s++) {
            uint32_t aaddr = sb + SS_OFF + (uint32_t)(wm * 16 + (lane & 15)) * 4128
                           + (((lane >> 4) << 3) + vt * 64 + s * 16) * 2;
            uint32_t awh[4], awl[4];
            LDMX4(awh[0], awh[1], awh[2], awh[3], aaddr);
            LDMX4(awl[0], awl[1], awl[2], awl[3], aaddr + 2064);
            uint32_t baddr = vb + (uint32_t)(s * 16 + (lane & 7) + ((lane >> 3) & 1) * 8) * 144
                           + (wn * 16 + ((lane >> 4) << 3)) * 2;
            uint32_t bvh[4], bvl[4];
            LDMX4T(bvh[0], bvh[1], bvh[2], bvh[3], baddr);
            LDMX4T(bvl[0], bvl[1], bvl[2], bvl[3], baddr + 9216);
#pragma unroll
            for (int nf = 0; nf < 2; nf++) {
                MMA16816(oacc[nf], awh, (&bvh[nf * 2]));
                MMA16816(oacc[nf], awh, (&bvl[nf * 2]));
                MMA16816(oacc[nf], awl, (&bvh[nf * 2]));
            }
        }
        __syncthreads();
    }

    for (int pt = 0; pt < 5; pt++) {
        const int buf = (16 + pt) & 1;
        if (pt < 4) {
            int nr = (pt == 3) ? 16 : 64;
            issue_tile(g_rvh, g_rvl, (size_t)(pt + 1) * 64, nr, sb + KV_OFF + (buf ^ 1) * KV_BUF);
            CP_WAIT(1);
        } else {
            CP_WAIT(0);
        }
        __syncthreads();

        const uint32_t vb = sb + KV_OFF + buf * KV_BUF;
        const int nk = (pt == 4) ? 1 : 4;
        for (int s = 0; s < nk; s++) {
            uint32_t arow = (uint32_t)(wm * 16 + (lane & 15));
            uint32_t acol = (((lane >> 4) << 3) + pt * 64 + s * 16) * 2;
            uint32_t awh[4], awl[4];
            LDMX4(awh[0], awh[1], awh[2], awh[3], sb + WRH_OFF + arow * 544 + acol);
            LDMX4(awl[0], awl[1], awl[2], awl[3], sb + WRL_OFF + arow * 544 + acol);
            uint32_t baddr = vb + (uint32_t)(s * 16 + (lane & 7) + ((lane >> 3) & 1) * 8) * 144
                           + (wn * 16 + ((lane >> 4) << 3)) * 2;
            uint32_t bvh[4], bvl[4];
            int nrh = (pt == 4) ? 16 : 64;
            LDMX4T(bvh[0], bvh[1], bvh[2], bvh[3], baddr);
            LDMX4T(bvl[0], bvl[1], bvl[2], bvl[3], baddr + (uint32_t)nrh * 144);
#pragma unroll
            for (int nf = 0; nf < 2; nf++) {
                MMA16816(oacc[nf], awh, (&bvh[nf * 2]));
                MMA16816(oacc[nf], awh, (&bvl[nf * 2]));
                MMA16816(oacc[nf], awl, (&bvh[nf * 2]));
            }
        }
        __syncthreads();
    }

    // ================= store out (headed fp32 -> g_attn) =================
    {
        const int bb = bh >> 4, h = bh & 15;
#pragma unroll
        for (int nf = 0; nf < 2; nf++) {
            int row = i0 + wm * 16 + (lane >> 2);
            int d = h * 64 + wn * 16 + nf * 8 + (lane & 3) * 2;
            *(float2*)(g_attn + ((size_t)bb * 1024 + row) * 1024 + d) =
                make_float2(oacc[nf][0], oacc[nf][1]);
            *(float2*)(g_attn + ((size_t)bb * 1024 + row + 8) * 1024 + d) =
                make_float2(oacc[nf][2], oacc[nf][3]);
        }
    }
}

// ---------------------------------------------------------------------------
extern "C" void kernel_launch(void* const* d_in, const int* in_sizes, int n_in,
                              void* d_out, int out_size)
{
    const float* x     = (const float*)d_in[0];
    const float* Wq    = (const float*)d_in[1];
    const float* bq    = (const float*)d_in[2];
    const float* Wk    = (const float*)d_in[3];
    const float* bk    = (const float*)d_in[4];
    const float* Wv    = (const float*)d_in[5];
    const float* bv    = (const float*)d_in[6];
    const float* Wo    = (const float*)d_in[7];
    const float* bo    = (const float*)d_in[8];
    const float* rel_k = (const float*)d_in[9];
    const float* rel_v = (const float*)d_in[10];

    float *q, *qr, *attn;
    __nv_bfloat16 *xh, *xl, *wh, *wl, *qh, *ql, *kh, *kl, *vh, *vl;
    cudaGetSymbolAddress((void**)&q,    g_q);
    cudaGetSymbolAddress((void**)&qr,   g_qr);
    cudaGetSymbolAddress((void**)&attn, g_attn);
    cudaGetSymbolAddress((void**)&xh,   g_xh);
    cudaGetSymbolAddress((void**)&xl,   g_xl);
    cudaGetSymbolAddress((void**)&wh,   g_wh);
    cudaGetSymbolAddress((void**)&wl,   g_wl);
    cudaGetSymbolAddress((void**)&qh,   g_qh);
    cudaGetSymbolAddress((void**)&ql,   g_ql);
    cudaGetSymbolAddress((void**)&kh,   g_kh);
    cudaGetSymbolAddress((void**)&kl,   g_kl);
    cudaGetSymbolAddress((void**)&vh,   g_vh);
    cudaGetSymbolAddress((void**)&vl,   g_vl);

    cudaFuncSetAttribute(gemm_mma, cudaFuncAttributeMaxDynamicSharedMemorySize, GEMM_SMEM);
    cudaFuncSetAttribute(attn_mma, cudaFuncAttributeMaxDynamicSharedMemorySize, ATTN_SMEM);

    dim3 blk(256);
    dim3 gtc(Dd / 128, NROW / 128);                  // (8, 32)

    // x -> split bf16
    split_bf16_kernel<<<4096, blk>>>(x, xh, xl, (NROW * Dd) / 4);

    // projections: q -> fp32 + split bf16 (headed); k, v -> split bf16 only
    split_bf16_kernel<<<1024, blk>>>(Wq, wh, wl, (Dd * Dd) / 4);
    gemm_mma<<<gtc, blk, GEMM_SMEM>>>(xh, xl, wh, wl, bq, q, qh, ql, 1);
    split_bf16_kernel<<<1024, blk>>>(Wk, wh, wl, (Dd * Dd) / 4);
    gemm_mma<<<gtc, blk, GEMM_SMEM>>>(xh, xl, wh, wl, bk, nullptr, kh, kl, 1);
    split_bf16_kernel<<<1024, blk>>>(Wv, wh, wl, (Dd * Dd) / 4);
    gemm_mma<<<gtc, blk, GEMM_SMEM>>>(xh, xl, wh, wl, bv, nullptr, vh, vl, 1);

    // qr[b,h,i,p] = q_i . rel_k[p]
    dim3 gqr((NP + 63) / 64, BHS / 64);
    gemm_nt<<<gqr, blk>>>(q, rel_k, qr, NP, HDd);

    // rel_v split + pad
    relv_prep<<<68, blk>>>(rel_v);

    // MMA attention core
    attn_mma<<<dim3(Ss / 32, Bv * Hh), blk, ATTN_SMEM>>>();

    // output projection -> d_out
    split_bf16_kernel<<<4096, blk>>>(attn, xh, xl, (NROW * Dd) / 4);
    split_bf16_kernel<<<1024, blk>>>(Wo, wh, wl, (Dd * Dd) / 4);
    gemm_mma<<<gtc, blk, GEMM_SMEM>>>(xh, xl, wh, wl, bo, (float*)d_out, nullptr, nullptr, 0);
}

// round 5
// speedup vs baseline: 2.4987x; 1.0294x over previous
#include <cuda_runtime.h>
#include <cuda_bf16.h>
#include <cstdint>

#define Bv 4
#define Hh 16
#define Ss 1024
#define Dd 1024
#define HDd 64
#define NP 257          // 2*128+1 relative buckets
#define NPP 384         // padded bucket rows (multiple of 128)
#define NROW (Bv*Ss)    // 4096
#define BHS (Bv*Hh*Ss)  // 65536

// ---------------- scratch (device globals: allocation-free) ----------------
__device__ float g_qr[(size_t)BHS * NPP];
__device__ float g_attn[(size_t)NROW * Dd];
__device__ __nv_bfloat16 g_qh[BHS * HDd];
__device__ __nv_bfloat16 g_ql[BHS * HDd];
__device__ __nv_bfloat16 g_kh[BHS * HDd];
__device__ __nv_bfloat16 g_kl[BHS * HDd];
__device__ __nv_bfloat16 g_vh[BHS * HDd];
__device__ __nv_bfloat16 g_vl[BHS * HDd];
__device__ __nv_bfloat16 g_rvh[272 * 64];
__device__ __nv_bfloat16 g_rvl[272 * 64];
__device__ __nv_bfloat16 g_rkh[NPP * 64];
__device__ __nv_bfloat16 g_rkl[NPP * 64];
__device__ __nv_bfloat16 g_xh[(size_t)NROW * Dd];
__device__ __nv_bfloat16 g_xl[(size_t)NROW * Dd];
__device__ __nv_bfloat16 g_wh[(size_t)Dd * Dd];
__device__ __nv_bfloat16 g_wl[(size_t)Dd * Dd];

// ====================== PTX helpers (family-portable only) ======================
__device__ __forceinline__ uint32_t smem_u32(const void* p) {
    uint32_t a;
    asm("{ .reg .u64 t; cvta.to.shared.u64 t, %1; cvt.u32.u64 %0, t; }" : "=r"(a) : "l"(p));
    return a;
}

#define LDMX4(r0, r1, r2, r3, addr) \
    asm volatile("ldmatrix.sync.aligned.m8n8.x4.shared.b16 {%0,%1,%2,%3}, [%4];" \
                 : "=r"(r0), "=r"(r1), "=r"(r2), "=r"(r3) : "r"(addr))

#define LDMX2(r0, r1, addr) \
    asm volatile("ldmatrix.sync.aligned.m8n8.x2.shared.b16 {%0,%1}, [%2];" \
                 : "=r"(r0), "=r"(r1) : "r"(addr))

#define LDMX4T(r0, r1, r2, r3, addr) \
    asm volatile("ldmatrix.sync.aligned.m8n8.x4.trans.shared.b16 {%0,%1,%2,%3}, [%4];" \
                 : "=r"(r0), "=r"(r1), "=r"(r2), "=r"(r3) : "r"(addr))

#define MMA16816(c, a, b) \
    asm volatile("mma.sync.aligned.m16n8k16.row.col.f32.bf16.bf16.f32 " \
                 "{%0,%1,%2,%3}, {%4,%5,%6,%7}, {%8,%9}, {%0,%1,%2,%3};" \
                 : "+f"((c)[0]), "+f"((c)[1]), "+f"((c)[2]), "+f"((c)[3]) \
                 : "r"((a)[0]), "r"((a)[1]), "r"((a)[2]), "r"((a)[3]), \
                   "r"((b)[0]), "r"((b)[1]))

#define CP_ASYNC16(s, g) \
    asm volatile("cp.async.cg.shared.global [%0], [%1], 16;" :: "r"(s), "l"(g))
#define CP_COMMIT() asm volatile("cp.async.commit_group;" ::: "memory")
#define CP_WAIT(n)  asm volatile("cp.async.wait_group %0;" :: "n"(n) : "memory")

// ---------------------------------------------------------------------------
// split f32 -> (hi bf16, lo bf16)
// ---------------------------------------------------------------------------
__global__ void split_bf16_kernel(const float* __restrict__ in,
                                  __nv_bfloat16* __restrict__ hi,
                                  __nv_bfloat16* __restrict__ lo, int n4)
{
    int i = blockIdx.x * 256 + threadIdx.x;
    if (i >= n4) return;
    float4 v = ((const float4*)in)[i];
    float vv[4] = {v.x, v.y, v.z, v.w};
    __nv_bfloat16 h[4], l[4];
#pragma unroll
    for (int j = 0; j < 4; j++) {
        h[j] = __float2bfloat16(vv[j]);
        l[j] = __float2bfloat16(vv[j] - __bfloat162float(h[j]));
    }
    ((__nv_bfloat162*)hi)[i * 2 + 0] = __nv_bfloat162(h[0], h[1]);
    ((__nv_bfloat162*)hi)[i * 2 + 1] = __nv_bfloat162(h[2], h[3]);
    ((__nv_bfloat162*)lo)[i * 2 + 0] = __nv_bfloat162(l[0], l[1]);
    ((__nv_bfloat162*)lo)[i * 2 + 1] = __nv_bfloat162(l[2], l[3]);
}

// rel_k -> split bf16 padded to 384 rows; rel_v -> split bf16 padded to 272 rows
__global__ void rel_prep(const float* __restrict__ rel_k, const float* __restrict__ rel_v)
{
    int idx = blockIdx.x * 256 + threadIdx.x;
    if (idx < NPP * 64) {
        int p = idx >> 6, d = idx & 63;
        float v = (p < NP) ? rel_k[p * 64 + d] : 0.f;
        __nv_bfloat16 h = __float2bfloat16(v);
        g_rkh[idx] = h;
        g_rkl[idx] = __float2bfloat16(v - __bfloat162float(h));
    }
    if (idx < 272 * 64) {
        int p = idx >> 6, d = idx & 63;
        float v = (p < NP) ? rel_v[p * 64 + d] : 0.f;
        __nv_bfloat16 h = __float2bfloat16(v);
        g_rvh[idx] = h;
        g_rvl[idx] = __float2bfloat16(v - __bfloat162float(h));
    }
}

// ---------------------------------------------------------------------------
// Warp-MMA split-bf16 NT GEMM:
// optional fp32 output Cf, optional split-bf16 outputs Ch/Cl; headed flag.
// ---------------------------------------------------------------------------
#define SPB 80
#define MAT_SM (128 * SPB)
#define BUF_SM (4 * MAT_SM)
#define GEMM_SMEM (2 * BUF_SM)

__global__ __launch_bounds__(256, 2)
void gemm_mma(const __nv_bfloat16* __restrict__ Ah_, const __nv_bfloat16* __restrict__ Al_,
              const __nv_bfloat16* __restrict__ Bh_, const __nv_bfloat16* __restrict__ Bl_,
              const float* __restrict__ bias, float* __restrict__ Cf,
              __nv_bfloat16* __restrict__ Ch, __nv_bfloat16* __restrict__ Cl, int headed)
{
    extern __shared__ char sm[];
    const uint32_t sb = smem_u32(sm);
    const int t    = threadIdx.x;
    const int wid  = t >> 5;
    const int lane = t & 31;
    const int m0 = blockIdx.y * 128;
    const int n0 = blockIdx.x * 128;
    const int wm = wid >> 2;
    const int wn = wid & 3;

    const char* gb0 = (const char*)(Ah_ + (size_t)m0 * 1024);
    const char* gb1 = (const char*)(Al_ + (size_t)m0 * 1024);
    const char* gb2 = (const char*)(Bh_ + (size_t)n0 * 1024);
    const char* gb3 = (const char*)(Bl_ + (size_t)n0 * 1024);

    auto issue = [&](int chunk, int buf) {
#pragma unroll
        for (int it = 0; it < 8; it++) {
            int id  = t + it * 256;
            int mat = id >> 9;
            int row = (id >> 2) & 127;
            int c16 = id & 3;
            const char* g = (mat == 0 ? gb0 : mat == 1 ? gb1 : mat == 2 ? gb2 : gb3);
            uint32_t sa = sb + buf * BUF_SM + mat * MAT_SM + row * SPB + c16 * 16;
            CP_ASYNC16(sa, g + (size_t)row * 2048 + chunk * 64 + c16 * 16);
        }
        CP_COMMIT();
    };

    float acc[4][4][4];
#pragma unroll
    for (int i = 0; i < 4; i++)
#pragma unroll
        for (int j = 0; j < 4; j++)
#pragma unroll
            for (int r = 0; r < 4; r++) acc[i][j][r] = 0.f;

    issue(0, 0);
    for (int c = 0; c < 32; c++) {
        const int buf = c & 1;
        if (c + 1 < 32) { issue(c + 1, buf ^ 1); CP_WAIT(1); }
        else            { CP_WAIT(0); }
        __syncthreads();

        const uint32_t Ahb = sb + buf * BUF_SM;
        const uint32_t Alb = Ahb + MAT_SM;
        const uint32_t Bhb = Ahb + 2 * MAT_SM;
        const uint32_t Blb = Ahb + 3 * MAT_SM;

#pragma unroll
        for (int s = 0; s < 2; s++) {
            uint32_t ah[4][4], al[4][4];
            const int arow = wm * 64 + (lane & 15);
            const int acolB = (((lane >> 4) << 3) + s * 16) * 2;
#pragma unroll
            for (int mf = 0; mf < 4; mf++) {
                uint32_t ad = Ahb + (uint32_t)(arow + mf * 16) * SPB + acolB;
                LDMX4(ah[mf][0], ah[mf][1], ah[mf][2], ah[mf][3], ad);
                ad = Alb + (uint32_t)(arow + mf * 16) * SPB + acolB;
                LDMX4(al[mf][0], al[mf][1], al[mf][2], al[mf][3], ad);
            }
            uint32_t bh[4][2], bl[4][2];
            const int brow = wn * 32 + (lane & 7) + ((lane >> 4) << 3);
            const int bcolB = ((((lane >> 3) & 1) << 3) + s * 16) * 2;
#pragma unroll
            for (int g = 0; g < 2; g++) {
                uint32_t r0, r1, r2, r3;
                uint32_t bd = Bhb + (uint32_t)(brow + g * 16) * SPB + bcolB;
                LDMX4(r0, r1, r2, r3, bd);
                bh[g * 2][0] = r0; bh[g * 2][1] = r1;
                bh[g * 2 + 1][0] = r2; bh[g * 2 + 1][1] = r3;
                bd = Blb + (uint32_t)(brow + g * 16) * SPB + bcolB;
                LDMX4(r0, r1, r2, r3, bd);
                bl[g * 2][0] = r0; bl[g * 2][1] = r1;
                bl[g * 2 + 1][0] = r2; bl[g * 2 + 1][1] = r3;
            }
#pragma unroll
            for (int mf = 0; mf < 4; mf++)
#pragma unroll
                for (int nf = 0; nf < 4; nf++) {
                    MMA16816(acc[mf][nf], ah[mf], bh[nf]);
                    MMA16816(acc[mf][nf], ah[mf], bl[nf]);
                    MMA16816(acc[mf][nf], al[mf], bh[nf]);
                }
        }
        __syncthreads();
    }

#pragma unroll
    for (int mf = 0; mf < 4; mf++) {
#pragma unroll
        for (int nf = 0; nf < 4; nf++) {
            int m = m0 + wm * 64 + mf * 16 + (lane >> 2);
            int n = n0 + wn * 32 + nf * 8 + (lane & 3) * 2;
            float p0 = acc[mf][nf][0] + bias[n];
            float p1 = acc[mf][nf][1] + bias[n + 1];
            float p2 = acc[mf][nf][2] + bias[n];
            float p3 = acc[mf][nf][3] + bias[n + 1];
            size_t off0, off1;
            if (headed) {
                int h = n >> 6, d = n & 63;
                int bb = m >> 10, s1 = m & 1023;
                off0 = ((((size_t)bb * Hh + h) << 10) + s1) * HDd + d;
                off1 = ((((size_t)bb * Hh + h) << 10) + s1 + 8) * HDd + d;
            } else {
                off0 = (size_t)m * 1024 + n;
                off1 = (size_t)(m + 8) * 1024 + n;
            }
            if (Cf) {
                *(float2*)(Cf + off0) = make_float2(p0, p1);
                *(float2*)(Cf + off1) = make_float2(p2, p3);
            }
            if (Ch) {
                __nv_bfloat16 h0 = __float2bfloat16(p0), h1 = __float2bfloat16(p1);
                __nv_bfloat16 h2 = __float2bfloat16(p2), h3 = __float2bfloat16(p3);
                *(__nv_bfloat162*)(Ch + off0) = __nv_bfloat162(h0, h1);
                *(__nv_bfloat162*)(Ch + off1) = __nv_bfloat162(h2, h3);
                __nv_bfloat16 l0 = __float2bfloat16(p0 - __bfloat162float(h0));
                __nv_bfloat16 l1 = __float2bfloat16(p1 - __bfloat162float(h1));
                __nv_bfloat16 l2 = __float2bfloat16(p2 - __bfloat162float(h2));
                __nv_bfloat16 l3 = __float2bfloat16(p3 - __bfloat162float(h3));
                *(__nv_bfloat162*)(Cl + off0) = __nv_bfloat162(l0, l1);
                *(__nv_bfloat162*)(Cl + off1) = __nv_bfloat162(l2, l3);
            }
        }
    }
}

// ---------------------------------------------------------------------------
// qr GEMM via MMA: g_qr[m, p] = q_m . rel_k[p], m in [0,BHS), p in [0,NPP)
// single-shot K=64, 128x128 tile, grid (NPP/128, BHS/128).
// ---------------------------------------------------------------------------
#define QSPB 144
#define QMAT (128 * QSPB)          // 18432
#define QR_SMEM (4 * QMAT)         // 73728

__global__ __launch_bounds__(256)
void gemm_qr(float* __restrict__ C)
{
    extern __shared__ char sm[];
    const uint32_t sb = smem_u32(sm);
    const int t = threadIdx.x, lane = t & 31, wid = t >> 5;
    const int m0 = blockIdx.y * 128;
    const int n0 = blockIdx.x * 128;
    const int wm = wid >> 2, wn = wid & 3;

    const char* gb0 = (const char*)(g_qh + (size_t)m0 * 64);
    const char* gb1 = (const char*)(g_ql + (size_t)m0 * 64);
    const char* gb2 = (const char*)(g_rkh + (size_t)n0 * 64);
    const char* gb3 = (const char*)(g_rkl + (size_t)n0 * 64);

#pragma unroll
    for (int it = 0; it < 16; it++) {
        int id = t + it * 256;
        int mat = id >> 10;
        int row = (id >> 3) & 127;
        int c16 = id & 7;
        const char* g = (mat == 0 ? gb0 : mat == 1 ? gb1 : mat == 2 ? gb2 : gb3);
        CP_ASYNC16(sb + mat * QMAT + row * QSPB + c16 * 16,
                   g + (size_t)row * 128 + c16 * 16);
    }
    CP_COMMIT();
    CP_WAIT(0);
    __syncthreads();

    float acc[4][4][4];
#pragma unroll
    for (int i = 0; i < 4; i++)
#pragma unroll
        for (int j = 0; j < 4; j++)
#pragma unroll
            for (int r = 0; r < 4; r++) acc[i][j][r] = 0.f;

    const uint32_t Ahb = sb, Alb = sb + QMAT, Bhb = sb + 2 * QMAT, Blb = sb + 3 * QMAT;
#pragma unroll
    for (int s = 0; s < 4; s++) {
        uint32_t ah[4][4], al[4][4];
        const int arow = wm * 64 + (lane & 15);
        const int acolB = (((lane >> 4) << 3) + s * 16) * 2;
#pragma unroll
        for (int mf = 0; mf < 4; mf++) {
            uint32_t ad = Ahb + (uint32_t)(arow + mf * 16) * QSPB + acolB;
            LDMX4(ah[mf][0], ah[mf][1], ah[mf][2], ah[mf][3], ad);
            ad = Alb + (uint32_t)(arow + mf * 16) * QSPB + acolB;
            LDMX4(al[mf][0], al[mf][1], al[mf][2], al[mf][3], ad);
        }
        uint32_t bh[4][2], bl[4][2];
        const int brow = wn * 32 + (lane & 7) + ((lane >> 4) << 3);
        const int bcolB = ((((lane >> 3) & 1) << 3) + s * 16) * 2;
#pragma unroll
        for (int g = 0; g < 2; g++) {
            uint32_t r0, r1, r2, r3;
            uint32_t bd = Bhb + (uint32_t)(brow + g * 16) * QSPB + bcolB;
            LDMX4(r0, r1, r2, r3, bd);
            bh[g * 2][0] = r0; bh[g * 2][1] = r1;
            bh[g * 2 + 1][0] = r2; bh[g * 2 + 1][1] = r3;
            bd = Blb + (uint32_t)(brow + g * 16) * QSPB + bcolB;
            LDMX4(r0, r1, r2, r3, bd);
            bl[g * 2][0] = r0; bl[g * 2][1] = r1;
            bl[g * 2 + 1][0] = r2; bl[g * 2 + 1][1] = r3;
        }
#pragma unroll
        for (int mf = 0; mf < 4; mf++)
#pragma unroll
            for (int nf = 0; nf < 4; nf++) {
                MMA16816(acc[mf][nf], ah[mf], bh[nf]);
                MMA16816(acc[mf][nf], ah[mf], bl[nf]);
                MMA16816(acc[mf][nf], al[mf], bh[nf]);
            }
    }

#pragma unroll
    for (int mf = 0; mf < 4; mf++)
#pragma unroll
        for (int nf = 0; nf < 4; nf++) {
            int m = m0 + wm * 64 + mf * 16 + (lane >> 2);
            int n = n0 + wn * 32 + nf * 8 + (lane & 3) * 2;
            *(float2*)(C + (size_t)m * NPP + n) =
                make_float2(acc[mf][nf][0], acc[mf][nf][1]);
            *(float2*)(C + (size_t)(m + 8) * NPP + n) =
                make_float2(acc[mf][nf][2], acc[mf][nf][3]);
        }
}

// ---------------------------------------------------------------------------
// MMA attention core. Block = (bh, 32 query rows). 256 threads, 8 warps.
// ---------------------------------------------------------------------------
#define Q_OFF   0u
#define KV_OFF  9216u
#define KV_BUF  18432u
#define SS_OFF  46080u
#define WRH_OFF 178176u
#define WRL_OFF 195584u
#define ATTN_SMEM 212992

__global__ __launch_bounds__(256, 1)
void attn_mma()
{
    extern __shared__ char sm[];
    const uint32_t sb = smem_u32(sm);
    const int t = threadIdx.x, lane = t & 31, wid = t >> 5;
    const int bh = blockIdx.y;
    const int i0 = blockIdx.x * 32;
    const int wm = wid >> 2, wn = wid & 3;

    auto issue_tile = [&](const __nv_bfloat16* sh, const __nv_bfloat16* sl,
                          size_t row0, int nrows, uint32_t dst) {
#pragma unroll
        for (int it = 0; it < 4; it++) {
            int id = t + it * 256;
            int sel = id / (nrows * 8);
            if (sel < 2) {
                int rid = id % (nrows * 8);
                int row = rid >> 3, c16 = rid & 7;
                const __nv_bfloat16* s = (sel ? sl : sh) + (row0 + row) * 64 + c16 * 8;
                CP_ASYNC16(dst + (uint32_t)sel * (nrows * 144) + row * 144 + c16 * 16, s);
            }
        }
        CP_COMMIT();
    };

    const size_t bhrow = (size_t)bh * 1024;

    issue_tile(g_qh, g_ql, bhrow + i0, 32, sb + Q_OFF);
    issue_tile(g_kh, g_kl, bhrow, 64, sb + KV_OFF);

    uint32_t qh_f[2][4][4], ql_f[2][4][4];

    // ================= scores =================
    for (int kt = 0; kt < 16; kt++) {
        const int buf = kt & 1;
        if (kt < 15) {
            issue_tile(g_kh, g_kl, bhrow + (kt + 1) * 64, 64, sb + KV_OFF + (buf ^ 1) * KV_BUF);
            CP_WAIT(1);
        } else {
            CP_WAIT(0);
        }
        __syncthreads();

        if (kt == 0) {
#pragma unroll
            for (int mf = 0; mf < 2; mf++)
#pragma unroll
                for (int s = 0; s < 4; s++) {
                    uint32_t a = sb + Q_OFF + (uint32_t)(mf * 16 + (lane & 15)) * 144
                               + (((lane >> 4) << 3) + s * 16) * 2;
                    LDMX4(qh_f[mf][s][0], qh_f[mf][s][1], qh_f[mf][s][2], qh_f[mf][s][3], a);
                    LDMX4(ql_f[mf][s][0], ql_f[mf][s][1], ql_f[mf][s][2], ql_f[mf][s][3], a + 4608);
                }
        }

        float acc[2][4] = {{0.f,0.f,0.f,0.f},{0.f,0.f,0.f,0.f}};
        const uint32_t kb = sb + KV_OFF + buf * KV_BUF;
#pragma unroll
        for (int s = 0; s < 4; s++) {
            uint32_t addr = kb + (uint32_t)(wid * 8 + (lane & 7)) * 144
                          + ((((lane >> 3) & 1) * 8) + s * 16) * 2;
            uint32_t bh2[2], bl2[2];
            LDMX2(bh2[0], bh2[1], addr);
            LDMX2(bl2[0], bl2[1], addr + 9216);
#pragma unroll
            for (int mf = 0; mf < 2; mf++) {
                MMA16816(acc[mf], qh_f[mf][s], bh2);
                MMA16816(acc[mf], qh_f[mf][s], bl2);
                MMA16816(acc[mf], ql_f[mf][s], bh2);
            }
        }
#pragma unroll
        for (int mf = 0; mf < 2; mf++) {
            int row = mf * 16 + (lane >> 2);
            int col = kt * 64 + wid * 8 + (lane & 3) * 2;
            *(float2*)(sm + SS_OFF + (uint32_t)row * 4128 + col * 4) =
                make_float2(acc[mf][0], acc[mf][1]);
            *(float2*)(sm + SS_OFF + (uint32_t)(row + 8) * 4128 + col * 4) =
                make_float2(acc[mf][2], acc[mf][3]);
        }
        __syncthreads();
    }

    // ================= relative bias + scale =================
    {
        const float* qrb = g_qr + (size_t)bh * Ss * NPP;
#pragma unroll 8
        for (int kk = 0; kk < 128; kk++) {
            int v = kk * 256 + t;
            int row = v >> 10, col = v & 1023;
            int i = i0 + row;
            int rel = col - i;
            rel = rel < -128 ? -128 : (rel > 128 ? 128 : rel);
            float* p = (float*)(sm + SS_OFF + (uint32_t)row * 4128 + col * 4);
            *p = (*p + qrb[(size_t)i * NPP + rel + 128]) * 0.125f;
        }
    }
    __syncthreads();

    // ================= softmax + wr extraction (4 rows per warp) =================
    for (int rr = 0; rr < 4; rr++) {
        const int row = wid * 4 + rr;
        float* rp = (float*)(sm + SS_OFF + (uint32_t)row * 4128);
        float mx = -1e30f;
        for (int j = lane; j < 1024; j += 32) mx = fmaxf(mx, rp[j]);
#pragma unroll
        for (int o = 16; o > 0; o >>= 1) mx = fmaxf(mx, __shfl_xor_sync(0xffffffffu, mx, o));
        float sum = 0.f;
        for (int j = lane; j < 1024; j += 32) { float e = __expf(rp[j] - mx); rp[j] = e; sum += e; }
#pragma unroll
        for (int o = 16; o > 0; o >>= 1) sum += __shfl_xor_sync(0xffffffffu, sum, o);
        float inv = 1.f / sum;
        for (int j = lane; j < 1024; j += 32) rp[j] *= inv;
        __syncwarp();

        const int i = i0 + row;
        __nv_bfloat16* wh_ = (__nv_bfloat16*)(sm + WRH_OFF + (uint32_t)row * 544);
        __nv_bfloat16* wl_ = (__nv_bfloat16*)(sm + WRL_OFF + (uint32_t)row * 544);
        for (int p = 1 + lane; p < 256; p += 32) {
            int j = i + p - 128;
            float val = (j >= 0 && j < 1024) ? rp[j] : 0.f;
            __nv_bfloat16 h = __float2bfloat16(val);
            wh_[p] = h;
            wl_[p] = __float2bfloat16(val - __bfloat162float(h));
        }
        float s0 = 0.f;
        for (int j = lane; j <= i - 128; j += 32) s0 += rp[j];
#pragma unroll
        for (int o = 16; o > 0; o >>= 1) s0 += __shfl_xor_sync(0xffffffffu, s0, o);
        float s2 = 0.f;
        for (int j = i + 128 + lane; j < 1024; j += 32) s2 += rp[j];
#pragma unroll
        for (int o = 16; o > 0; o >>= 1) s2 += __shfl_xor_sync(0xffffffffu, s2, o);
        if (lane == 0) {
            __nv_bfloat16 h0 = __float2bfloat16(s0);
            wh_[0] = h0; wl_[0] = __float2bfloat16(s0 - __bfloat162float(h0));
            __nv_bfloat16 h2 = __float2bfloat16(s2);
            wh_[256] = h2; wl_[256] = __float2bfloat16(s2 - __bfloat162float(h2));
        }
        if (lane < 15) { wh_[257 + lane] = __float2bfloat16(0.f);
                         wl_[257 + lane] = __float2bfloat16(0.f); }
    }
    __syncthreads();

    // ================= in-place fp32 w -> (hi,lo) bf16 per row slot =================
    for (int g = 0; g < 4; g++) {
        float tmp[32];
#pragma unroll
        for (int kk = 0; kk < 32; kk++) {
            int v = g * 8192 + kk * 256 + t;
            int row = v >> 10, col = v & 1023;
            tmp[kk] = *(const float*)(sm + SS_OFF + (uint32_t)row * 4128 + col * 4);
        }
        __syncthreads();
#pragma unroll
        for (int kk = 0; kk < 32; kk++) {
            int v = g * 8192 + kk * 256 + t;
            int row = v >> 10, col = v & 1023;
            __nv_bfloat16 h = __float2bfloat16(tmp[kk]);
            __nv_bfloat16 l = __float2bfloat16(tmp[kk] - __bfloat162float(h));
            *(__nv_bfloat16*)(sm + SS_OFF + (uint32_t)row * 4128 + col * 2) = h;
            *(__nv_bfloat16*)(sm + SS_OFF + (uint32_t)row * 4128 + 2064 + col * 2) = l;
        }
        __syncthreads();
    }

    // ================= PV (w @ v) + relative-V (wr @ rel_v) =================
    float oacc[2][4] = {{0.f,0.f,0.f,0.f},{0.f,0.f,0.f,0.f}};

    issue_tile(g_vh, g_vl, bhrow, 64, sb + KV_OFF);
    for (int vt = 0; vt < 16; vt++) {
        const int buf = vt & 1;
        if (vt < 15) issue_tile(g_vh, g_vl, bhrow + (vt + 1) * 64, 64, sb + KV_OFF + (buf ^ 1) * KV_BUF);
        else         issue_tile(g_rvh, g_rvl, 0, 64, sb + KV_OFF + (buf ^ 1) * KV_BUF);
        CP_WAIT(1);
        __syncthreads();

        const uint32_t vb = sb + KV_OFF + buf * KV_BUF;
#pragma unroll
        for (int s = 0; s < 4; s++) {
            uint32_t aaddr = sb + SS_OFF + (uint32_t)(wm * 16 + (lane & 15)) * 4128
                           + (((lane >> 4) << 3) + vt * 64 + s * 16) * 2;
            uint32_t awh[4], awl[4];
            LDMX4(awh[0], awh[1], awh[2], awh[3], aaddr);
            LDMX4(awl[0], awl[1], awl[2], awl[3], aaddr + 2064);
            uint32_t baddr = vb + (uint32_t)(s * 16 + (lane & 7) + ((lane >> 3) & 1) * 8) * 144
                           + (wn * 16 + ((lane >> 4) << 3)) * 2;
            uint32_t bvh[4], bvl[4];
            LDMX4T(bvh[0], bvh[1], bvh[2], bvh[3], baddr);
            LDMX4T(bvl[0], bvl[1], bvl[2], bvl[3], baddr + 9216);
#pragma unroll
            for (int nf = 0; nf < 2; nf++) {
                MMA16816(oacc[nf], awh, (&bvh[nf * 2]));
                MMA16816(oacc[nf], awh, (&bvl[nf * 2]));
                MMA16816(oacc[nf], awl, (&bvh[nf * 2]));
            }
        }
        __syncthreads();
    }

    for (int pt = 0; pt < 5; pt++) {
        const int buf = (16 + pt) & 1;
        if (pt < 4) {
            int nr = (pt == 3) ? 16 : 64;
            issue_tile(g_rvh, g_rvl, (size_t)(pt + 1) * 64, nr, sb + KV_OFF + (buf ^ 1) * KV_BUF);
            CP_WAIT(1);
        } else {
            CP_WAIT(0);
        }
        __syncthreads();

        const uint32_t vb = sb + KV_OFF + buf * KV_BUF;
        const int nk = (pt == 4) ? 1 : 4;
        for (int s = 0; s < nk; s++) {
            uint32_t arow = (uint32_t)(wm * 16 + (lane & 15));
            uint32_t acol = (((lane >> 4) << 3) + pt * 64 + s * 16) * 2;
            uint32_t awh[4], awl[4];
            LDMX4(awh[0], awh[1], awh[2], awh[3], sb + WRH_OFF + arow * 544 + acol);
            LDMX4(awl[0], awl[1], awl[2], awl[3], sb + WRL_OFF + arow * 544 + acol);
            uint32_t baddr = vb + (uint32_t)(s * 16 + (lane & 7) + ((lane >> 3) & 1) * 8) * 144
                           + (wn * 16 + ((lane >> 4) << 3)) * 2;
            uint32_t bvh[4], bvl[4];
            int nrh = (pt == 4) ? 16 : 64;
            LDMX4T(bvh[0], bvh[1], bvh[2], bvh[3], baddr);
            LDMX4T(bvl[0], bvl[1], bvl[2], bvl[3], baddr + (uint32_t)nrh * 144);
#pragma unroll
            for (int nf = 0; nf < 2; nf++) {
                MMA16816(oacc[nf], awh, (&bvh[nf * 2]));
                MMA16816(oacc[nf], awh, (&bvl[nf * 2]));
                MMA16816(oacc[nf], awl, (&bvh[nf * 2]));
            }
        }
        __syncthreads();
    }

    // ================= store out (headed fp32 -> g_attn) =================
    {
        const int bb = bh >> 4, h = bh & 15;
#pragma unroll
        for (int nf = 0; nf < 2; nf++) {
            int row = i0 + wm * 16 + (lane >> 2);
            int d = h * 64 + wn * 16 + nf * 8 + (lane & 3) * 2;
            *(float2*)(g_attn + ((size_t)bb * 1024 + row) * 1024 + d) =
                make_float2(oacc[nf][0], oacc[nf][1]);
            *(float2*)(g_attn + ((size_t)bb * 1024 + row + 8) * 1024 + d) =
                make_float2(oacc[nf][2], oacc[nf][3]);
        }
    }
}

// ---------------------------------------------------------------------------
extern "C" void kernel_launch(void* const* d_in, const int* in_sizes, int n_in,
                              void* d_out, int out_size)
{
    const float* x     = (const float*)d_in[0];
    const float* Wq    = (const float*)d_in[1];
    const float* bq    = (const float*)d_in[2];
    const float* Wk    = (const float*)d_in[3];
    const float* bk    = (const float*)d_in[4];
    const float* Wv    = (const float*)d_in[5];
    const float* bv    = (const float*)d_in[6];
    const float* Wo    = (const float*)d_in[7];
    const float* bo    = (const float*)d_in[8];
    const float* rel_k = (const float*)d_in[9];
    const float* rel_v = (const float*)d_in[10];

    float *qr, *attn;
    __nv_bfloat16 *xh, *xl, *wh, *wl, *qh, *ql, *kh, *kl, *vh, *vl;
    cudaGetSymbolAddress((void**)&qr,   g_qr);
    cudaGetSymbolAddress((void**)&attn, g_attn);
    cudaGetSymbolAddress((void**)&xh,   g_xh);
    cudaGetSymbolAddress((void**)&xl,   g_xl);
    cudaGetSymbolAddress((void**)&wh,   g_wh);
    cudaGetSymbolAddress((void**)&wl,   g_wl);
    cudaGetSymbolAddress((void**)&qh,   g_qh);
    cudaGetSymbolAddress((void**)&ql,   g_ql);
    cudaGetSymbolAddress((void**)&kh,   g_kh);
    cudaGetSymbolAddress((void**)&kl,   g_kl);
    cudaGetSymbolAddress((void**)&vh,   g_vh);
    cudaGetSymbolAddress((void**)&vl,   g_vl);

    cudaFuncSetAttribute(gemm_mma, cudaFuncAttributeMaxDynamicSharedMemorySize, GEMM_SMEM);
    cudaFuncSetAttribute(gemm_qr,  cudaFuncAttributeMaxDynamicSharedMemorySize, QR_SMEM);
    cudaFuncSetAttribute(attn_mma, cudaFuncAttributeMaxDynamicSharedMemorySize, ATTN_SMEM);

    dim3 blk(256);
    dim3 gtc(Dd / 128, NROW / 128);                  // (8, 32)

    // x -> split bf16; rel_k / rel_v prep
    split_bf16_kernel<<<4096, blk>>>(x, xh, xl, (NROW * Dd) / 4);
    rel_prep<<<96, blk>>>(rel_k, rel_v);

    // projections -> split bf16 (headed)
    split_bf16_kernel<<<1024, blk>>>(Wq, wh, wl, (Dd * Dd) / 4);
    gemm_mma<<<gtc, blk, GEMM_SMEM>>>(xh, xl, wh, wl, bq, nullptr, qh, ql, 1);
    split_bf16_kernel<<<1024, blk>>>(Wk, wh, wl, (Dd * Dd) / 4);
    gemm_mma<<<gtc, blk, GEMM_SMEM>>>(xh, xl, wh, wl, bk, nullptr, kh, kl, 1);
    split_bf16_kernel<<<1024, blk>>>(Wv, wh, wl, (Dd * Dd) / 4);
    gemm_mma<<<gtc, blk, GEMM_SMEM>>>(xh, xl, wh, wl, bv, nullptr, vh, vl, 1);

    // qr[b,h,i,p] = q_i . rel_k[p]   (MMA, padded N=384)
    gemm_qr<<<dim3(NPP / 128, BHS / 128), blk, QR_SMEM>>>(qr);

    // MMA attention core
    attn_mma<<<dim3(Ss / 32, Bv * Hh), blk, ATTN_SMEM>>>();

    // output projection -> d_out
    split_bf16_kernel<<<4096, blk>>>(attn, xh, xl, (NROW * Dd) / 4);
    split_bf16_kernel<<<1024, blk>>>(Wo, wh, wl, (Dd * Dd) / 4);
    gemm_mma<<<gtc, blk, GEMM_SMEM>>>(xh, xl, wh, wl, bo, (float*)d_out, nullptr, nullptr, 0);
}

// round 6
// speedup vs baseline: 2.7704x; 1.1087x over previous
#include <cuda_runtime.h>
#include <cuda_bf16.h>
#include <cstdint>

#define Bv 4
#define Hh 16
#define Ss 1024
#define Dd 1024
#define HDd 64
#define NP 257          // 2*128+1 relative buckets
#define NPP 384         // padded bucket rows (multiple of 128)
#define NROW (Bv*Ss)    // 4096
#define BHS (Bv*Hh*Ss)  // 65536

// ---------------- scratch (device globals: allocation-free) ----------------
__device__ float g_qr[(size_t)BHS * NPP];
__device__ float g_attn[(size_t)NROW * Dd];
__device__ __nv_bfloat16 g_qh[BHS * HDd];
__device__ __nv_bfloat16 g_ql[BHS * HDd];
__device__ __nv_bfloat16 g_kh[BHS * HDd];
__device__ __nv_bfloat16 g_kl[BHS * HDd];
__device__ __nv_bfloat16 g_vh[BHS * HDd];
__device__ __nv_bfloat16 g_vl[BHS * HDd];
__device__ __nv_bfloat16 g_rvh[272 * 64];
__device__ __nv_bfloat16 g_rvl[272 * 64];
__device__ __nv_bfloat16 g_rkh[NPP * 64];
__device__ __nv_bfloat16 g_rkl[NPP * 64];
__device__ __nv_bfloat16 g_xh[(size_t)NROW * Dd];
__device__ __nv_bfloat16 g_xl[(size_t)NROW * Dd];
__device__ __nv_bfloat16 g_wh[(size_t)Dd * Dd];
__device__ __nv_bfloat16 g_wl[(size_t)Dd * Dd];

// ====================== PTX helpers (family-portable only) ======================
__device__ __forceinline__ uint32_t smem_u32(const void* p) {
    uint32_t a;
    asm("{ .reg .u64 t; cvta.to.shared.u64 t, %1; cvt.u32.u64 %0, t; }" : "=r"(a) : "l"(p));
    return a;
}

#define LDMX4(r0, r1, r2, r3, addr) \
    asm volatile("ldmatrix.sync.aligned.m8n8.x4.shared.b16 {%0,%1,%2,%3}, [%4];" \
                 : "=r"(r0), "=r"(r1), "=r"(r2), "=r"(r3) : "r"(addr))

#define LDMX2(r0, r1, addr) \
    asm volatile("ldmatrix.sync.aligned.m8n8.x2.shared.b16 {%0,%1}, [%2];" \
                 : "=r"(r0), "=r"(r1) : "r"(addr))

#define LDMX2T(r0, r1, addr) \
    asm volatile("ldmatrix.sync.aligned.m8n8.x2.trans.shared.b16 {%0,%1}, [%2];" \
                 : "=r"(r0), "=r"(r1) : "r"(addr))

#define MMA16816(c, a, b) \
    asm volatile("mma.sync.aligned.m16n8k16.row.col.f32.bf16.bf16.f32 " \
                 "{%0,%1,%2,%3}, {%4,%5,%6,%7}, {%8,%9}, {%0,%1,%2,%3};" \
                 : "+f"((c)[0]), "+f"((c)[1]), "+f"((c)[2]), "+f"((c)[3]) \
                 : "r"((a)[0]), "r"((a)[1]), "r"((a)[2]), "r"((a)[3]), \
                   "r"((b)[0]), "r"((b)[1]))

#define CP_ASYNC16(s, g) \
    asm volatile("cp.async.cg.shared.global [%0], [%1], 16;" :: "r"(s), "l"(g))
#define CP_COMMIT() asm volatile("cp.async.commit_group;" ::: "memory")
#define CP_WAIT(n)  asm volatile("cp.async.wait_group %0;" :: "n"(n) : "memory")

// ---------------------------------------------------------------------------
// split f32 -> (hi bf16, lo bf16)
// ---------------------------------------------------------------------------
__global__ void split_bf16_kernel(const float* __restrict__ in,
                                  __nv_bfloat16* __restrict__ hi,
                                  __nv_bfloat16* __restrict__ lo, int n4)
{
    int i = blockIdx.x * 256 + threadIdx.x;
    if (i >= n4) return;
    float4 v = ((const float4*)in)[i];
    float vv[4] = {v.x, v.y, v.z, v.w};
    __nv_bfloat16 h[4], l[4];
#pragma unroll
    for (int j = 0; j < 4; j++) {
        h[j] = __float2bfloat16(vv[j]);
        l[j] = __float2bfloat16(vv[j] - __bfloat162float(h[j]));
    }
    ((__nv_bfloat162*)hi)[i * 2 + 0] = __nv_bfloat162(h[0], h[1]);
    ((__nv_bfloat162*)hi)[i * 2 + 1] = __nv_bfloat162(h[2], h[3]);
    ((__nv_bfloat162*)lo)[i * 2 + 0] = __nv_bfloat162(l[0], l[1]);
    ((__nv_bfloat162*)lo)[i * 2 + 1] = __nv_bfloat162(l[2], l[3]);
}

// rel_k -> split bf16 padded to 384 rows; rel_v -> split bf16 padded to 272 rows
__global__ void rel_prep(const float* __restrict__ rel_k, const float* __restrict__ rel_v)
{
    int idx = blockIdx.x * 256 + threadIdx.x;
    if (idx < NPP * 64) {
        int p = idx >> 6, d = idx & 63;
        float v = (p < NP) ? rel_k[p * 64 + d] : 0.f;
        __nv_bfloat16 h = __float2bfloat16(v);
        g_rkh[idx] = h;
        g_rkl[idx] = __float2bfloat16(v - __bfloat162float(h));
    }
    if (idx < 272 * 64) {
        int p = idx >> 6, d = idx & 63;
        float v = (p < NP) ? rel_v[p * 64 + d] : 0.f;
        __nv_bfloat16 h = __float2bfloat16(v);
        g_rvh[idx] = h;
        g_rvl[idx] = __float2bfloat16(v - __bfloat162float(h));
    }
}

// ---------------------------------------------------------------------------
// Warp-MMA split-bf16 NT GEMM (unchanged from R5)
// ---------------------------------------------------------------------------
#define SPB 80
#define MAT_SM (128 * SPB)
#define BUF_SM (4 * MAT_SM)
#define GEMM_SMEM (2 * BUF_SM)

__global__ __launch_bounds__(256, 2)
void gemm_mma(const __nv_bfloat16* __restrict__ Ah_, const __nv_bfloat16* __restrict__ Al_,
              const __nv_bfloat16* __restrict__ Bh_, const __nv_bfloat16* __restrict__ Bl_,
              const float* __restrict__ bias, float* __restrict__ Cf,
              __nv_bfloat16* __restrict__ Ch, __nv_bfloat16* __restrict__ Cl, int headed)
{
    extern __shared__ char sm[];
    const uint32_t sb = smem_u32(sm);
    const int t    = threadIdx.x;
    const int wid  = t >> 5;
    const int lane = t & 31;
    const int m0 = blockIdx.y * 128;
    const int n0 = blockIdx.x * 128;
    const int wm = wid >> 2;
    const int wn = wid & 3;

    const char* gb0 = (const char*)(Ah_ + (size_t)m0 * 1024);
    const char* gb1 = (const char*)(Al_ + (size_t)m0 * 1024);
    const char* gb2 = (const char*)(Bh_ + (size_t)n0 * 1024);
    const char* gb3 = (const char*)(Bl_ + (size_t)n0 * 1024);

    auto issue = [&](int chunk, int buf) {
#pragma unroll
        for (int it = 0; it < 8; it++) {
            int id  = t + it * 256;
            int mat = id >> 9;
            int row = (id >> 2) & 127;
            int c16 = id & 3;
            const char* g = (mat == 0 ? gb0 : mat == 1 ? gb1 : mat == 2 ? gb2 : gb3);
            uint32_t sa = sb + buf * BUF_SM + mat * MAT_SM + row * SPB + c16 * 16;
            CP_ASYNC16(sa, g + (size_t)row * 2048 + chunk * 64 + c16 * 16);
        }
        CP_COMMIT();
    };

    float acc[4][4][4];
#pragma unroll
    for (int i = 0; i < 4; i++)
#pragma unroll
        for (int j = 0; j < 4; j++)
#pragma unroll
            for (int r = 0; r < 4; r++) acc[i][j][r] = 0.f;

    issue(0, 0);
    for (int c = 0; c < 32; c++) {
        const int buf = c & 1;
        if (c + 1 < 32) { issue(c + 1, buf ^ 1); CP_WAIT(1); }
        else            { CP_WAIT(0); }
        __syncthreads();

        const uint32_t Ahb = sb + buf * BUF_SM;
        const uint32_t Alb = Ahb + MAT_SM;
        const uint32_t Bhb = Ahb + 2 * MAT_SM;
        const uint32_t Blb = Ahb + 3 * MAT_SM;

#pragma unroll
        for (int s = 0; s < 2; s++) {
            uint32_t ah[4][4], al[4][4];
            const int arow = wm * 64 + (lane & 15);
            const int acolB = (((lane >> 4) << 3) + s * 16) * 2;
#pragma unroll
            for (int mf = 0; mf < 4; mf++) {
                uint32_t ad = Ahb + (uint32_t)(arow + mf * 16) * SPB + acolB;
                LDMX4(ah[mf][0], ah[mf][1], ah[mf][2], ah[mf][3], ad);
                ad = Alb + (uint32_t)(arow + mf * 16) * SPB + acolB;
                LDMX4(al[mf][0], al[mf][1], al[mf][2], al[mf][3], ad);
            }
            uint32_t bh[4][2], bl[4][2];
            const int brow = wn * 32 + (lane & 7) + ((lane >> 4) << 3);
            const int bcolB = ((((lane >> 3) & 1) << 3) + s * 16) * 2;
#pragma unroll
            for (int g = 0; g < 2; g++) {
                uint32_t r0, r1, r2, r3;
                uint32_t bd = Bhb + (uint32_t)(brow + g * 16) * SPB + bcolB;
                LDMX4(r0, r1, r2, r3, bd);
                bh[g * 2][0] = r0; bh[g * 2][1] = r1;
                bh[g * 2 + 1][0] = r2; bh[g * 2 + 1][1] = r3;
                bd = Blb + (uint32_t)(brow + g * 16) * SPB + bcolB;
                LDMX4(r0, r1, r2, r3, bd);
                bl[g * 2][0] = r0; bl[g * 2][1] = r1;
                bl[g * 2 + 1][0] = r2; bl[g * 2 + 1][1] = r3;
            }
#pragma unroll
            for (int mf = 0; mf < 4; mf++)
#pragma unroll
                for (int nf = 0; nf < 4; nf++) {
                    MMA16816(acc[mf][nf], ah[mf], bh[nf]);
                    MMA16816(acc[mf][nf], ah[mf], bl[nf]);
                    MMA16816(acc[mf][nf], al[mf], bh[nf]);
                }
        }
        __syncthreads();
    }

#pragma unroll
    for (int mf = 0; mf < 4; mf++) {
#pragma unroll
        for (int nf = 0; nf < 4; nf++) {
            int m = m0 + wm * 64 + mf * 16 + (lane >> 2);
            int n = n0 + wn * 32 + nf * 8 + (lane & 3) * 2;
            float p0 = acc[mf][nf][0] + bias[n];
            float p1 = acc[mf][nf][1] + bias[n + 1];
            float p2 = acc[mf][nf][2] + bias[n];
            float p3 = acc[mf][nf][3] + bias[n + 1];
            size_t off0, off1;
            if (headed) {
                int h = n >> 6, d = n & 63;
                int bb = m >> 10, s1 = m & 1023;
                off0 = ((((size_t)bb * Hh + h) << 10) + s1) * HDd + d;
                off1 = ((((size_t)bb * Hh + h) << 10) + s1 + 8) * HDd + d;
            } else {
                off0 = (size_t)m * 1024 + n;
                off1 = (size_t)(m + 8) * 1024 + n;
            }
            if (Cf) {
                *(float2*)(Cf + off0) = make_float2(p0, p1);
                *(float2*)(Cf + off1) = make_float2(p2, p3);
            }
            if (Ch) {
                __nv_bfloat16 h0 = __float2bfloat16(p0), h1 = __float2bfloat16(p1);
                __nv_bfloat16 h2 = __float2bfloat16(p2), h3 = __float2bfloat16(p3);
                *(__nv_bfloat162*)(Ch + off0) = __nv_bfloat162(h0, h1);
                *(__nv_bfloat162*)(Ch + off1) = __nv_bfloat162(h2, h3);
                __nv_bfloat16 l0 = __float2bfloat16(p0 - __bfloat162float(h0));
                __nv_bfloat16 l1 = __float2bfloat16(p1 - __bfloat162float(h1));
                __nv_bfloat16 l2 = __float2bfloat16(p2 - __bfloat162float(h2));
                __nv_bfloat16 l3 = __float2bfloat16(p3 - __bfloat162float(h3));
                *(__nv_bfloat162*)(Cl + off0) = __nv_bfloat162(l0, l1);
                *(__nv_bfloat162*)(Cl + off1) = __nv_bfloat162(l2, l3);
            }
        }
    }
}

// ---------------------------------------------------------------------------
// qr GEMM via MMA (unchanged from R5)
// ---------------------------------------------------------------------------
#define QSPB 144
#define QMAT (128 * QSPB)
#define QR_SMEM (4 * QMAT)

__global__ __launch_bounds__(256)
void gemm_qr(float* __restrict__ C)
{
    extern __shared__ char sm[];
    const uint32_t sb = smem_u32(sm);
    const int t = threadIdx.x, lane = t & 31, wid = t >> 5;
    const int m0 = blockIdx.y * 128;
    const int n0 = blockIdx.x * 128;
    const int wm = wid >> 2, wn = wid & 3;

    const char* gb0 = (const char*)(g_qh + (size_t)m0 * 64);
    const char* gb1 = (const char*)(g_ql + (size_t)m0 * 64);
    const char* gb2 = (const char*)(g_rkh + (size_t)n0 * 64);
    const char* gb3 = (const char*)(g_rkl + (size_t)n0 * 64);

#pragma unroll
    for (int it = 0; it < 16; it++) {
        int id = t + it * 256;
        int mat = id >> 10;
        int row = (id >> 3) & 127;
        int c16 = id & 7;
        const char* g = (mat == 0 ? gb0 : mat == 1 ? gb1 : mat == 2 ? gb2 : gb3);
        CP_ASYNC16(sb + mat * QMAT + row * QSPB + c16 * 16,
                   g + (size_t)row * 128 + c16 * 16);
    }
    CP_COMMIT();
    CP_WAIT(0);
    __syncthreads();

    float acc[4][4][4];
#pragma unroll
    for (int i = 0; i < 4; i++)
#pragma unroll
        for (int j = 0; j < 4; j++)
#pragma unroll
            for (int r = 0; r < 4; r++) acc[i][j][r] = 0.f;

    const uint32_t Ahb = sb, Alb = sb + QMAT, Bhb = sb + 2 * QMAT, Blb = sb + 3 * QMAT;
#pragma unroll
    for (int s = 0; s < 4; s++) {
        uint32_t ah[4][4], al[4][4];
        const int arow = wm * 64 + (lane & 15);
        const int acolB = (((lane >> 4) << 3) + s * 16) * 2;
#pragma unroll
        for (int mf = 0; mf < 4; mf++) {
            uint32_t ad = Ahb + (uint32_t)(arow + mf * 16) * QSPB + acolB;
            LDMX4(ah[mf][0], ah[mf][1], ah[mf][2], ah[mf][3], ad);
            ad = Alb + (uint32_t)(arow + mf * 16) * QSPB + acolB;
            LDMX4(al[mf][0], al[mf][1], al[mf][2], al[mf][3], ad);
        }
        uint32_t bh[4][2], bl[4][2];
        const int brow = wn * 32 + (lane & 7) + ((lane >> 4) << 3);
        const int bcolB = ((((lane >> 3) & 1) << 3) + s * 16) * 2;
#pragma unroll
        for (int g = 0; g < 2; g++) {
            uint32_t r0, r1, r2, r3;
            uint32_t bd = Bhb + (uint32_t)(brow + g * 16) * QSPB + bcolB;
            LDMX4(r0, r1, r2, r3, bd);
            bh[g * 2][0] = r0; bh[g * 2][1] = r1;
            bh[g * 2 + 1][0] = r2; bh[g * 2 + 1][1] = r3;
            bd = Blb + (uint32_t)(brow + g * 16) * QSPB + bcolB;
            LDMX4(r0, r1, r2, r3, bd);
            bl[g * 2][0] = r0; bl[g * 2][1] = r1;
            bl[g * 2 + 1][0] = r2; bl[g * 2 + 1][1] = r3;
        }
#pragma unroll
        for (int mf = 0; mf < 4; mf++)
#pragma unroll
            for (int nf = 0; nf < 4; nf++) {
                MMA16816(acc[mf][nf], ah[mf], bh[nf]);
                MMA16816(acc[mf][nf], ah[mf], bl[nf]);
                MMA16816(acc[mf][nf], al[mf], bh[nf]);
            }
    }

#pragma unroll
    for (int mf = 0; mf < 4; mf++)
#pragma unroll
        for (int nf = 0; nf < 4; nf++) {
            int m = m0 + wm * 64 + mf * 16 + (lane >> 2);
            int n = n0 + wn * 32 + nf * 8 + (lane & 3) * 2;
            *(float2*)(C + (size_t)m * NPP + n) =
                make_float2(acc[mf][nf][0], acc[mf][nf][1]);
            *(float2*)(C + (size_t)(m + 8) * NPP + n) =
                make_float2(acc[mf][nf][2], acc[mf][nf][3]);
        }
}

// ---------------------------------------------------------------------------
// MMA attention core. Block = (bh, 32 query rows). 512 threads, 16 warps.
// Warp grid: wq = wid>>3 (2 m-groups of 16 rows), wk = wid&7 (8 n-groups of 8).
// 3 independent accumulator chains (hi*hi, hi*lo, lo*hi) merged at store.
// ---------------------------------------------------------------------------
#define Q_OFF   0u
#define KV_OFF  9216u
#define KV_BUF  18432u
#define SS_OFF  46080u
#define WRH_OFF 178176u
#define WRL_OFF 195584u
#define ATTN_SMEM 212992

__global__ __launch_bounds__(512, 1)
void attn_mma()
{
    extern __shared__ char sm[];
    const uint32_t sb = smem_u32(sm);
    const int t = threadIdx.x, lane = t & 31, wid = t >> 5;
    const int bh = blockIdx.y;
    const int i0 = blockIdx.x * 32;
    const int wq = wid >> 3;        // 0..1
    const int wk = wid & 7;         // 0..7

    auto issue_tile = [&](const __nv_bfloat16* sh, const __nv_bfloat16* sl,
                          size_t row0, int nrows, uint32_t dst) {
#pragma unroll
        for (int it = 0; it < 2; it++) {
            int id = t + it * 512;
            if (id < nrows * 16) {
                int sel = id / (nrows * 8);
                int rid = id % (nrows * 8);
                int row = rid >> 3, c16 = rid & 7;
                const __nv_bfloat16* s = (sel ? sl : sh) + (row0 + row) * 64 + c16 * 8;
                CP_ASYNC16(dst + (uint32_t)sel * (nrows * 144) + row * 144 + c16 * 16, s);
            }
        }
        CP_COMMIT();
    };

    const size_t bhrow = (size_t)bh * 1024;

    issue_tile(g_qh, g_ql, bhrow + i0, 32, sb + Q_OFF);
    issue_tile(g_kh, g_kl, bhrow, 64, sb + KV_OFF);

    uint32_t qhf[4][4], qlf[4][4];

    // ================= scores =================
    for (int kt = 0; kt < 16; kt++) {
        const int buf = kt & 1;
        if (kt < 15) {
            issue_tile(g_kh, g_kl, bhrow + (kt + 1) * 64, 64, sb + KV_OFF + (buf ^ 1) * KV_BUF);
            CP_WAIT(1);
        } else {
            CP_WAIT(0);
        }
        __syncthreads();

        if (kt == 0) {
#pragma unroll
            for (int s = 0; s < 4; s++) {
                uint32_t a = sb + Q_OFF + (uint32_t)(wq * 16 + (lane & 15)) * 144
                           + (((lane >> 4) << 3) + s * 16) * 2;
                LDMX4(qhf[s][0], qhf[s][1], qhf[s][2], qhf[s][3], a);
                LDMX4(qlf[s][0], qlf[s][1], qlf[s][2], qlf[s][3], a + 4608);
            }
        }

        float a1[4] = {0.f,0.f,0.f,0.f}, a2[4] = {0.f,0.f,0.f,0.f}, a3[4] = {0.f,0.f,0.f,0.f};
        const uint32_t kb = sb + KV_OFF + buf * KV_BUF;
#pragma unroll
        for (int s = 0; s < 4; s++) {
            uint32_t addr = kb + (uint32_t)(wk * 8 + (lane & 7)) * 144
                          + ((((lane >> 3) & 1) * 8) + s * 16) * 2;
            uint32_t bh2[2], bl2[2];
            LDMX2(bh2[0], bh2[1], addr);
            LDMX2(bl2[0], bl2[1], addr + 9216);
            MMA16816(a1, qhf[s], bh2);
            MMA16816(a2, qhf[s], bl2);
            MMA16816(a3, qlf[s], bh2);
        }
        {
            int row = wq * 16 + (lane >> 2);
            int col = kt * 64 + wk * 8 + (lane & 3) * 2;
            *(float2*)(sm + SS_OFF + (uint32_t)row * 4128 + col * 4) =
                make_float2(a1[0] + a2[0] + a3[0], a1[1] + a2[1] + a3[1]);
            *(float2*)(sm + SS_OFF + (uint32_t)(row + 8) * 4128 + col * 4) =
                make_float2(a1[2] + a2[2] + a3[2], a1[3] + a2[3] + a3[3]);
        }
        __syncthreads();
    }

    // ================= relative bias + scale (qr window staged in smem) ====
    {
        const float* qrb = g_qr + (size_t)bh * Ss * NPP + (size_t)i0 * NPP;
        float* qw = (float*)(sm + KV_OFF);          // 32 x 264 f32 = 33792 B
#pragma unroll
        for (int kk = 0; kk < 4; kk++) {
            int id = kk * 512 + t;                  // 0..2047
            int row = id >> 6, c4 = id & 63;
            float4 v = *(const float4*)(qrb + (size_t)row * NPP + c4 * 4);
            *(float4*)(qw + row * 264 + c4 * 4) = v;
        }
        if (t < 32) qw[t * 264 + 256] = qrb[(size_t)t * NPP + 256];
        __syncthreads();
#pragma unroll 8
        for (int kk = 0; kk < 64; kk++) {
            int v = kk * 512 + t;
            int row = v >> 10, col = v & 1023;
            int rel = col - (i0 + row);
            rel = rel < -128 ? -128 : (rel > 128 ? 128 : rel);
            float* p = (float*)(sm + SS_OFF + (uint32_t)row * 4128 + col * 4);
            *p = (*p + qw[row * 264 + rel + 128]) * 0.125f;
        }
    }
    __syncthreads();

    // prefetch v tile 0 (overlaps softmax + conversion)
    issue_tile(g_vh, g_vl, bhrow, 64, sb + KV_OFF);

    // ================= softmax + wr extraction (2 rows per warp) ===========
    for (int rr = 0; rr < 2; rr++) {
        const int row = wid * 2 + rr;
        float* rp = (float*)(sm + SS_OFF + (uint32_t)row * 4128);
        float mx = -1e30f;
        for (int j = lane; j < 1024; j += 32) mx = fmaxf(mx, rp[j]);
#pragma unroll
        for (int o = 16; o > 0; o >>= 1) mx = fmaxf(mx, __shfl_xor_sync(0xffffffffu, mx, o));
        float sum = 0.f;
        for (int j = lane; j < 1024; j += 32) { float e = __expf(rp[j] - mx); rp[j] = e; sum += e; }
#pragma unroll
        for (int o = 16; o > 0; o >>= 1) sum += __shfl_xor_sync(0xffffffffu, sum, o);
        float inv = 1.f / sum;
        for (int j = lane; j < 1024; j += 32) rp[j] *= inv;
        __syncwarp();

        const int i = i0 + row;
        __nv_bfloat16* wh_ = (__nv_bfloat16*)(sm + WRH_OFF + (uint32_t)row * 544);
        __nv_bfloat16* wl_ = (__nv_bfloat16*)(sm + WRL_OFF + (uint32_t)row * 544);
        for (int p = 1 + lane; p < 256; p += 32) {
            int j = i + p - 128;
            float val = (j >= 0 && j < 1024) ? rp[j] : 0.f;
            __nv_bfloat16 h = __float2bfloat16(val);
            wh_[p] = h;
            wl_[p] = __float2bfloat16(val - __bfloat162float(h));
        }
        float s0 = 0.f;
        for (int j = lane; j <= i - 128; j += 32) s0 += rp[j];
#pragma unroll
        for (int o = 16; o > 0; o >>= 1) s0 += __shfl_xor_sync(0xffffffffu, s0, o);
        float s2 = 0.f;
        for (int j = i + 128 + lane; j < 1024; j += 32) s2 += rp[j];
#pragma unroll
        for (int o = 16; o > 0; o >>= 1) s2 += __shfl_xor_sync(0xffffffffu, s2, o);
        if (lane == 0) {
            __nv_bfloat16 h0 = __float2bfloat16(s0);
            wh_[0] = h0; wl_[0] = __float2bfloat16(s0 - __bfloat162float(h0));
            __nv_bfloat16 h2 = __float2bfloat16(s2);
            wh_[256] = h2; wl_[256] = __float2bfloat16(s2 - __bfloat162float(h2));
        }
        if (lane < 15) { wh_[257 + lane] = __float2bfloat16(0.f);
                         wl_[257 + lane] = __float2bfloat16(0.f); }
    }
    __syncthreads();

    // ================= in-place fp32 w -> (hi,lo) bf16 per row slot ========
    for (int g = 0; g < 2; g++) {
        float tmp[32];
#pragma unroll
        for (int kk = 0; kk < 32; kk++) {
            int v = g * 16384 + kk * 512 + t;
            int row = v >> 10, col = v & 1023;
            tmp[kk] = *(const float*)(sm + SS_OFF + (uint32_t)row * 4128 + col * 4);
        }
        __syncthreads();
#pragma unroll
        for (int kk = 0; kk < 32; kk++) {
            int v = g * 16384 + kk * 512 + t;
            int row = v >> 10, col = v & 1023;
            __nv_bfloat16 h = __float2bfloat16(tmp[kk]);
            __nv_bfloat16 l = __float2bfloat16(tmp[kk] - __bfloat162float(h));
            *(__nv_bfloat16*)(sm + SS_OFF + (uint32_t)row * 4128 + col * 2) = h;
            *(__nv_bfloat16*)(sm + SS_OFF + (uint32_t)row * 4128 + 2064 + col * 2) = l;
        }
        __syncthreads();
    }

    // ================= PV (w @ v) ==========================================
    float o1[4] = {0.f,0.f,0.f,0.f}, o2[4] = {0.f,0.f,0.f,0.f}, o3[4] = {0.f,0.f,0.f,0.f};

    for (int vt = 0; vt < 16; vt++) {
        const int buf = vt & 1;
        if (vt < 15) issue_tile(g_vh, g_vl, bhrow + (vt + 1) * 64, 64, sb + KV_OFF + (buf ^ 1) * KV_BUF);
        else         issue_tile(g_rvh, g_rvl, 0, 64, sb + KV_OFF + (buf ^ 1) * KV_BUF);
        CP_WAIT(1);
        __syncthreads();

        const uint32_t vb = sb + KV_OFF + buf * KV_BUF;
#pragma unroll
        for (int s = 0; s < 4; s++) {
            uint32_t aaddr = sb + SS_OFF + (uint32_t)(wq * 16 + (lane & 15)) * 4128
                           + (((lane >> 4) << 3) + vt * 64 + s * 16) * 2;
            uint32_t awh[4], awl[4];
            LDMX4(awh[0], awh[1], awh[2], awh[3], aaddr);
            LDMX4(awl[0], awl[1], awl[2], awl[3], aaddr + 2064);
            uint32_t baddr = vb + (uint32_t)(s * 16 + (lane & 7) + ((lane >> 3) & 1) * 8) * 144
                           + wk * 16;
            uint32_t bvh[2], bvl[2];
            LDMX2T(bvh[0], bvh[1], baddr);
            LDMX2T(bvl[0], bvl[1], baddr + 9216);
            MMA16816(o1, awh, bvh);
            MMA16816(o2, awh, bvl);
            MMA16816(o3, awl, bvh);
        }
        __syncthreads();
    }

    // ================= relative-V (wr @ rel_v) =============================
    for (int pt = 0; pt < 5; pt++) {
        const int buf = (16 + pt) & 1;
        if (pt < 4) {
            int nr = (pt == 3) ? 16 : 64;
            issue_tile(g_rvh, g_rvl, (size_t)(pt + 1) * 64, nr, sb + KV_OFF + (buf ^ 1) * KV_BUF);
            CP_WAIT(1);
        } else {
            CP_WAIT(0);
        }
        __syncthreads();

        const uint32_t vb = sb + KV_OFF + buf * KV_BUF;
        const int nk = (pt == 4) ? 1 : 4;
        const int nrh = (pt == 4) ? 16 : 64;
        for (int s = 0; s < nk; s++) {
            uint32_t arow = (uint32_t)(wq * 16 + (lane & 15));
            uint32_t acol = (((lane >> 4) << 3) + pt * 64 + s * 16) * 2;
            uint32_t awh[4], awl[4];
            LDMX4(awh[0], awh[1], awh[2], awh[3], sb + WRH_OFF + arow * 544 + acol);
            LDMX4(awl[0], awl[1], awl[2], awl[3], sb + WRL_OFF + arow * 544 + acol);
            uint32_t baddr = vb + (uint32_t)(s * 16 + (lane & 7) + ((lane >> 3) & 1) * 8) * 144
                           + wk * 16;
            uint32_t bvh[2], bvl[2];
            LDMX2T(bvh[0], bvh[1], baddr);
            LDMX2T(bvl[0], bvl[1], baddr + (uint32_t)nrh * 144);
            MMA16816(o1, awh, bvh);
            MMA16816(o2, awh, bvl);
            MMA16816(o3, awl, bvh);
        }
        __syncthreads();
    }

    // ================= store out (headed fp32 -> g_attn) ===================
    {
        const int bb = bh >> 4, h = bh & 15;
        int row = i0 + wq * 16 + (lane >> 2);
        int d = h * 64 + wk * 8 + (lane & 3) * 2;
        *(float2*)(g_attn + ((size_t)bb * 1024 + row) * 1024 + d) =
            make_float2(o1[0] + o2[0] + o3[0], o1[1] + o2[1] + o3[1]);
        *(float2*)(g_attn + ((size_t)bb * 1024 + row + 8) * 1024 + d) =
            make_float2(o1[2] + o2[2] + o3[2], o1[3] + o2[3] + o3[3]);
    }
}

// ---------------------------------------------------------------------------
extern "C" void kernel_launch(void* const* d_in, const int* in_sizes, int n_in,
                              void* d_out, int out_size)
{
    const float* x     = (const float*)d_in[0];
    const float* Wq    = (const float*)d_in[1];
    const float* bq    = (const float*)d_in[2];
    const float* Wk    = (const float*)d_in[3];
    const float* bk    = (const float*)d_in[4];
    const float* Wv    = (const float*)d_in[5];
    const float* bv    = (const float*)d_in[6];
    const float* Wo    = (const float*)d_in[7];
    const float* bo    = (const float*)d_in[8];
    const float* rel_k = (const float*)d_in[9];
    const float* rel_v = (const float*)d_in[10];

    float *qr, *attn;
    __nv_bfloat16 *xh, *xl, *wh, *wl, *qh, *ql, *kh, *kl, *vh, *vl;
    cudaGetSymbolAddress((void**)&qr,   g_qr);
    cudaGetSymbolAddress((void**)&attn, g_attn);
    cudaGetSymbolAddress((void**)&xh,   g_xh);
    cudaGetSymbolAddress((void**)&xl,   g_xl);
    cudaGetSymbolAddress((void**)&wh,   g_wh);
    cudaGetSymbolAddress((void**)&wl,   g_wl);
    cudaGetSymbolAddress((void**)&qh,   g_qh);
    cudaGetSymbolAddress((void**)&ql,   g_ql);
    cudaGetSymbolAddress((void**)&kh,   g_kh);
    cudaGetSymbolAddress((void**)&kl,   g_kl);
    cudaGetSymbolAddress((void**)&vh,   g_vh);
    cudaGetSymbolAddress((void**)&vl,   g_vl);

    cudaFuncSetAttribute(gemm_mma, cudaFuncAttributeMaxDynamicSharedMemorySize, GEMM_SMEM);
    cudaFuncSetAttribute(gemm_qr,  cudaFuncAttributeMaxDynamicSharedMemorySize, QR_SMEM);
    cudaFuncSetAttribute(attn_mma, cudaFuncAttributeMaxDynamicSharedMemorySize, ATTN_SMEM);

    dim3 blk(256);
    dim3 gtc(Dd / 128, NROW / 128);                  // (8, 32)

    // x -> split bf16; rel_k / rel_v prep
    split_bf16_kernel<<<4096, blk>>>(x, xh, xl, (NROW * Dd) / 4);
    rel_prep<<<96, blk>>>(rel_k, rel_v);

    // projections -> split bf16 (headed)
    split_bf16_kernel<<<1024, blk>>>(Wq, wh, wl, (Dd * Dd) / 4);
    gemm_mma<<<gtc, blk, GEMM_SMEM>>>(xh, xl, wh, wl, bq, nullptr, qh, ql, 1);
    split_bf16_kernel<<<1024, blk>>>(Wk, wh, wl, (Dd * Dd) / 4);
    gemm_mma<<<gtc, blk, GEMM_SMEM>>>(xh, xl, wh, wl, bk, nullptr, kh, kl, 1);
    split_bf16_kernel<<<1024, blk>>>(Wv, wh, wl, (Dd * Dd) / 4);
    gemm_mma<<<gtc, blk, GEMM_SMEM>>>(xh, xl, wh, wl, bv, nullptr, vh, vl, 1);

    // qr[b,h,i,p] = q_i . rel_k[p]   (MMA, padded N=384)
    gemm_qr<<<dim3(NPP / 128, BHS / 128), blk, QR_SMEM>>>(qr);

    // MMA attention core (512 threads)
    attn_mma<<<dim3(Ss / 32, Bv * Hh), 512, ATTN_SMEM>>>();

    // output projection -> d_out
    split_bf16_kernel<<<4096, blk>>>(attn, xh, xl, (NROW * Dd) / 4);
    split_bf16_kernel<<<1024, blk>>>(Wo, wh, wl, (Dd * Dd) / 4);
    gemm_mma<<<gtc, blk, GEMM_SMEM>>>(xh, xl, wh, wl, bo, (float*)d_out, nullptr, nullptr, 0);
}

// round 7
// speedup vs baseline: 2.8321x; 1.0223x over previous
#include <cuda_runtime.h>
#include <cuda_bf16.h>
#include <cstdint>

#define Bv 4
#define Hh 16
#define Ss 1024
#define Dd 1024
#define HDd 64
#define NP 257          // 2*128+1 relative buckets
#define NPP 384         // padded bucket rows (multiple of 128)
#define NROW (Bv*Ss)    // 4096
#define BHS (Bv*Hh*Ss)  // 65536

// ---------------- scratch (device globals: allocation-free) ----------------
__device__ float g_qr[(size_t)BHS * NPP];
__device__ float g_attn[(size_t)NROW * Dd];
__device__ __nv_bfloat16 g_qh[BHS * HDd];
__device__ __nv_bfloat16 g_ql[BHS * HDd];
__device__ __nv_bfloat16 g_kh[BHS * HDd];
__device__ __nv_bfloat16 g_kl[BHS * HDd];
__device__ __nv_bfloat16 g_vh[BHS * HDd];
__device__ __nv_bfloat16 g_vl[BHS * HDd];
__device__ __nv_bfloat16 g_rvh[272 * 64];
__device__ __nv_bfloat16 g_rvl[272 * 64];
__device__ __nv_bfloat16 g_rkh[NPP * 64];
__device__ __nv_bfloat16 g_rkl[NPP * 64];
__device__ __nv_bfloat16 g_xh[(size_t)NROW * Dd];
__device__ __nv_bfloat16 g_xl[(size_t)NROW * Dd];
__device__ __nv_bfloat16 g_wh[(size_t)Dd * Dd];
__device__ __nv_bfloat16 g_wl[(size_t)Dd * Dd];

// ====================== PTX helpers (family-portable only) ======================
__device__ __forceinline__ uint32_t smem_u32(const void* p) {
    uint32_t a;
    asm("{ .reg .u64 t; cvta.to.shared.u64 t, %1; cvt.u32.u64 %0, t; }" : "=r"(a) : "l"(p));
    return a;
}

#define LDMX4(r0, r1, r2, r3, addr) \
    asm volatile("ldmatrix.sync.aligned.m8n8.x4.shared.b16 {%0,%1,%2,%3}, [%4];" \
                 : "=r"(r0), "=r"(r1), "=r"(r2), "=r"(r3) : "r"(addr))

#define LDMX2(r0, r1, addr) \
    asm volatile("ldmatrix.sync.aligned.m8n8.x2.shared.b16 {%0,%1}, [%2];" \
                 : "=r"(r0), "=r"(r1) : "r"(addr))

#define LDMX2T(r0, r1, addr) \
    asm volatile("ldmatrix.sync.aligned.m8n8.x2.trans.shared.b16 {%0,%1}, [%2];" \
                 : "=r"(r0), "=r"(r1) : "r"(addr))

#define MMA16816(c, a, b) \
    asm volatile("mma.sync.aligned.m16n8k16.row.col.f32.bf16.bf16.f32 " \
                 "{%0,%1,%2,%3}, {%4,%5,%6,%7}, {%8,%9}, {%0,%1,%2,%3};" \
                 : "+f"((c)[0]), "+f"((c)[1]), "+f"((c)[2]), "+f"((c)[3]) \
                 : "r"((a)[0]), "r"((a)[1]), "r"((a)[2]), "r"((a)[3]), \
                   "r"((b)[0]), "r"((b)[1]))

#define CP_ASYNC16(s, g) \
    asm volatile("cp.async.cg.shared.global [%0], [%1], 16;" :: "r"(s), "l"(g))
#define CP_COMMIT() asm volatile("cp.async.commit_group;" ::: "memory")
#define CP_WAIT(n)  asm volatile("cp.async.wait_group %0;" :: "n"(n) : "memory")

// ---------------------------------------------------------------------------
// split f32 -> (hi bf16, lo bf16)
// ---------------------------------------------------------------------------
__global__ void split_bf16_kernel(const float* __restrict__ in,
                                  __nv_bfloat16* __restrict__ hi,
                                  __nv_bfloat16* __restrict__ lo, int n4)
{
    int i = blockIdx.x * 256 + threadIdx.x;
    if (i >= n4) return;
    float4 v = ((const float4*)in)[i];
    float vv[4] = {v.x, v.y, v.z, v.w};
    __nv_bfloat16 h[4], l[4];
#pragma unroll
    for (int j = 0; j < 4; j++) {
        h[j] = __float2bfloat16(vv[j]);
        l[j] = __float2bfloat16(vv[j] - __bfloat162float(h[j]));
    }
    ((__nv_bfloat162*)hi)[i * 2 + 0] = __nv_bfloat162(h[0], h[1]);
    ((__nv_bfloat162*)hi)[i * 2 + 1] = __nv_bfloat162(h[2], h[3]);
    ((__nv_bfloat162*)lo)[i * 2 + 0] = __nv_bfloat162(l[0], l[1]);
    ((__nv_bfloat162*)lo)[i * 2 + 1] = __nv_bfloat162(l[2], l[3]);
}

// rel_k -> split bf16 padded to 384 rows; rel_v -> split bf16 padded to 272 rows
__global__ void rel_prep(const float* __restrict__ rel_k, const float* __restrict__ rel_v)
{
    int idx = blockIdx.x * 256 + threadIdx.x;
    if (idx < NPP * 64) {
        int p = idx >> 6, d = idx & 63;
        float v = (p < NP) ? rel_k[p * 64 + d] : 0.f;
        __nv_bfloat16 h = __float2bfloat16(v);
        g_rkh[idx] = h;
        g_rkl[idx] = __float2bfloat16(v - __bfloat162float(h));
    }
    if (idx < 272 * 64) {
        int p = idx >> 6, d = idx & 63;
        float v = (p < NP) ? rel_v[p * 64 + d] : 0.f;
        __nv_bfloat16 h = __float2bfloat16(v);
        g_rvh[idx] = h;
        g_rvl[idx] = __float2bfloat16(v - __bfloat162float(h));
    }
}

// ---------------------------------------------------------------------------
// Warp-MMA split-bf16 NT GEMM (unchanged)
// ---------------------------------------------------------------------------
#define SPB 80
#define MAT_SM (128 * SPB)
#define BUF_SM (4 * MAT_SM)
#define GEMM_SMEM (2 * BUF_SM)

__global__ __launch_bounds__(256, 2)
void gemm_mma(const __nv_bfloat16* __restrict__ Ah_, const __nv_bfloat16* __restrict__ Al_,
              const __nv_bfloat16* __restrict__ Bh_, const __nv_bfloat16* __restrict__ Bl_,
              const float* __restrict__ bias, float* __restrict__ Cf,
              __nv_bfloat16* __restrict__ Ch, __nv_bfloat16* __restrict__ Cl, int headed)
{
    extern __shared__ char sm[];
    const uint32_t sb = smem_u32(sm);
    const int t    = threadIdx.x;
    const int wid  = t >> 5;
    const int lane = t & 31;
    const int m0 = blockIdx.y * 128;
    const int n0 = blockIdx.x * 128;
    const int wm = wid >> 2;
    const int wn = wid & 3;

    const char* gb0 = (const char*)(Ah_ + (size_t)m0 * 1024);
    const char* gb1 = (const char*)(Al_ + (size_t)m0 * 1024);
    const char* gb2 = (const char*)(Bh_ + (size_t)n0 * 1024);
    const char* gb3 = (const char*)(Bl_ + (size_t)n0 * 1024);

    auto issue = [&](int chunk, int buf) {
#pragma unroll
        for (int it = 0; it < 8; it++) {
            int id  = t + it * 256;
            int mat = id >> 9;
            int row = (id >> 2) & 127;
            int c16 = id & 3;
            const char* g = (mat == 0 ? gb0 : mat == 1 ? gb1 : mat == 2 ? gb2 : gb3);
            uint32_t sa = sb + buf * BUF_SM + mat * MAT_SM + row * SPB + c16 * 16;
            CP_ASYNC16(sa, g + (size_t)row * 2048 + chunk * 64 + c16 * 16);
        }
        CP_COMMIT();
    };

    float acc[4][4][4];
#pragma unroll
    for (int i = 0; i < 4; i++)
#pragma unroll
        for (int j = 0; j < 4; j++)
#pragma unroll
            for (int r = 0; r < 4; r++) acc[i][j][r] = 0.f;

    issue(0, 0);
    for (int c = 0; c < 32; c++) {
        const int buf = c & 1;
        if (c + 1 < 32) { issue(c + 1, buf ^ 1); CP_WAIT(1); }
        else            { CP_WAIT(0); }
        __syncthreads();

        const uint32_t Ahb = sb + buf * BUF_SM;
        const uint32_t Alb = Ahb + MAT_SM;
        const uint32_t Bhb = Ahb + 2 * MAT_SM;
        const uint32_t Blb = Ahb + 3 * MAT_SM;

#pragma unroll
        for (int s = 0; s < 2; s++) {
            uint32_t ah[4][4], al[4][4];
            const int arow = wm * 64 + (lane & 15);
            const int acolB = (((lane >> 4) << 3) + s * 16) * 2;
#pragma unroll
            for (int mf = 0; mf < 4; mf++) {
                uint32_t ad = Ahb + (uint32_t)(arow + mf * 16) * SPB + acolB;
                LDMX4(ah[mf][0], ah[mf][1], ah[mf][2], ah[mf][3], ad);
                ad = Alb + (uint32_t)(arow + mf * 16) * SPB + acolB;
                LDMX4(al[mf][0], al[mf][1], al[mf][2], al[mf][3], ad);
            }
            uint32_t bh[4][2], bl[4][2];
            const int brow = wn * 32 + (lane & 7) + ((lane >> 4) << 3);
            const int bcolB = ((((lane >> 3) & 1) << 3) + s * 16) * 2;
#pragma unroll
            for (int g = 0; g < 2; g++) {
                uint32_t r0, r1, r2, r3;
                uint32_t bd = Bhb + (uint32_t)(brow + g * 16) * SPB + bcolB;
                LDMX4(r0, r1, r2, r3, bd);
                bh[g * 2][0] = r0; bh[g * 2][1] = r1;
                bh[g * 2 + 1][0] = r2; bh[g * 2 + 1][1] = r3;
                bd = Blb + (uint32_t)(brow + g * 16) * SPB + bcolB;
                LDMX4(r0, r1, r2, r3, bd);
                bl[g * 2][0] = r0; bl[g * 2][1] = r1;
                bl[g * 2 + 1][0] = r2; bl[g * 2 + 1][1] = r3;
            }
#pragma unroll
            for (int mf = 0; mf < 4; mf++)
#pragma unroll
                for (int nf = 0; nf < 4; nf++) {
                    MMA16816(acc[mf][nf], ah[mf], bh[nf]);
                    MMA16816(acc[mf][nf], ah[mf], bl[nf]);
                    MMA16816(acc[mf][nf], al[mf], bh[nf]);
                }
        }
        __syncthreads();
    }

#pragma unroll
    for (int mf = 0; mf < 4; mf++) {
#pragma unroll
        for (int nf = 0; nf < 4; nf++) {
            int m = m0 + wm * 64 + mf * 16 + (lane >> 2);
            int n = n0 + wn * 32 + nf * 8 + (lane & 3) * 2;
            float p0 = acc[mf][nf][0] + bias[n];
            float p1 = acc[mf][nf][1] + bias[n + 1];
            float p2 = acc[mf][nf][2] + bias[n];
            float p3 = acc[mf][nf][3] + bias[n + 1];
            size_t off0, off1;
            if (headed) {
                int h = n >> 6, d = n & 63;
                int bb = m >> 10, s1 = m & 1023;
                off0 = ((((size_t)bb * Hh + h) << 10) + s1) * HDd + d;
                off1 = ((((size_t)bb * Hh + h) << 10) + s1 + 8) * HDd + d;
            } else {
                off0 = (size_t)m * 1024 + n;
                off1 = (size_t)(m + 8) * 1024 + n;
            }
            if (Cf) {
                *(float2*)(Cf + off0) = make_float2(p0, p1);
                *(float2*)(Cf + off1) = make_float2(p2, p3);
            }
            if (Ch) {
                __nv_bfloat16 h0 = __float2bfloat16(p0), h1 = __float2bfloat16(p1);
                __nv_bfloat16 h2 = __float2bfloat16(p2), h3 = __float2bfloat16(p3);
                *(__nv_bfloat162*)(Ch + off0) = __nv_bfloat162(h0, h1);
                *(__nv_bfloat162*)(Ch + off1) = __nv_bfloat162(h2, h3);
                __nv_bfloat16 l0 = __float2bfloat16(p0 - __bfloat162float(h0));
                __nv_bfloat16 l1 = __float2bfloat16(p1 - __bfloat162float(h1));
                __nv_bfloat16 l2 = __float2bfloat16(p2 - __bfloat162float(h2));
                __nv_bfloat16 l3 = __float2bfloat16(p3 - __bfloat162float(h3));
                *(__nv_bfloat162*)(Cl + off0) = __nv_bfloat162(l0, l1);
                *(__nv_bfloat162*)(Cl + off1) = __nv_bfloat162(l2, l3);
            }
        }
    }
}

// ---------------------------------------------------------------------------
// qr GEMM via MMA (unchanged)
// ---------------------------------------------------------------------------
#define QSPB 144
#define QMAT (128 * QSPB)
#define QR_SMEM (4 * QMAT)

__global__ __launch_bounds__(256)
void gemm_qr(float* __restrict__ C)
{
    extern __shared__ char sm[];
    const uint32_t sb = smem_u32(sm);
    const int t = threadIdx.x, lane = t & 31, wid = t >> 5;
    const int m0 = blockIdx.y * 128;
    const int n0 = blockIdx.x * 128;
    const int wm = wid >> 2, wn = wid & 3;

    const char* gb0 = (const char*)(g_qh + (size_t)m0 * 64);
    const char* gb1 = (const char*)(g_ql + (size_t)m0 * 64);
    const char* gb2 = (const char*)(g_rkh + (size_t)n0 * 64);
    const char* gb3 = (const char*)(g_rkl + (size_t)n0 * 64);

#pragma unroll
    for (int it = 0; it < 16; it++) {
        int id = t + it * 256;
        int mat = id >> 10;
        int row = (id >> 3) & 127;
        int c16 = id & 7;
        const char* g = (mat == 0 ? gb0 : mat == 1 ? gb1 : mat == 2 ? gb2 : gb3);
        CP_ASYNC16(sb + mat * QMAT + row * QSPB + c16 * 16,
                   g + (size_t)row * 128 + c16 * 16);
    }
    CP_COMMIT();
    CP_WAIT(0);
    __syncthreads();

    float acc[4][4][4];
#pragma unroll
    for (int i = 0; i < 4; i++)
#pragma unroll
        for (int j = 0; j < 4; j++)
#pragma unroll
            for (int r = 0; r < 4; r++) acc[i][j][r] = 0.f;

    const uint32_t Ahb = sb, Alb = sb + QMAT, Bhb = sb + 2 * QMAT, Blb = sb + 3 * QMAT;
#pragma unroll
    for (int s = 0; s < 4; s++) {
        uint32_t ah[4][4], al[4][4];
        const int arow = wm * 64 + (lane & 15);
        const int acolB = (((lane >> 4) << 3) + s * 16) * 2;
#pragma unroll
        for (int mf = 0; mf < 4; mf++) {
            uint32_t ad = Ahb + (uint32_t)(arow + mf * 16) * QSPB + acolB;
            LDMX4(ah[mf][0], ah[mf][1], ah[mf][2], ah[mf][3], ad);
            ad = Alb + (uint32_t)(arow + mf * 16) * QSPB + acolB;
            LDMX4(al[mf][0], al[mf][1], al[mf][2], al[mf][3], ad);
        }
        uint32_t bh[4][2], bl[4][2];
        const int brow = wn * 32 + (lane & 7) + ((lane >> 4) << 3);
        const int bcolB = ((((lane >> 3) & 1) << 3) + s * 16) * 2;
#pragma unroll
        for (int g = 0; g < 2; g++) {
            uint32_t r0, r1, r2, r3;
            uint32_t bd = Bhb + (uint32_t)(brow + g * 16) * QSPB + bcolB;
            LDMX4(r0, r1, r2, r3, bd);
            bh[g * 2][0] = r0; bh[g * 2][1] = r1;
            bh[g * 2 + 1][0] = r2; bh[g * 2 + 1][1] = r3;
            bd = Blb + (uint32_t)(brow + g * 16) * QSPB + bcolB;
            LDMX4(r0, r1, r2, r3, bd);
            bl[g * 2][0] = r0; bl[g * 2][1] = r1;
            bl[g * 2 + 1][0] = r2; bl[g * 2 + 1][1] = r3;
        }
#pragma unroll
        for (int mf = 0; mf < 4; mf++)
#pragma unroll
            for (int nf = 0; nf < 4; nf++) {
                MMA16816(acc[mf][nf], ah[mf], bh[nf]);
                MMA16816(acc[mf][nf], ah[mf], bl[nf]);
                MMA16816(acc[mf][nf], al[mf], bh[nf]);
            }
    }

#pragma unroll
    for (int mf = 0; mf < 4; mf++)
#pragma unroll
        for (int nf = 0; nf < 4; nf++) {
            int m = m0 + wm * 64 + mf * 16 + (lane >> 2);
            int n = n0 + wn * 32 + nf * 8 + (lane & 3) * 2;
            *(float2*)(C + (size_t)m * NPP + n) =
                make_float2(acc[mf][nf][0], acc[mf][nf][1]);
            *(float2*)(C + (size_t)(m + 8) * NPP + n) =
                make_float2(acc[mf][nf][2], acc[mf][nf][3]);
        }
}

// ---------------------------------------------------------------------------
// MMA attention core. Block = (bh, 32 query rows). 512 threads, 16 warps.
// Triple-buffered tiles, ONE barrier per tile. Register-resident softmax
// with fused bias; direct bf16 hi/lo emission; wr extraction from regs.
// smem: q 9216 | kv 3x18432 | ss 32x4128 | wrh 32x544 | wrl 32x544
// ---------------------------------------------------------------------------
#define Q_OFF   0u
#define KV_OFF  9216u
#define KV_BUF  18432u
#define SS_OFF  64512u
#define WRH_OFF 196608u
#define WRL_OFF 214016u
#define ATTN_SMEM 231424

__global__ __launch_bounds__(512, 1)
void attn_mma()
{
    extern __shared__ char sm[];
    const uint32_t sb = smem_u32(sm);
    const int t = threadIdx.x, lane = t & 31, wid = t >> 5;
    const int bh = blockIdx.y;
    const int i0 = blockIdx.x * 32;
    const int wq = wid >> 3;        // 0..1
    const int wk = wid & 7;         // 0..7

    auto issue_tile = [&](const __nv_bfloat16* sh, const __nv_bfloat16* sl,
                          size_t row0, int nrows, uint32_t dst) {
#pragma unroll
        for (int it = 0; it < 2; it++) {
            int id = t + it * 512;
            if (id < nrows * 16) {
                int sel = id / (nrows * 8);
                int rid = id % (nrows * 8);
                int row = rid >> 3, c16 = rid & 7;
                const __nv_bfloat16* s = (sel ? sl : sh) + (row0 + row) * 64 + c16 * 8;
                CP_ASYNC16(dst + (uint32_t)sel * (nrows * 144) + row * 144 + c16 * 16, s);
            }
        }
        CP_COMMIT();
    };

    const size_t bhrow = (size_t)bh * 1024;

    issue_tile(g_qh, g_ql, bhrow + i0, 32, sb + Q_OFF);
    issue_tile(g_kh, g_kl, bhrow, 64, sb + KV_OFF);
    issue_tile(g_kh, g_kl, bhrow + 64, 64, sb + KV_OFF + KV_BUF);

    uint32_t qhf[4][4], qlf[4][4];

    // ================= scores: 16 tiles, 1 barrier each ====================
    for (int kt = 0; kt < 16; kt++) {
        if (kt < 15) { CP_WAIT(1); } else { CP_WAIT(0); }
        __syncthreads();
        if (kt + 2 < 16)
            issue_tile(g_kh, g_kl, bhrow + (size_t)(kt + 2) * 64, 64,
                       sb + KV_OFF + (uint32_t)((kt + 2) % 3) * KV_BUF);

        if (kt == 0) {
#pragma unroll
            for (int s = 0; s < 4; s++) {
                uint32_t a = sb + Q_OFF + (uint32_t)(wq * 16 + (lane & 15)) * 144
                           + (((lane >> 4) << 3) + s * 16) * 2;
                LDMX4(qhf[s][0], qhf[s][1], qhf[s][2], qhf[s][3], a);
                LDMX4(qlf[s][0], qlf[s][1], qlf[s][2], qlf[s][3], a + 4608);
            }
        }

        float a1[4] = {0.f,0.f,0.f,0.f}, a2[4] = {0.f,0.f,0.f,0.f}, a3[4] = {0.f,0.f,0.f,0.f};
        const uint32_t kb = sb + KV_OFF + (uint32_t)(kt % 3) * KV_BUF;
#pragma unroll
        for (int s = 0; s < 4; s++) {
            uint32_t addr = kb + (uint32_t)(wk * 8 + (lane & 7)) * 144
                          + ((((lane >> 3) & 1) * 8) + s * 16) * 2;
            uint32_t bh2[2], bl2[2];
            LDMX2(bh2[0], bh2[1], addr);
            LDMX2(bl2[0], bl2[1], addr + 9216);
            MMA16816(a1, qhf[s], bh2);
            MMA16816(a2, qhf[s], bl2);
            MMA16816(a3, qlf[s], bh2);
        }
        {
            int row = wq * 16 + (lane >> 2);
            int col = kt * 64 + wk * 8 + (lane & 3) * 2;
            *(float2*)(sm + SS_OFF + (uint32_t)row * 4128 + col * 4) =
                make_float2(a1[0] + a2[0] + a3[0], a1[1] + a2[1] + a3[1]);
            *(float2*)(sm + SS_OFF + (uint32_t)(row + 8) * 4128 + col * 4) =
                make_float2(a1[2] + a2[2] + a3[2], a1[3] + a2[3] + a3[3]);
        }
    }
    __syncthreads();   // scores visible; k-buffer reads done

    // ================= stage qr window into smem (32 x 264 f32) ============
    float* qw = (float*)(sm + KV_OFF);
    {
        const float* qrb = g_qr + (size_t)bh * Ss * NPP + (size_t)i0 * NPP;
#pragma unroll
        for (int kk = 0; kk < 4; kk++) {
            int id = kk * 512 + t;
            int row = id >> 6, c4 = id & 63;
            float4 v = *(const float4*)(qrb + (size_t)row * NPP + c4 * 4);
            *(float4*)(qw + row * 264 + c4 * 4) = v;
        }
        if (t < 32) qw[t * 264 + 256] = qrb[(size_t)t * NPP + 256];
    }
    __syncthreads();

    // prefetch v tile 0 -> buf 2 (disjoint from qw); overlaps softmax
    issue_tile(g_vh, g_vl, bhrow, 64, sb + KV_OFF + 2u * KV_BUF);

    // ================= softmax (fused bias, reg-resident), 2 rows/warp =====
    for (int rr = 0; rr < 2; rr++) {
        const int row = wid * 2 + rr;
        const int i = i0 + row;
        const float* rp = (const float*)(sm + SS_OFF + (uint32_t)row * 4128);
        const float* qwr = qw + row * 264;
        float tmp[32];
#pragma unroll
        for (int kk = 0; kk < 32; kk++) {
            int j = lane + kk * 32;
            int rel = j - i;
            rel = rel < -128 ? -128 : (rel > 128 ? 128 : rel);
            tmp[kk] = (rp[j] + qwr[rel + 128]) * 0.125f;
        }
        float mx = -1e30f;
#pragma unroll
        for (int kk = 0; kk < 32; kk++) mx = fmaxf(mx, tmp[kk]);
#pragma unroll
        for (int o = 16; o > 0; o >>= 1) mx = fmaxf(mx, __shfl_xor_sync(0xffffffffu, mx, o));
        float sum = 0.f;
#pragma unroll
        for (int kk = 0; kk < 32; kk++) { tmp[kk] = __expf(tmp[kk] - mx); sum += tmp[kk]; }
#pragma unroll
        for (int o = 16; o > 0; o >>= 1) sum += __shfl_xor_sync(0xffffffffu, sum, o);
        const float inv = 1.f / sum;

        uint32_t* whz = (uint32_t*)(sm + WRH_OFF + (uint32_t)row * 544);
        uint32_t* wlz = (uint32_t*)(sm + WRL_OFF + (uint32_t)row * 544);
        for (int idx = lane; idx < 136; idx += 32) { whz[idx] = 0u; wlz[idx] = 0u; }
        __syncwarp();

        __nv_bfloat16* wh_ = (__nv_bfloat16*)whz;
        __nv_bfloat16* wl_ = (__nv_bfloat16*)wlz;
        float s0 = 0.f, s2 = 0.f;
#pragma unroll
        for (int kk = 0; kk < 32; kk++) {
            int j = lane + kk * 32;
            float w = tmp[kk] * inv;
            __nv_bfloat16 h = __float2bfloat16(w);
            __nv_bfloat16 l = __float2bfloat16(w - __bfloat162float(h));
            *(__nv_bfloat16*)(sm + SS_OFF + (uint32_t)row * 4128 + j * 2) = h;
            *(__nv_bfloat16*)(sm + SS_OFF + (uint32_t)row * 4128 + 2064 + j * 2) = l;
            int dlt = j - i;
            if (dlt <= -128)      s0 += w;
            else if (dlt >= 128)  s2 += w;
            else { wh_[dlt + 128] = h; wl_[dlt + 128] = l; }
        }
#pragma unroll
        for (int o = 16; o > 0; o >>= 1) s0 += __shfl_xor_sync(0xffffffffu, s0, o);
#pragma unroll
        for (int o = 16; o > 0; o >>= 1) s2 += __shfl_xor_sync(0xffffffffu, s2, o);
        __syncwarp();
        if (lane == 0) {
            __nv_bfloat16 h0 = __float2bfloat16(s0);
            wh_[0] = h0; wl_[0] = __float2bfloat16(s0 - __bfloat162float(h0));
            __nv_bfloat16 h2 = __float2bfloat16(s2);
            wh_[256] = h2; wl_[256] = __float2bfloat16(s2 - __bfloat162float(h2));
        }
    }

    // ================= PV: 16 v tiles + 5 rel_v tiles, 1 barrier each ======
    auto issue_pv = [&](int tt) {
        uint32_t dst = sb + KV_OFF + (uint32_t)((tt + 2) % 3) * KV_BUF;
        if (tt < 16) issue_tile(g_vh, g_vl, bhrow + (size_t)tt * 64, 64, dst);
        else         issue_tile(g_rvh, g_rvl, (size_t)(tt - 16) * 64,
                                (tt == 20) ? 16 : 64, dst);
    };

    float o1[4] = {0.f,0.f,0.f,0.f}, o2[4] = {0.f,0.f,0.f,0.f}, o3[4] = {0.f,0.f,0.f,0.f};

    for (int vt = 0; vt < 21; vt++) {
        if (vt == 0 || vt == 20) { CP_WAIT(0); } else { CP_WAIT(1); }
        __syncthreads();
        if (vt == 0)            { issue_pv(1); issue_pv(2); }
        else if (vt + 2 <= 20)  issue_pv(vt + 2);

        const int nrows = (vt == 20) ? 16 : 64;
        const int nk = (vt == 20) ? 1 : 4;
        const uint32_t vb = sb + KV_OFF + (uint32_t)((vt + 2) % 3) * KV_BUF;
        for (int s = 0; s < nk; s++) {
            uint32_t awh[4], awl[4];
            if (vt < 16) {
                uint32_t aaddr = sb + SS_OFF + (uint32_t)(wq * 16 + (lane & 15)) * 4128
                               + (((lane >> 4) << 3) + vt * 64 + s * 16) * 2;
                LDMX4(awh[0], awh[1], awh[2], awh[3], aaddr);
                LDMX4(awl[0], awl[1], awl[2], awl[3], aaddr + 2064);
            } else {
                uint32_t arow = (uint32_t)(wq * 16 + (lane & 15));
                uint32_t acol = (((lane >> 4) << 3) + (vt - 16) * 64 + s * 16) * 2;
                LDMX4(awh[0], awh[1], awh[2], awh[3], sb + WRH_OFF + arow * 544 + acol);
                LDMX4(awl[0], awl[1], awl[2], awl[3], sb + WRL_OFF + arow * 544 + acol);
            }
            uint32_t baddr = vb + (uint32_t)(s * 16 + (lane & 7) + ((lane >> 3) & 1) * 8) * 144
                           + wk * 16;
            uint32_t bvh[2], bvl[2];
            LDMX2T(bvh[0], bvh[1], baddr);
            LDMX2T(bvl[0], bvl[1], baddr + (uint32_t)nrows * 144);
            MMA16816(o1, awh, bvh);
            MMA16816(o2, awh, bvl);
            MMA16816(o3, awl, bvh);
        }
    }

    // ================= store out (headed fp32 -> g_attn) ===================
    {
        const int bb = bh >> 4, h = bh & 15;
        int row = i0 + wq * 16 + (lane >> 2);
        int d = h * 64 + wk * 8 + (lane & 3) * 2;
        *(float2*)(g_attn + ((size_t)bb * 1024 + row) * 1024 + d) =
            make_float2(o1[0] + o2[0] + o3[0], o1[1] + o2[1] + o3[1]);
        *(float2*)(g_attn + ((size_t)bb * 1024 + row + 8) * 1024 + d) =
            make_float2(o1[2] + o2[2] + o3[2], o1[3] + o2[3] + o3[3]);
    }
}

// ---------------------------------------------------------------------------
extern "C" void kernel_launch(void* const* d_in, const int* in_sizes, int n_in,
                              void* d_out, int out_size)
{
    const float* x     = (const float*)d_in[0];
    const float* Wq    = (const float*)d_in[1];
    const float* bq    = (const float*)d_in[2];
    const float* Wk    = (const float*)d_in[3];
    const float* bk    = (const float*)d_in[4];
    const float* Wv    = (const float*)d_in[5];
    const float* bv    = (const float*)d_in[6];
    const float* Wo    = (const float*)d_in[7];
    const float* bo    = (const float*)d_in[8];
    const float* rel_k = (const float*)d_in[9];
    const float* rel_v = (const float*)d_in[10];

    float *qr, *attn;
    __nv_bfloat16 *xh, *xl, *wh, *wl, *qh, *ql, *kh, *kl, *vh, *vl;
    cudaGetSymbolAddress((void**)&qr,   g_qr);
    cudaGetSymbolAddress((void**)&attn, g_attn);
    cudaGetSymbolAddress((void**)&xh,   g_xh);
    cudaGetSymbolAddress((void**)&xl,   g_xl);
    cudaGetSymbolAddress((void**)&wh,   g_wh);
    cudaGetSymbolAddress((void**)&wl,   g_wl);
    cudaGetSymbolAddress((void**)&qh,   g_qh);
    cudaGetSymbolAddress((void**)&ql,   g_ql);
    cudaGetSymbolAddress((void**)&kh,   g_kh);
    cudaGetSymbolAddress((void**)&kl,   g_kl);
    cudaGetSymbolAddress((void**)&vh,   g_vh);
    cudaGetSymbolAddress((void**)&vl,   g_vl);

    cudaFuncSetAttribute(gemm_mma, cudaFuncAttributeMaxDynamicSharedMemorySize, GEMM_SMEM);
    cudaFuncSetAttribute(gemm_qr,  cudaFuncAttributeMaxDynamicSharedMemorySize, QR_SMEM);
    cudaFuncSetAttribute(attn_mma, cudaFuncAttributeMaxDynamicSharedMemorySize, ATTN_SMEM);

    dim3 blk(256);
    dim3 gtc(Dd / 128, NROW / 128);                  // (8, 32)

    // x -> split bf16; rel_k / rel_v prep
    split_bf16_kernel<<<4096, blk>>>(x, xh, xl, (NROW * Dd) / 4);
    rel_prep<<<96, blk>>>(rel_k, rel_v);

    // projections -> split bf16 (headed)
    split_bf16_kernel<<<1024, blk>>>(Wq, wh, wl, (Dd * Dd) / 4);
    gemm_mma<<<gtc, blk, GEMM_SMEM>>>(xh, xl, wh, wl, bq, nullptr, qh, ql, 1);
    split_bf16_kernel<<<1024, blk>>>(Wk, wh, wl, (Dd * Dd) / 4);
    gemm_mma<<<gtc, blk, GEMM_SMEM>>>(xh, xl, wh, wl, bk, nullptr, kh, kl, 1);
    split_bf16_kernel<<<1024, blk>>>(Wv, wh, wl, (Dd * Dd) / 4);
    gemm_mma<<<gtc, blk, GEMM_SMEM>>>(xh, xl, wh, wl, bv, nullptr, vh, vl, 1);

    // qr[b,h,i,p] = q_i . rel_k[p]   (MMA, padded N=384)
    gemm_qr<<<dim3(NPP / 128, BHS / 128), blk, QR_SMEM>>>(qr);

    // MMA attention core (512 threads)
    attn_mma<<<dim3(Ss / 32, Bv * Hh), 512, ATTN_SMEM>>>();

    // output projection -> d_out
    split_bf16_kernel<<<4096, blk>>>(attn, xh, xl, (NROW * Dd) / 4);
    split_bf16_kernel<<<1024, blk>>>(Wo, wh, wl, (Dd * Dd) / 4);
    gemm_mma<<<gtc, blk, GEMM_SMEM>>>(xh, xl, wh, wl, bo, (float*)d_out, nullptr, nullptr, 0);
}

// round 8
// speedup vs baseline: 3.1786x; 1.1223x over previous
#include <cuda_runtime.h>
#include <cuda_bf16.h>
#include <cstdint>

#define Bv 4
#define Hh 16
#define Ss 1024
#define Dd 1024
#define HDd 64
#define NP 257          // 2*128+1 relative buckets
#define NPP 384         // padded bucket rows (multiple of 128)
#define NROW (Bv*Ss)    // 4096
#define BHS (Bv*Hh*Ss)  // 65536

// ---------------- scratch (device globals: allocation-free) ----------------
__device__ float g_qr[(size_t)BHS * NPP];
__device__ float g_attn[(size_t)NROW * Dd];
__device__ __nv_bfloat16 g_qh[BHS * HDd];
__device__ __nv_bfloat16 g_ql[BHS * HDd];
__device__ __nv_bfloat16 g_kh[BHS * HDd];
__device__ __nv_bfloat16 g_kl[BHS * HDd];
__device__ __nv_bfloat16 g_vh[BHS * HDd];
__device__ __nv_bfloat16 g_vl[BHS * HDd];
__device__ __nv_bfloat16 g_rvh[272 * 64];
__device__ __nv_bfloat16 g_rvl[272 * 64];
__device__ __nv_bfloat16 g_rkh[NPP * 64];
__device__ __nv_bfloat16 g_rkl[NPP * 64];
__device__ __nv_bfloat16 g_xh[(size_t)NROW * Dd];
__device__ __nv_bfloat16 g_xl[(size_t)NROW * Dd];
__device__ __nv_bfloat16 g_wh[(size_t)Dd * Dd];
__device__ __nv_bfloat16 g_wl[(size_t)Dd * Dd];

// ====================== PTX helpers (family-portable only) ======================
__device__ __forceinline__ uint32_t smem_u32(const void* p) {
    uint32_t a;
    asm("{ .reg .u64 t; cvta.to.shared.u64 t, %1; cvt.u32.u64 %0, t; }" : "=r"(a) : "l"(p));
    return a;
}

#define LDMX4(r0, r1, r2, r3, addr) \
    asm volatile("ldmatrix.sync.aligned.m8n8.x4.shared.b16 {%0,%1,%2,%3}, [%4];" \
                 : "=r"(r0), "=r"(r1), "=r"(r2), "=r"(r3) : "r"(addr))

#define LDMX2(r0, r1, addr) \
    asm volatile("ldmatrix.sync.aligned.m8n8.x2.shared.b16 {%0,%1}, [%2];" \
                 : "=r"(r0), "=r"(r1) : "r"(addr))

#define LDMX2T(r0, r1, addr) \
    asm volatile("ldmatrix.sync.aligned.m8n8.x2.trans.shared.b16 {%0,%1}, [%2];" \
                 : "=r"(r0), "=r"(r1) : "r"(addr))

#define MMA16816(c, a, b) \
    asm volatile("mma.sync.aligned.m16n8k16.row.col.f32.bf16.bf16.f32 " \
                 "{%0,%1,%2,%3}, {%4,%5,%6,%7}, {%8,%9}, {%0,%1,%2,%3};" \
                 : "+f"((c)[0]), "+f"((c)[1]), "+f"((c)[2]), "+f"((c)[3]) \
                 : "r"((a)[0]), "r"((a)[1]), "r"((a)[2]), "r"((a)[3]), \
                   "r"((b)[0]), "r"((b)[1]))

#define CP_ASYNC16(s, g) \
    asm volatile("cp.async.cg.shared.global [%0], [%1], 16;" :: "r"(s), "l"(g))
#define CP_COMMIT() asm volatile("cp.async.commit_group;" ::: "memory")
#define CP_WAIT(n)  asm volatile("cp.async.wait_group %0;" :: "n"(n) : "memory")

// ---------------------------------------------------------------------------
// split f32 -> (hi bf16, lo bf16); 2 float4 per thread (MLP=2)
// ---------------------------------------------------------------------------
__global__ void split_bf16_kernel(const float* __restrict__ in,
                                  __nv_bfloat16* __restrict__ hi,
                                  __nv_bfloat16* __restrict__ lo, int n4)
{
    int i = blockIdx.x * 512 + threadIdx.x;
#pragma unroll
    for (int rep = 0; rep < 2; rep++, i += 256) {
        if (i >= n4) return;
        float4 v = ((const float4*)in)[i];
        float vv[4] = {v.x, v.y, v.z, v.w};
        __nv_bfloat16 h[4], l[4];
#pragma unroll
        for (int j = 0; j < 4; j++) {
            h[j] = __float2bfloat16(vv[j]);
            l[j] = __float2bfloat16(vv[j] - __bfloat162float(h[j]));
        }
        ((__nv_bfloat162*)hi)[i * 2 + 0] = __nv_bfloat162(h[0], h[1]);
        ((__nv_bfloat162*)hi)[i * 2 + 1] = __nv_bfloat162(h[2], h[3]);
        ((__nv_bfloat162*)lo)[i * 2 + 0] = __nv_bfloat162(l[0], l[1]);
        ((__nv_bfloat162*)lo)[i * 2 + 1] = __nv_bfloat162(l[2], l[3]);
    }
}

// rel_k -> split bf16 padded to 384 rows; rel_v -> split bf16 padded to 272 rows
__global__ void rel_prep(const float* __restrict__ rel_k, const float* __restrict__ rel_v)
{
    int idx = blockIdx.x * 256 + threadIdx.x;
    if (idx < NPP * 64) {
        int p = idx >> 6, d = idx & 63;
        float v = (p < NP) ? rel_k[p * 64 + d] : 0.f;
        __nv_bfloat16 h = __float2bfloat16(v);
        g_rkh[idx] = h;
        g_rkl[idx] = __float2bfloat16(v - __bfloat162float(h));
    }
    if (idx < 272 * 64) {
        int p = idx >> 6, d = idx & 63;
        float v = (p < NP) ? rel_v[p * 64 + d] : 0.f;
        __nv_bfloat16 h = __float2bfloat16(v);
        g_rvh[idx] = h;
        g_rvl[idx] = __float2bfloat16(v - __bfloat162float(h));
    }
}

// ---------------------------------------------------------------------------
// Warp-MMA split-bf16 NT GEMM — now ONE barrier per chunk
// (wait -> barrier -> issue next into buffer last read before barrier -> compute)
// ---------------------------------------------------------------------------
#define SPB 80
#define MAT_SM (128 * SPB)
#define BUF_SM (4 * MAT_SM)
#define GEMM_SMEM (2 * BUF_SM)

__global__ __launch_bounds__(256, 2)
void gemm_mma(const __nv_bfloat16* __restrict__ Ah_, const __nv_bfloat16* __restrict__ Al_,
              const __nv_bfloat16* __restrict__ Bh_, const __nv_bfloat16* __restrict__ Bl_,
              const float* __restrict__ bias, float* __restrict__ Cf,
              __nv_bfloat16* __restrict__ Ch, __nv_bfloat16* __restrict__ Cl, int headed)
{
    extern __shared__ char sm[];
    const uint32_t sb = smem_u32(sm);
    const int t    = threadIdx.x;
    const int wid  = t >> 5;
    const int lane = t & 31;
    const int m0 = blockIdx.y * 128;
    const int n0 = blockIdx.x * 128;
    const int wm = wid >> 2;
    const int wn = wid & 3;

    const char* gb0 = (const char*)(Ah_ + (size_t)m0 * 1024);
    const char* gb1 = (const char*)(Al_ + (size_t)m0 * 1024);
    const char* gb2 = (const char*)(Bh_ + (size_t)n0 * 1024);
    const char* gb3 = (const char*)(Bl_ + (size_t)n0 * 1024);

    auto issue = [&](int chunk, int buf) {
#pragma unroll
        for (int it = 0; it < 8; it++) {
            int id  = t + it * 256;
            int mat = id >> 9;
            int row = (id >> 2) & 127;
            int c16 = id & 3;
            const char* g = (mat == 0 ? gb0 : mat == 1 ? gb1 : mat == 2 ? gb2 : gb3);
            uint32_t sa = sb + buf * BUF_SM + mat * MAT_SM + row * SPB + c16 * 16;
            CP_ASYNC16(sa, g + (size_t)row * 2048 + chunk * 64 + c16 * 16);
        }
        CP_COMMIT();
    };

    float acc[4][4][4];
#pragma unroll
    for (int i = 0; i < 4; i++)
#pragma unroll
        for (int j = 0; j < 4; j++)
#pragma unroll
            for (int r = 0; r < 4; r++) acc[i][j][r] = 0.f;

    issue(0, 0);
    for (int c = 0; c < 32; c++) {
        const int buf = c & 1;
        CP_WAIT(0);
        __syncthreads();           // tile c visible to all; reads of c-1 complete
        if (c + 1 < 32) issue(c + 1, buf ^ 1);

        const uint32_t Ahb = sb + buf * BUF_SM;
        const uint32_t Alb = Ahb + MAT_SM;
        const uint32_t Bhb = Ahb + 2 * MAT_SM;
        const uint32_t Blb = Ahb + 3 * MAT_SM;

#pragma unroll
        for (int s = 0; s < 2; s++) {
            uint32_t ah[4][4], al[4][4];
            const int arow = wm * 64 + (lane & 15);
            const int acolB = (((lane >> 4) << 3) + s * 16) * 2;
#pragma unroll
            for (int mf = 0; mf < 4; mf++) {
                uint32_t ad = Ahb + (uint32_t)(arow + mf * 16) * SPB + acolB;
                LDMX4(ah[mf][0], ah[mf][1], ah[mf][2], ah[mf][3], ad);
                ad = Alb + (uint32_t)(arow + mf * 16) * SPB + acolB;
                LDMX4(al[mf][0], al[mf][1], al[mf][2], al[mf][3], ad);
            }
            uint32_t bh[4][2], bl[4][2];
            const int brow = wn * 32 + (lane & 7) + ((lane >> 4) << 3);
            const int bcolB = ((((lane >> 3) & 1) << 3) + s * 16) * 2;
#pragma unroll
            for (int g = 0; g < 2; g++) {
                uint32_t r0, r1, r2, r3;
                uint32_t bd = Bhb + (uint32_t)(brow + g * 16) * SPB + bcolB;
                LDMX4(r0, r1, r2, r3, bd);
                bh[g * 2][0] = r0; bh[g * 2][1] = r1;
                bh[g * 2 + 1][0] = r2; bh[g * 2 + 1][1] = r3;
                bd = Blb + (uint32_t)(brow + g * 16) * SPB + bcolB;
                LDMX4(r0, r1, r2, r3, bd);
                bl[g * 2][0] = r0; bl[g * 2][1] = r1;
                bl[g * 2 + 1][0] = r2; bl[g * 2 + 1][1] = r3;
            }
#pragma unroll
            for (int mf = 0; mf < 4; mf++)
#pragma unroll
                for (int nf = 0; nf < 4; nf++) {
                    MMA16816(acc[mf][nf], ah[mf], bh[nf]);
                    MMA16816(acc[mf][nf], ah[mf], bl[nf]);
                    MMA16816(acc[mf][nf], al[mf], bh[nf]);
                }
        }
    }

#pragma unroll
    for (int mf = 0; mf < 4; mf++) {
#pragma unroll
        for (int nf = 0; nf < 4; nf++) {
            int m = m0 + wm * 64 + mf * 16 + (lane >> 2);
            int n = n0 + wn * 32 + nf * 8 + (lane & 3) * 2;
            float p0 = acc[mf][nf][0] + bias[n];
            float p1 = acc[mf][nf][1] + bias[n + 1];
            float p2 = acc[mf][nf][2] + bias[n];
            float p3 = acc[mf][nf][3] + bias[n + 1];
            size_t off0, off1;
            if (headed) {
                int h = n >> 6, d = n & 63;
                int bb = m >> 10, s1 = m & 1023;
                off0 = ((((size_t)bb * Hh + h) << 10) + s1) * HDd + d;
                off1 = ((((size_t)bb * Hh + h) << 10) + s1 + 8) * HDd + d;
            } else {
                off0 = (size_t)m * 1024 + n;
                off1 = (size_t)(m + 8) * 1024 + n;
            }
            if (Cf) {
                *(float2*)(Cf + off0) = make_float2(p0, p1);
                *(float2*)(Cf + off1) = make_float2(p2, p3);
            }
            if (Ch) {
                __nv_bfloat16 h0 = __float2bfloat16(p0), h1 = __float2bfloat16(p1);
                __nv_bfloat16 h2 = __float2bfloat16(p2), h3 = __float2bfloat16(p3);
                *(__nv_bfloat162*)(Ch + off0) = __nv_bfloat162(h0, h1);
                *(__nv_bfloat162*)(Ch + off1) = __nv_bfloat162(h2, h3);
                __nv_bfloat16 l0 = __float2bfloat16(p0 - __bfloat162float(h0));
                __nv_bfloat16 l1 = __float2bfloat16(p1 - __bfloat162float(h1));
                __nv_bfloat16 l2 = __float2bfloat16(p2 - __bfloat162float(h2));
                __nv_bfloat16 l3 = __float2bfloat16(p3 - __bfloat162float(h3));
                *(__nv_bfloat162*)(Cl + off0) = __nv_bfloat162(l0, l1);
                *(__nv_bfloat162*)(Cl + off1) = __nv_bfloat162(l2, l3);
            }
        }
    }
}

// ---------------------------------------------------------------------------
// qr GEMM via MMA (unchanged)
// ---------------------------------------------------------------------------
#define QSPB 144
#define QMAT (128 * QSPB)
#define QR_SMEM (4 * QMAT)

__global__ __launch_bounds__(256)
void gemm_qr(float* __restrict__ C)
{
    extern __shared__ char sm[];
    const uint32_t sb = smem_u32(sm);
    const int t = threadIdx.x, lane = t & 31, wid = t >> 5;
    const int m0 = blockIdx.y * 128;
    const int n0 = blockIdx.x * 128;
    const int wm = wid >> 2, wn = wid & 3;

    const char* gb0 = (const char*)(g_qh + (size_t)m0 * 64);
    const char* gb1 = (const char*)(g_ql + (size_t)m0 * 64);
    const char* gb2 = (const char*)(g_rkh + (size_t)n0 * 64);
    const char* gb3 = (const char*)(g_rkl + (size_t)n0 * 64);

#pragma unroll
    for (int it = 0; it < 16; it++) {
        int id = t + it * 256;
        int mat = id >> 10;
        int row = (id >> 3) & 127;
        int c16 = id & 7;
        const char* g = (mat == 0 ? gb0 : mat == 1 ? gb1 : mat == 2 ? gb2 : gb3);
        CP_ASYNC16(sb + mat * QMAT + row * QSPB + c16 * 16,
                   g + (size_t)row * 128 + c16 * 16);
    }
    CP_COMMIT();
    CP_WAIT(0);
    __syncthreads();

    float acc[4][4][4];
#pragma unroll
    for (int i = 0; i < 4; i++)
#pragma unroll
        for (int j = 0; j < 4; j++)
#pragma unroll
            for (int r = 0; r < 4; r++) acc[i][j][r] = 0.f;

    const uint32_t Ahb = sb, Alb = sb + QMAT, Bhb = sb + 2 * QMAT, Blb = sb + 3 * QMAT;
#pragma unroll
    for (int s = 0; s < 4; s++) {
        uint32_t ah[4][4], al[4][4];
        const int arow = wm * 64 + (lane & 15);
        const int acolB = (((lane >> 4) << 3) + s * 16) * 2;
#pragma unroll
        for (int mf = 0; mf < 4; mf++) {
            uint32_t ad = Ahb + (uint32_t)(arow + mf * 16) * QSPB + acolB;
            LDMX4(ah[mf][0], ah[mf][1], ah[mf][2], ah[mf][3], ad);
            ad = Alb + (uint32_t)(arow + mf * 16) * QSPB + acolB;
            LDMX4(al[mf][0], al[mf][1], al[mf][2], al[mf][3], ad);
        }
        uint32_t bh[4][2], bl[4][2];
        const int brow = wn * 32 + (lane & 7) + ((lane >> 4) << 3);
        const int bcolB = ((((lane >> 3) & 1) << 3) + s * 16) * 2;
#pragma unroll
        for (int g = 0; g < 2; g++) {
            uint32_t r0, r1, r2, r3;
            uint32_t bd = Bhb + (uint32_t)(brow + g * 16) * QSPB + bcolB;
            LDMX4(r0, r1, r2, r3, bd);
            bh[g * 2][0] = r0; bh[g * 2][1] = r1;
            bh[g * 2 + 1][0] = r2; bh[g * 2 + 1][1] = r3;
            bd = Blb + (uint32_t)(brow + g * 16) * QSPB + bcolB;
            LDMX4(r0, r1, r2, r3, bd);
            bl[g * 2][0] = r0; bl[g * 2][1] = r1;
            bl[g * 2 + 1][0] = r2; bl[g * 2 + 1][1] = r3;
        }
#pragma unroll
        for (int mf = 0; mf < 4; mf++)
#pragma unroll
            for (int nf = 0; nf < 4; nf++) {
                MMA16816(acc[mf][nf], ah[mf], bh[nf]);
                MMA16816(acc[mf][nf], ah[mf], bl[nf]);
                MMA16816(acc[mf][nf], al[mf], bh[nf]);
            }
    }

#pragma unroll
    for (int mf = 0; mf < 4; mf++)
#pragma unroll
        for (int nf = 0; nf < 4; nf++) {
            int m = m0 + wm * 64 + mf * 16 + (lane >> 2);
            int n = n0 + wn * 32 + nf * 8 + (lane & 3) * 2;
            *(float2*)(C + (size_t)m * NPP + n) =
                make_float2(acc[mf][nf][0], acc[mf][nf][1]);
            *(float2*)(C + (size_t)(m + 8) * NPP + n) =
                make_float2(acc[mf][nf][2], acc[mf][nf][3]);
        }
}

// ---------------------------------------------------------------------------
// MMA attention core. Block = (bh, 32 query rows). 512 threads, 16 warps.
// Conflict-free pitches: ss 4112 B (16*257), wr 560 B (16*35).
// ---------------------------------------------------------------------------
#define SSP  4112u
#define WRP  560u
#define Q_OFF   0u
#define KV_OFF  9216u
#define KV_BUF  18432u
#define SS_OFF  64512u
#define WRH_OFF 196096u
#define WRL_OFF 214016u
#define ATTN_SMEM 231936

__global__ __launch_bounds__(512, 1)
void attn_mma()
{
    extern __shared__ char sm[];
    const uint32_t sb = smem_u32(sm);
    const int t = threadIdx.x, lane = t & 31, wid = t >> 5;
    const int bh = blockIdx.y;
    const int i0 = blockIdx.x * 32;
    const int wq = wid >> 3;        // 0..1
    const int wk = wid & 7;         // 0..7

    auto issue_tile = [&](const __nv_bfloat16* sh, const __nv_bfloat16* sl,
                          size_t row0, int nrows, uint32_t dst) {
#pragma unroll
        for (int it = 0; it < 2; it++) {
            int id = t + it * 512;
            if (id < nrows * 16) {
                int sel = id / (nrows * 8);
                int rid = id % (nrows * 8);
                int row = rid >> 3, c16 = rid & 7;
                const __nv_bfloat16* s = (sel ? sl : sh) + (row0 + row) * 64 + c16 * 8;
                CP_ASYNC16(dst + (uint32_t)sel * (nrows * 144) + row * 144 + c16 * 16, s);
            }
        }
        CP_COMMIT();
    };

    const size_t bhrow = (size_t)bh * 1024;

    issue_tile(g_qh, g_ql, bhrow + i0, 32, sb + Q_OFF);
    issue_tile(g_kh, g_kl, bhrow, 64, sb + KV_OFF);
    issue_tile(g_kh, g_kl, bhrow + 64, 64, sb + KV_OFF + KV_BUF);

    uint32_t qhf[4][4], qlf[4][4];

    // ================= scores: 16 tiles, 1 barrier each ====================
    for (int kt = 0; kt < 16; kt++) {
        if (kt < 15) { CP_WAIT(1); } else { CP_WAIT(0); }
        __syncthreads();
        if (kt + 2 < 16)
            issue_tile(g_kh, g_kl, bhrow + (size_t)(kt + 2) * 64, 64,
                       sb + KV_OFF + (uint32_t)((kt + 2) % 3) * KV_BUF);

        if (kt == 0) {
#pragma unroll
            for (int s = 0; s < 4; s++) {
                uint32_t a = sb + Q_OFF + (uint32_t)(wq * 16 + (lane & 15)) * 144
                           + (((lane >> 4) << 3) + s * 16) * 2;
                LDMX4(qhf[s][0], qhf[s][1], qhf[s][2], qhf[s][3], a);
                LDMX4(qlf[s][0], qlf[s][1], qlf[s][2], qlf[s][3], a + 4608);
            }
        }

        float a1[4] = {0.f,0.f,0.f,0.f}, a2[4] = {0.f,0.f,0.f,0.f}, a3[4] = {0.f,0.f,0.f,0.f};
        const uint32_t kb = sb + KV_OFF + (uint32_t)(kt % 3) * KV_BUF;
#pragma unroll
        for (int s = 0; s < 4; s++) {
            uint32_t addr = kb + (uint32_t)(wk * 8 + (lane & 7)) * 144
                          + ((((lane >> 3) & 1) * 8) + s * 16) * 2;
            uint32_t bh2[2], bl2[2];
            LDMX2(bh2[0], bh2[1], addr);
            LDMX2(bl2[0], bl2[1], addr + 9216);
            MMA16816(a1, qhf[s], bh2);
            MMA16816(a2, qhf[s], bl2);
            MMA16816(a3, qlf[s], bh2);
        }
        {
            int row = wq * 16 + (lane >> 2);
            int col = kt * 64 + wk * 8 + (lane & 3) * 2;
            *(float2*)(sm + SS_OFF + (uint32_t)row * SSP + col * 4) =
                make_float2(a1[0] + a2[0] + a3[0], a1[1] + a2[1] + a3[1]);
            *(float2*)(sm + SS_OFF + (uint32_t)(row + 8) * SSP + col * 4) =
                make_float2(a1[2] + a2[2] + a3[2], a1[3] + a2[3] + a3[3]);
        }
    }
    __syncthreads();   // scores visible; k-buffer reads done

    // ================= stage qr window into smem (32 x 264 f32) ============
    float* qw = (float*)(sm + KV_OFF);
    {
        const float* qrb = g_qr + (size_t)bh * Ss * NPP + (size_t)i0 * NPP;
#pragma unroll
        for (int kk = 0; kk < 4; kk++) {
            int id = kk * 512 + t;
            int row = id >> 6, c4 = id & 63;
            float4 v = *(const float4*)(qrb + (size_t)row * NPP + c4 * 4);
            *(float4*)(qw + row * 264 + c4 * 4) = v;
        }
        if (t < 32) qw[t * 264 + 256] = qrb[(size_t)t * NPP + 256];
    }
    __syncthreads();

    // prefetch v tile 0 -> buf 2 (disjoint from qw); overlaps softmax
    issue_tile(g_vh, g_vl, bhrow, 64, sb + KV_OFF + 2u * KV_BUF);

    // ================= softmax (fused bias, reg-resident), 2 rows/warp =====
    for (int rr = 0; rr < 2; rr++) {
        const int row = wid * 2 + rr;
        const int i = i0 + row;
        const float* rp = (const float*)(sm + SS_OFF + (uint32_t)row * SSP);
        const float* qwr = qw + row * 264;
        float tmp[32];
#pragma unroll
        for (int kk = 0; kk < 32; kk++) {
            int j = lane + kk * 32;
            int rel = j - i;
            rel = rel < -128 ? -128 : (rel > 128 ? 128 : rel);
            tmp[kk] = (rp[j] + qwr[rel + 128]) * 0.125f;
        }
        float mx = -1e30f;
#pragma unroll
        for (int kk = 0; kk < 32; kk++) mx = fmaxf(mx, tmp[kk]);
#pragma unroll
        for (int o = 16; o > 0; o >>= 1) mx = fmaxf(mx, __shfl_xor_sync(0xffffffffu, mx, o));
        float sum = 0.f;
#pragma unroll
        for (int kk = 0; kk < 32; kk++) { tmp[kk] = __expf(tmp[kk] - mx); sum += tmp[kk]; }
#pragma unroll
        for (int o = 16; o > 0; o >>= 1) sum += __shfl_xor_sync(0xffffffffu, sum, o);
        const float inv = 1.f / sum;

        uint32_t* whz = (uint32_t*)(sm + WRH_OFF + (uint32_t)row * WRP);
        uint32_t* wlz = (uint32_t*)(sm + WRL_OFF + (uint32_t)row * WRP);
        for (int idx = lane; idx < 140; idx += 32) { whz[idx] = 0u; wlz[idx] = 0u; }
        __syncwarp();

        __nv_bfloat16* wh_ = (__nv_bfloat16*)whz;
        __nv_bfloat16* wl_ = (__nv_bfloat16*)wlz;
        float s0 = 0.f, s2 = 0.f;
#pragma unroll
        for (int kk = 0; kk < 32; kk++) {
            int j = lane + kk * 32;
            float w = tmp[kk] * inv;
            __nv_bfloat16 h = __float2bfloat16(w);
            __nv_bfloat16 l = __float2bfloat16(w - __bfloat162float(h));
            *(__nv_bfloat16*)(sm + SS_OFF + (uint32_t)row * SSP + j * 2) = h;
            *(__nv_bfloat16*)(sm + SS_OFF + (uint32_t)row * SSP + 2064 + j * 2) = l;
            int dlt = j - i;
            if (dlt <= -128)      s0 += w;
            else if (dlt >= 128)  s2 += w;
            else { wh_[dlt + 128] = h; wl_[dlt + 128] = l; }
        }
#pragma unroll
        for (int o = 16; o > 0; o >>= 1) s0 += __shfl_xor_sync(0xffffffffu, s0, o);
#pragma unroll
        for (int o = 16; o > 0; o >>= 1) s2 += __shfl_xor_sync(0xffffffffu, s2, o);
        __syncwarp();
        if (lane == 0) {
            __nv_bfloat16 h0 = __float2bfloat16(s0);
            wh_[0] = h0; wl_[0] = __float2bfloat16(s0 - __bfloat162float(h0));
            __nv_bfloat16 h2 = __float2bfloat16(s2);
            wh_[256] = h2; wl_[256] = __float2bfloat16(s2 - __bfloat162float(h2));
        }
    }

    // ================= PV: 16 v tiles + 5 rel_v tiles, 1 barrier each ======
    auto issue_pv = [&](int tt) {
        uint32_t dst = sb + KV_OFF + (uint32_t)((tt + 2) % 3) * KV_BUF;
        if (tt < 16) issue_tile(g_vh, g_vl, bhrow + (size_t)tt * 64, 64, dst);
        else         issue_tile(g_rvh, g_rvl, (size_t)(tt - 16) * 64,
                                (tt == 20) ? 16 : 64, dst);
    };

    float o1[4] = {0.f,0.f,0.f,0.f}, o2[4] = {0.f,0.f,0.f,0.f}, o3[4] = {0.f,0.f,0.f,0.f};

    for (int vt = 0; vt < 21; vt++) {
        if (vt == 0 || vt == 20) { CP_WAIT(0); } else { CP_WAIT(1); }
        __syncthreads();
        if (vt == 0)            { issue_pv(1); issue_pv(2); }
        else if (vt + 2 <= 20)  issue_pv(vt + 2);

        const uint32_t vb = sb + KV_OFF + (uint32_t)((vt + 2) % 3) * KV_BUF;
        const uint32_t bbase = vb + (uint32_t)((lane & 7) + ((lane >> 3) & 1) * 8) * 144
                             + wk * 16;
        if (vt < 16) {
#pragma unroll
            for (int s = 0; s < 4; s++) {
                uint32_t aaddr = sb + SS_OFF + (uint32_t)(wq * 16 + (lane & 15)) * SSP
                               + (((lane >> 4) << 3) + vt * 64 + s * 16) * 2;
                uint32_t awh[4], awl[4];
                LDMX4(awh[0], awh[1], awh[2], awh[3], aaddr);
                LDMX4(awl[0], awl[1], awl[2], awl[3], aaddr + 2064);
                uint32_t bvh[2], bvl[2];
                LDMX2T(bvh[0], bvh[1], bbase + (uint32_t)(s * 16) * 144);
                LDMX2T(bvl[0], bvl[1], bbase + (uint32_t)(s * 16) * 144 + 64u * 144u);
                MMA16816(o1, awh, bvh);
                MMA16816(o2, awh, bvl);
                MMA16816(o3, awl, bvh);
            }
        } else if (vt < 20) {
            const uint32_t arow = (uint32_t)(wq * 16 + (lane & 15));
#pragma unroll
            for (int s = 0; s < 4; s++) {
                uint32_t acol = (((lane >> 4) << 3) + (vt - 16) * 64 + s * 16) * 2;
                uint32_t awh[4], awl[4];
                LDMX4(awh[0], awh[1], awh[2], awh[3], sb + WRH_OFF + arow * WRP + acol);
                LDMX4(awl[0], awl[1], awl[2], awl[3], sb + WRL_OFF + arow * WRP + acol);
                uint32_t bvh[2], bvl[2];
                LDMX2T(bvh[0], bvh[1], bbase + (uint32_t)(s * 16) * 144);
                LDMX2T(bvl[0], bvl[1], bbase + (uint32_t)(s * 16) * 144 + 64u * 144u);
                MMA16816(o1, awh, bvh);
                MMA16816(o2, awh, bvl);
                MMA16816(o3, awl, bvh);
            }
        } else {
            const uint32_t arow = (uint32_t)(wq * 16 + (lane & 15));
            uint32_t acol = (((lane >> 4) << 3) + 256) * 2;
            uint32_t awh[4], awl[4];
            LDMX4(awh[0], awh[1], awh[2], awh[3], sb + WRH_OFF + arow * WRP + acol);
            LDMX4(awl[0], awl[1], awl[2], awl[3], sb + WRL_OFF + arow * WRP + acol);
            uint32_t bvh[2], bvl[2];
            LDMX2T(bvh[0], bvh[1], bbase);
            LDMX2T(bvl[0], bvl[1], bbase + 16u * 144u);
            MMA16816(o1, awh, bvh);
            MMA16816(o2, awh, bvl);
            MMA16816(o3, awl, bvh);
        }
    }

    // ================= store out (headed fp32 -> g_attn) ===================
    {
        const int bb = bh >> 4, h = bh & 15;
        int row = i0 + wq * 16 + (lane >> 2);
        int d = h * 64 + wk * 8 + (lane & 3) * 2;
        *(float2*)(g_attn + ((size_t)bb * 1024 + row) * 1024 + d) =
            make_float2(o1[0] + o2[0] + o3[0], o1[1] + o2[1] + o3[1]);
        *(float2*)(g_attn + ((size_t)bb * 1024 + row + 8) * 1024 + d) =
            make_float2(o1[2] + o2[2] + o3[2], o1[3] + o2[3] + o3[3]);
    }
}

// ---------------------------------------------------------------------------
extern "C" void kernel_launch(void* const* d_in, const int* in_sizes, int n_in,
                              void* d_out, int out_size)
{
    const float* x     = (const float*)d_in[0];
    const float* Wq    = (const float*)d_in[1];
    const float* bq    = (const float*)d_in[2];
    const float* Wk    = (const float*)d_in[3];
    const float* bk    = (const float*)d_in[4];
    const float* Wv    = (const float*)d_in[5];
    const float* bv    = (const float*)d_in[6];
    const float* Wo    = (const float*)d_in[7];
    const float* bo    = (const float*)d_in[8];
    const float* rel_k = (const float*)d_in[9];
    const float* rel_v = (const float*)d_in[10];

    float *qr, *attn;
    __nv_bfloat16 *xh, *xl, *wh, *wl, *qh, *ql, *kh, *kl, *vh, *vl;
    cudaGetSymbolAddress((void**)&qr,   g_qr);
    cudaGetSymbolAddress((void**)&attn, g_attn);
    cudaGetSymbolAddress((void**)&xh,   g_xh);
    cudaGetSymbolAddress((void**)&xl,   g_xl);
    cudaGetSymbolAddress((void**)&wh,   g_wh);
    cudaGetSymbolAddress((void**)&wl,   g_wl);
    cudaGetSymbolAddress((void**)&qh,   g_qh);
    cudaGetSymbolAddress((void**)&ql,   g_ql);
    cudaGetSymbolAddress((void**)&kh,   g_kh);
    cudaGetSymbolAddress((void**)&kl,   g_kl);
    cudaGetSymbolAddress((void**)&vh,   g_vh);
    cudaGetSymbolAddress((void**)&vl,   g_vl);

    cudaFuncSetAttribute(gemm_mma, cudaFuncAttributeMaxDynamicSharedMemorySize, GEMM_SMEM);
    cudaFuncSetAttribute(gemm_qr,  cudaFuncAttributeMaxDynamicSharedMemorySize, QR_SMEM);
    cudaFuncSetAttribute(attn_mma, cudaFuncAttributeMaxDynamicSharedMemorySize, ATTN_SMEM);

    dim3 blk(256);
    dim3 gtc(Dd / 128, NROW / 128);                  // (8, 32)

    // x -> split bf16; rel_k / rel_v prep
    split_bf16_kernel<<<2048, blk>>>(x, xh, xl, (NROW * Dd) / 4);
    rel_prep<<<96, blk>>>(rel_k, rel_v);

    // projections -> split bf16 (headed)
    split_bf16_kernel<<<512, blk>>>(Wq, wh, wl, (Dd * Dd) / 4);
    gemm_mma<<<gtc, blk, GEMM_SMEM>>>(xh, xl, wh, wl, bq, nullptr, qh, ql, 1);
    split_bf16_kernel<<<512, blk>>>(Wk, wh, wl, (Dd * Dd) / 4);
    gemm_mma<<<gtc, blk, GEMM_SMEM>>>(xh, xl, wh, wl, bk, nullptr, kh, kl, 1);
    split_bf16_kernel<<<512, blk>>>(Wv, wh, wl, (Dd * Dd) / 4);
    gemm_mma<<<gtc, blk, GEMM_SMEM>>>(xh, xl, wh, wl, bv, nullptr, vh, vl, 1);

    // qr[b,h,i,p] = q_i . rel_k[p]   (MMA, padded N=384)
    gemm_qr<<<dim3(NPP / 128, BHS / 128), blk, QR_SMEM>>>(qr);

    // MMA attention core (512 threads)
    attn_mma<<<dim3(Ss / 32, Bv * Hh), 512, ATTN_SMEM>>>();

    // output projection -> d_out
    split_bf16_kernel<<<2048, blk>>>(attn, xh, xl, (NROW * Dd) / 4);
    split_bf16_kernel<<<512, blk>>>(Wo, wh, wl, (Dd * Dd) / 4);
    gemm_mma<<<gtc, blk, GEMM_SMEM>>>(xh, xl, wh, wl, bo, (float*)d_out, nullptr, nullptr, 0);
}

// round 9
// speedup vs baseline: 3.3010x; 1.0385x over previous
#include <cuda_runtime.h>
#include <cuda_bf16.h>
#include <cstdint>

#define Bv 4
#define Hh 16
#define Ss 1024
#define Dd 1024
#define HDd 64
#define NP 257
#define NPP 384
#define NROW (Bv*Ss)    // 4096
#define BHS (Bv*Hh*Ss)  // 65536

// ---------------- scratch (device globals: allocation-free) ----------------
__device__ float g_qr[(size_t)BHS * NPP];
__device__ float g_attn[(size_t)NROW * Dd];
__device__ __nv_bfloat16 g_qh[BHS * HDd];
__device__ __nv_bfloat16 g_ql[BHS * HDd];
__device__ __nv_bfloat16 g_kh[BHS * HDd];
__device__ __nv_bfloat16 g_kl[BHS * HDd];
__device__ __nv_bfloat16 g_vh[BHS * HDd];
__device__ __nv_bfloat16 g_vl[BHS * HDd];
__device__ __nv_bfloat16 g_rvh[272 * 64];
__device__ __nv_bfloat16 g_rvl[272 * 64];
__device__ __nv_bfloat16 g_rkh[NPP * 64];
__device__ __nv_bfloat16 g_rkl[NPP * 64];
__device__ __nv_bfloat16 g_xh[(size_t)NROW * Dd];
__device__ __nv_bfloat16 g_xl[(size_t)NROW * Dd];
__device__ __nv_bfloat16 g_wsp[8][(size_t)Dd * Dd];   // q,k,v,o  hi/lo interleaved: [2z]=hi,[2z+1]=lo

// ====================== PTX helpers (family-portable only) ======================
__device__ __forceinline__ uint32_t smem_u32(const void* p) {
    uint32_t a;
    asm("{ .reg .u64 t; cvta.to.shared.u64 t, %1; cvt.u32.u64 %0, t; }" : "=r"(a) : "l"(p));
    return a;
}

#define LDMX4(r0, r1, r2, r3, addr) \
    asm volatile("ldmatrix.sync.aligned.m8n8.x4.shared.b16 {%0,%1,%2,%3}, [%4];" \
                 : "=r"(r0), "=r"(r1), "=r"(r2), "=r"(r3) : "r"(addr))

#define LDMX2(r0, r1, addr) \
    asm volatile("ldmatrix.sync.aligned.m8n8.x2.shared.b16 {%0,%1}, [%2];" \
                 : "=r"(r0), "=r"(r1) : "r"(addr))

#define LDMX4T(r0, r1, r2, r3, addr) \
    asm volatile("ldmatrix.sync.aligned.m8n8.x4.trans.shared.b16 {%0,%1,%2,%3}, [%4];" \
                 : "=r"(r0), "=r"(r1), "=r"(r2), "=r"(r3) : "r"(addr))

#define LDMX2T(r0, r1, addr) \
    asm volatile("ldmatrix.sync.aligned.m8n8.x2.trans.shared.b16 {%0,%1}, [%2];" \
                 : "=r"(r0), "=r"(r1) : "r"(addr))

#define MMA16816(c, a, b) \
    asm volatile("mma.sync.aligned.m16n8k16.row.col.f32.bf16.bf16.f32 " \
                 "{%0,%1,%2,%3}, {%4,%5,%6,%7}, {%8,%9}, {%0,%1,%2,%3};" \
                 : "+f"((c)[0]), "+f"((c)[1]), "+f"((c)[2]), "+f"((c)[3]) \
                 : "r"((a)[0]), "r"((a)[1]), "r"((a)[2]), "r"((a)[3]), \
                   "r"((b)[0]), "r"((b)[1]))

#define CP_ASYNC16(s, g) \
    asm volatile("cp.async.cg.shared.global [%0], [%1], 16;" :: "r"(s), "l"(g))
#define CP_COMMIT() asm volatile("cp.async.commit_group;" ::: "memory")
#define CP_WAIT(n)  asm volatile("cp.async.wait_group %0;" :: "n"(n) : "memory")

// ---------------------------------------------------------------------------
// splits
// ---------------------------------------------------------------------------
__global__ void split_bf16_kernel(const float* __restrict__ in,
                                  __nv_bfloat16* __restrict__ hi,
                                  __nv_bfloat16* __restrict__ lo, int n4)
{
    int i = blockIdx.x * 512 + threadIdx.x;
#pragma unroll
    for (int rep = 0; rep < 2; rep++, i += 256) {
        if (i >= n4) return;
        float4 v = ((const float4*)in)[i];
        float vv[4] = {v.x, v.y, v.z, v.w};
        __nv_bfloat16 h[4], l[4];
#pragma unroll
        for (int j = 0; j < 4; j++) {
            h[j] = __float2bfloat16(vv[j]);
            l[j] = __float2bfloat16(vv[j] - __bfloat162float(h[j]));
        }
        ((__nv_bfloat162*)hi)[i * 2 + 0] = __nv_bfloat162(h[0], h[1]);
        ((__nv_bfloat162*)hi)[i * 2 + 1] = __nv_bfloat162(h[2], h[3]);
        ((__nv_bfloat162*)lo)[i * 2 + 0] = __nv_bfloat162(l[0], l[1]);
        ((__nv_bfloat162*)lo)[i * 2 + 1] = __nv_bfloat162(l[2], l[3]);
    }
}

// all 4 weights in one launch (blockIdx.y selects)
__global__ void split_w_kernel(const float* __restrict__ W0, const float* __restrict__ W1,
                               const float* __restrict__ W2, const float* __restrict__ W3)
{
    int z = blockIdx.y;
    const float* in = (z == 0 ? W0 : z == 1 ? W1 : z == 2 ? W2 : W3);
    __nv_bfloat16* hi = g_wsp[2 * z];
    __nv_bfloat16* lo = g_wsp[2 * z + 1];
    int i = blockIdx.x * 512 + threadIdx.x;
#pragma unroll
    for (int rep = 0; rep < 2; rep++, i += 256) {
        float4 v = ((const float4*)in)[i];
        float vv[4] = {v.x, v.y, v.z, v.w};
        __nv_bfloat16 h[4], l[4];
#pragma unroll
        for (int j = 0; j < 4; j++) {
            h[j] = __float2bfloat16(vv[j]);
            l[j] = __float2bfloat16(vv[j] - __bfloat162float(h[j]));
        }
        ((__nv_bfloat162*)hi)[i * 2 + 0] = __nv_bfloat162(h[0], h[1]);
        ((__nv_bfloat162*)hi)[i * 2 + 1] = __nv_bfloat162(h[2], h[3]);
        ((__nv_bfloat162*)lo)[i * 2 + 0] = __nv_bfloat162(l[0], l[1]);
        ((__nv_bfloat162*)lo)[i * 2 + 1] = __nv_bfloat162(l[2], l[3]);
    }
}

__global__ void rel_prep(const float* __restrict__ rel_k, const float* __restrict__ rel_v)
{
    int idx = blockIdx.x * 256 + threadIdx.x;
    if (idx < NPP * 64) {
        int p = idx >> 6, d = idx & 63;
        float v = (p < NP) ? rel_k[p * 64 + d] : 0.f;
        __nv_bfloat16 h = __float2bfloat16(v);
        g_rkh[idx] = h;
        g_rkl[idx] = __float2bfloat16(v - __bfloat162float(h));
    }
    if (idx < 272 * 64) {
        int p = idx >> 6, d = idx & 63;
        float v = (p < NP) ? rel_v[p * 64 + d] : 0.f;
        __nv_bfloat16 h = __float2bfloat16(v);
        g_rvh[idx] = h;
        g_rvl[idx] = __float2bfloat16(v - __bfloat162float(h));
    }
}

// ---------------------------------------------------------------------------
// shared GEMM body (128x128 tile, BK=32, double buffer, 1 barrier/chunk)
// ---------------------------------------------------------------------------
#define SPB 80
#define MAT_SM (128 * SPB)
#define BUF_SM (4 * MAT_SM)
#define GEMM_SMEM (2 * BUF_SM)

__device__ __forceinline__ void gemm_body(
    char* sm,
    const __nv_bfloat16* __restrict__ Ah_, const __nv_bfloat16* __restrict__ Al_,
    const __nv_bfloat16* __restrict__ Bh_, const __nv_bfloat16* __restrict__ Bl_,
    const float* __restrict__ bias, float* __restrict__ Cf,
    __nv_bfloat16* __restrict__ Ch, __nv_bfloat16* __restrict__ Cl, int headed)
{
    const uint32_t sb = smem_u32(sm);
    const int t    = threadIdx.x;
    const int wid  = t >> 5;
    const int lane = t & 31;
    const int m0 = blockIdx.y * 128;
    const int n0 = blockIdx.x * 128;
    const int wm = wid >> 2;
    const int wn = wid & 3;

    const char* gb0 = (const char*)(Ah_ + (size_t)m0 * 1024);
    const char* gb1 = (const char*)(Al_ + (size_t)m0 * 1024);
    const char* gb2 = (const char*)(Bh_ + (size_t)n0 * 1024);
    const char* gb3 = (const char*)(Bl_ + (size_t)n0 * 1024);

    auto issue = [&](int chunk, int buf) {
#pragma unroll
        for (int it = 0; it < 8; it++) {
            int id  = t + it * 256;
            int mat = id >> 9;
            int row = (id >> 2) & 127;
            int c16 = id & 3;
            const char* g = (mat == 0 ? gb0 : mat == 1 ? gb1 : mat == 2 ? gb2 : gb3);
            uint32_t sa = sb + buf * BUF_SM + mat * MAT_SM + row * SPB + c16 * 16;
            CP_ASYNC16(sa, g + (size_t)row * 2048 + chunk * 64 + c16 * 16);
        }
        CP_COMMIT();
    };

    float acc[4][4][4];
#pragma unroll
    for (int i = 0; i < 4; i++)
#pragma unroll
        for (int j = 0; j < 4; j++)
#pragma unroll
            for (int r = 0; r < 4; r++) acc[i][j][r] = 0.f;

    issue(0, 0);
    for (int c = 0; c < 32; c++) {
        const int buf = c & 1;
        CP_WAIT(0);
        __syncthreads();
        if (c + 1 < 32) issue(c + 1, buf ^ 1);

        const uint32_t Ahb = sb + buf * BUF_SM;
        const uint32_t Alb = Ahb + MAT_SM;
        const uint32_t Bhb = Ahb + 2 * MAT_SM;
        const uint32_t Blb = Ahb + 3 * MAT_SM;

#pragma unroll
        for (int s = 0; s < 2; s++) {
            uint32_t ah[4][4], al[4][4];
            const int arow = wm * 64 + (lane & 15);
            const int acolB = (((lane >> 4) << 3) + s * 16) * 2;
#pragma unroll
            for (int mf = 0; mf < 4; mf++) {
                uint32_t ad = Ahb + (uint32_t)(arow + mf * 16) * SPB + acolB;
                LDMX4(ah[mf][0], ah[mf][1], ah[mf][2], ah[mf][3], ad);
                ad = Alb + (uint32_t)(arow + mf * 16) * SPB + acolB;
                LDMX4(al[mf][0], al[mf][1], al[mf][2], al[mf][3], ad);
            }
            uint32_t bh[4][2], bl[4][2];
            const int brow = wn * 32 + (lane & 7) + ((lane >> 4) << 3);
            const int bcolB = ((((lane >> 3) & 1) << 3) + s * 16) * 2;
#pragma unroll
            for (int g = 0; g < 2; g++) {
                uint32_t r0, r1, r2, r3;
                uint32_t bd = Bhb + (uint32_t)(brow + g * 16) * SPB + bcolB;
                LDMX4(r0, r1, r2, r3, bd);
                bh[g * 2][0] = r0; bh[g * 2][1] = r1;
                bh[g * 2 + 1][0] = r2; bh[g * 2 + 1][1] = r3;
                bd = Blb + (uint32_t)(brow + g * 16) * SPB + bcolB;
                LDMX4(r0, r1, r2, r3, bd);
                bl[g * 2][0] = r0; bl[g * 2][1] = r1;
                bl[g * 2 + 1][0] = r2; bl[g * 2 + 1][1] = r3;
            }
#pragma unroll
            for (int mf = 0; mf < 4; mf++)
#pragma unroll
                for (int nf = 0; nf < 4; nf++) {
                    MMA16816(acc[mf][nf], ah[mf], bh[nf]);
                    MMA16816(acc[mf][nf], ah[mf], bl[nf]);
                    MMA16816(acc[mf][nf], al[mf], bh[nf]);
                }
        }
    }

#pragma unroll
    for (int mf = 0; mf < 4; mf++) {
#pragma unroll
        for (int nf = 0; nf < 4; nf++) {
            int m = m0 + wm * 64 + mf * 16 + (lane >> 2);
            int n = n0 + wn * 32 + nf * 8 + (lane & 3) * 2;
            float p0 = acc[mf][nf][0] + bias[n];
            float p1 = acc[mf][nf][1] + bias[n + 1];
            float p2 = acc[mf][nf][2] + bias[n];
            float p3 = acc[mf][nf][3] + bias[n + 1];
            size_t off0, off1;
            if (headed) {
                int h = n >> 6, d = n & 63;
                int bb = m >> 10, s1 = m & 1023;
                off0 = ((((size_t)bb * Hh + h) << 10) + s1) * HDd + d;
                off1 = ((((size_t)bb * Hh + h) << 10) + s1 + 8) * HDd + d;
            } else {
                off0 = (size_t)m * 1024 + n;
                off1 = (size_t)(m + 8) * 1024 + n;
            }
            if (Cf) {
                *(float2*)(Cf + off0) = make_float2(p0, p1);
                *(float2*)(Cf + off1) = make_float2(p2, p3);
            }
            if (Ch) {
                __nv_bfloat16 h0 = __float2bfloat16(p0), h1 = __float2bfloat16(p1);
                __nv_bfloat16 h2 = __float2bfloat16(p2), h3 = __float2bfloat16(p3);
                *(__nv_bfloat162*)(Ch + off0) = __nv_bfloat162(h0, h1);
                *(__nv_bfloat162*)(Ch + off1) = __nv_bfloat162(h2, h3);
                __nv_bfloat16 l0 = __float2bfloat16(p0 - __bfloat162float(h0));
                __nv_bfloat16 l1 = __float2bfloat16(p1 - __bfloat162float(h1));
                __nv_bfloat16 l2 = __float2bfloat16(p2 - __bfloat162float(h2));
                __nv_bfloat16 l3 = __float2bfloat16(p3 - __bfloat162float(h3));
                *(__nv_bfloat162*)(Cl + off0) = __nv_bfloat162(l0, l1);
                *(__nv_bfloat162*)(Cl + off1) = __nv_bfloat162(l2, l3);
            }
        }
    }
}

// QKV merged: blockIdx.z selects weight/bias/output
__global__ __launch_bounds__(256, 2)
void gemm_qkv(const float* __restrict__ bq, const float* __restrict__ bk,
              const float* __restrict__ bv)
{
    extern __shared__ char sm[];
    int z = blockIdx.z;
    const float* bias = (z == 0 ? bq : z == 1 ? bk : bv);
    __nv_bfloat16* Ch = (z == 0 ? g_qh : z == 1 ? g_kh : g_vh);
    __nv_bfloat16* Cl = (z == 0 ? g_ql : z == 1 ? g_kl : g_vl);
    gemm_body(sm, g_xh, g_xl, g_wsp[2 * z], g_wsp[2 * z + 1], bias,
              nullptr, Ch, Cl, 1);
}

// single GEMM (output projection)
__global__ __launch_bounds__(256, 2)
void gemm_mma(const __nv_bfloat16* __restrict__ Ah_, const __nv_bfloat16* __restrict__ Al_,
              const __nv_bfloat16* __restrict__ Bh_, const __nv_bfloat16* __restrict__ Bl_,
              const float* __restrict__ bias, float* __restrict__ Cf)
{
    extern __shared__ char sm[];
    gemm_body(sm, Ah_, Al_, Bh_, Bl_, bias, Cf, nullptr, nullptr, 0);
}

// ---------------------------------------------------------------------------
// qr GEMM via MMA (unchanged)
// ---------------------------------------------------------------------------
#define QSPB 144
#define QMAT (128 * QSPB)
#define QR_SMEM (4 * QMAT)

__global__ __launch_bounds__(256)
void gemm_qr(float* __restrict__ C)
{
    extern __shared__ char sm[];
    const uint32_t sb = smem_u32(sm);
    const int t = threadIdx.x, lane = t & 31, wid = t >> 5;
    const int m0 = blockIdx.y * 128;
    const int n0 = blockIdx.x * 128;
    const int wm = wid >> 2, wn = wid & 3;

    const char* gb0 = (const char*)(g_qh + (size_t)m0 * 64);
    const char* gb1 = (const char*)(g_ql + (size_t)m0 * 64);
    const char* gb2 = (const char*)(g_rkh + (size_t)n0 * 64);
    const char* gb3 = (const char*)(g_rkl + (size_t)n0 * 64);

#pragma unroll
    for (int it = 0; it < 16; it++) {
        int id = t + it * 256;
        int mat = id >> 10;
        int row = (id >> 3) & 127;
        int c16 = id & 7;
        const char* g = (mat == 0 ? gb0 : mat == 1 ? gb1 : mat == 2 ? gb2 : gb3);
        CP_ASYNC16(sb + mat * QMAT + row * QSPB + c16 * 16,
                   g + (size_t)row * 128 + c16 * 16);
    }
    CP_COMMIT();
    CP_WAIT(0);
    __syncthreads();

    float acc[4][4][4];
#pragma unroll
    for (int i = 0; i < 4; i++)
#pragma unroll
        for (int j = 0; j < 4; j++)
#pragma unroll
            for (int r = 0; r < 4; r++) acc[i][j][r] = 0.f;

    const uint32_t Ahb = sb, Alb = sb + QMAT, Bhb = sb + 2 * QMAT, Blb = sb + 3 * QMAT;
#pragma unroll
    for (int s = 0; s < 4; s++) {
        uint32_t ah[4][4], al[4][4];
        const int arow = wm * 64 + (lane & 15);
        const int acolB = (((lane >> 4) << 3) + s * 16) * 2;
#pragma unroll
        for (int mf = 0; mf < 4; mf++) {
            uint32_t ad = Ahb + (uint32_t)(arow + mf * 16) * QSPB + acolB;
            LDMX4(ah[mf][0], ah[mf][1], ah[mf][2], ah[mf][3], ad);
            ad = Alb + (uint32_t)(arow + mf * 16) * QSPB + acolB;
            LDMX4(al[mf][0], al[mf][1], al[mf][2], al[mf][3], ad);
        }
        uint32_t bh[4][2], bl[4][2];
        const int brow = wn * 32 + (lane & 7) + ((lane >> 4) << 3);
        const int bcolB = ((((lane >> 3) & 1) << 3) + s * 16) * 2;
#pragma unroll
        for (int g = 0; g < 2; g++) {
            uint32_t r0, r1, r2, r3;
            uint32_t bd = Bhb + (uint32_t)(brow + g * 16) * QSPB + bcolB;
            LDMX4(r0, r1, r2, r3, bd);
            bh[g * 2][0] = r0; bh[g * 2][1] = r1;
            bh[g * 2 + 1][0] = r2; bh[g * 2 + 1][1] = r3;
            bd = Blb + (uint32_t)(brow + g * 16) * QSPB + bcolB;
            LDMX4(r0, r1, r2, r3, bd);
            bl[g * 2][0] = r0; bl[g * 2][1] = r1;
            bl[g * 2 + 1][0] = r2; bl[g * 2 + 1][1] = r3;
        }
#pragma unroll
        for (int mf = 0; mf < 4; mf++)
#pragma unroll
            for (int nf = 0; nf < 4; nf++) {
                MMA16816(acc[mf][nf], ah[mf], bh[nf]);
                MMA16816(acc[mf][nf], ah[mf], bl[nf]);
                MMA16816(acc[mf][nf], al[mf], bh[nf]);
            }
    }

#pragma unroll
    for (int mf = 0; mf < 4; mf++)
#pragma unroll
        for (int nf = 0; nf < 4; nf++) {
            int m = m0 + wm * 64 + mf * 16 + (lane >> 2);
            int n = n0 + wn * 32 + nf * 8 + (lane & 3) * 2;
            *(float2*)(C + (size_t)m * NPP + n) =
                make_float2(acc[mf][nf][0], acc[mf][nf][1]);
            *(float2*)(C + (size_t)(m + 8) * NPP + n) =
                make_float2(acc[mf][nf][2], acc[mf][nf][3]);
        }
}

// ---------------------------------------------------------------------------
// MMA attention core. Block = (bh, 32 query rows). 512 threads, 16 warps.
// Scores: warp (wq2, wk8).  PV: warp (wm2, wn4 n16, ws2 k-split) + reduction.
// ---------------------------------------------------------------------------
#define SSP  4112u
#define WRP  560u
#define Q_OFF   0u
#define KV_OFF  9216u
#define KV_BUF  18432u
#define SS_OFF  64512u
#define WRH_OFF 196096u
#define WRL_OFF 214016u
#define ATTN_SMEM 231936

__global__ __launch_bounds__(512, 1)
void attn_mma()
{
    extern __shared__ char sm[];
    const uint32_t sb = smem_u32(sm);
    const int t = threadIdx.x, lane = t & 31, wid = t >> 5;
    const int bh = blockIdx.y;
    const int i0 = blockIdx.x * 32;

    auto issue_tile = [&](const __nv_bfloat16* sh, const __nv_bfloat16* sl,
                          size_t row0, int nrows, uint32_t dst) {
#pragma unroll
        for (int it = 0; it < 2; it++) {
            int id = t + it * 512;
            if (id < nrows * 16) {
                int sel = id / (nrows * 8);
                int rid = id % (nrows * 8);
                int row = rid >> 3, c16 = rid & 7;
                const __nv_bfloat16* s = (sel ? sl : sh) + (row0 + row) * 64 + c16 * 8;
                CP_ASYNC16(dst + (uint32_t)sel * (nrows * 144) + row * 144 + c16 * 16, s);
            }
        }
        CP_COMMIT();
    };

    const size_t bhrow = (size_t)bh * 1024;

    issue_tile(g_qh, g_ql, bhrow + i0, 32, sb + Q_OFF);
    issue_tile(g_kh, g_kl, bhrow, 64, sb + KV_OFF);
    issue_tile(g_kh, g_kl, bhrow + 64, 64, sb + KV_OFF + KV_BUF);

    // ================= scores: warp (wq, wk), 1 barrier/tile ===============
    {
        const int wq = wid >> 3;        // 0..1
        const int wk = wid & 7;         // 0..7
        uint32_t qhf[4][4], qlf[4][4];

        for (int kt = 0; kt < 16; kt++) {
            if (kt < 15) { CP_WAIT(1); } else { CP_WAIT(0); }
            __syncthreads();
            if (kt + 2 < 16)
                issue_tile(g_kh, g_kl, bhrow + (size_t)(kt + 2) * 64, 64,
                           sb + KV_OFF + (uint32_t)((kt + 2) % 3) * KV_BUF);

            if (kt == 0) {
#pragma unroll
                for (int s = 0; s < 4; s++) {
                    uint32_t a = sb + Q_OFF + (uint32_t)(wq * 16 + (lane & 15)) * 144
                               + (((lane >> 4) << 3) + s * 16) * 2;
                    LDMX4(qhf[s][0], qhf[s][1], qhf[s][2], qhf[s][3], a);
                    LDMX4(qlf[s][0], qlf[s][1], qlf[s][2], qlf[s][3], a + 4608);
                }
            }

            float a1[4] = {0.f,0.f,0.f,0.f}, a2[4] = {0.f,0.f,0.f,0.f}, a3[4] = {0.f,0.f,0.f,0.f};
            const uint32_t kb = sb + KV_OFF + (uint32_t)(kt % 3) * KV_BUF;
#pragma unroll
            for (int s = 0; s < 4; s++) {
                uint32_t addr = kb + (uint32_t)(wk * 8 + (lane & 7)) * 144
                              + ((((lane >> 3) & 1) * 8) + s * 16) * 2;
                uint32_t bh2[2], bl2[2];
                LDMX2(bh2[0], bh2[1], addr);
                LDMX2(bl2[0], bl2[1], addr + 9216);
                MMA16816(a1, qhf[s], bh2);
                MMA16816(a2, qhf[s], bl2);
                MMA16816(a3, qlf[s], bh2);
            }
            {
                int row = wq * 16 + (lane >> 2);
                int col = kt * 64 + wk * 8 + (lane & 3) * 2;
                *(float2*)(sm + SS_OFF + (uint32_t)row * SSP + col * 4) =
                    make_float2(a1[0] + a2[0] + a3[0], a1[1] + a2[1] + a3[1]);
                *(float2*)(sm + SS_OFF + (uint32_t)(row + 8) * SSP + col * 4) =
                    make_float2(a1[2] + a2[2] + a3[2], a1[3] + a2[3] + a3[3]);
            }
        }
    }
    __syncthreads();

    // ================= stage qr window (32 x 264 f32) ======================
    float* qw = (float*)(sm + KV_OFF);
    {
        const float* qrb = g_qr + (size_t)bh * Ss * NPP + (size_t)i0 * NPP;
#pragma unroll
        for (int kk = 0; kk < 4; kk++) {
            int id = kk * 512 + t;
            int row = id >> 6, c4 = id & 63;
            float4 v = *(const float4*)(qrb + (size_t)row * NPP + c4 * 4);
            *(float4*)(qw + row * 264 + c4 * 4) = v;
        }
        if (t < 32) qw[t * 264 + 256] = qrb[(size_t)t * NPP + 256];
    }
    __syncthreads();

    // prefetch v tile 0 -> buf 2 (disjoint from qw)
    issue_tile(g_vh, g_vl, bhrow, 64, sb + KV_OFF + 2u * KV_BUF);

    // ================= softmax (fused bias, reg-resident), 2 rows/warp =====
    for (int rr = 0; rr < 2; rr++) {
        const int row = wid * 2 + rr;
        const int i = i0 + row;
        const float* rp = (const float*)(sm + SS_OFF + (uint32_t)row * SSP);
        const float* qwr = qw + row * 264;
        float tmp[32];
#pragma unroll
        for (int kk = 0; kk < 32; kk++) {
            int j = lane + kk * 32;
            int rel = j - i;
            rel = rel < -128 ? -128 : (rel > 128 ? 128 : rel);
            tmp[kk] = (rp[j] + qwr[rel + 128]) * 0.125f;
        }
        float mx = -1e30f;
#pragma unroll
        for (int kk = 0; kk < 32; kk++) mx = fmaxf(mx, tmp[kk]);
#pragma unroll
        for (int o = 16; o > 0; o >>= 1) mx = fmaxf(mx, __shfl_xor_sync(0xffffffffu, mx, o));
        float sum = 0.f;
#pragma unroll
        for (int kk = 0; kk < 32; kk++) { tmp[kk] = __expf(tmp[kk] - mx); sum += tmp[kk]; }
#pragma unroll
        for (int o = 16; o > 0; o >>= 1) sum += __shfl_xor_sync(0xffffffffu, sum, o);
        const float inv = 1.f / sum;

        uint32_t* whz = (uint32_t*)(sm + WRH_OFF + (uint32_t)row * WRP);
        uint32_t* wlz = (uint32_t*)(sm + WRL_OFF + (uint32_t)row * WRP);
        for (int idx = lane; idx < 140; idx += 32) { whz[idx] = 0u; wlz[idx] = 0u; }
        __syncwarp();

        __nv_bfloat16* wh_ = (__nv_bfloat16*)whz;
        __nv_bfloat16* wl_ = (__nv_bfloat16*)wlz;
        float s0 = 0.f, s2 = 0.f;
#pragma unroll
        for (int kk = 0; kk < 32; kk++) {
            int j = lane + kk * 32;
            float w = tmp[kk] * inv;
            __nv_bfloat16 h = __float2bfloat16(w);
            __nv_bfloat16 l = __float2bfloat16(w - __bfloat162float(h));
            *(__nv_bfloat16*)(sm + SS_OFF + (uint32_t)row * SSP + j * 2) = h;
            *(__nv_bfloat16*)(sm + SS_OFF + (uint32_t)row * SSP + 2064 + j * 2) = l;
            int dlt = j - i;
            if (dlt <= -128)      s0 += w;
            else if (dlt >= 128)  s2 += w;
            else { wh_[dlt + 128] = h; wl_[dlt + 128] = l; }
        }
#pragma unroll
        for (int o = 16; o > 0; o >>= 1) s0 += __shfl_xor_sync(0xffffffffu, s0, o);
#pragma unroll
        for (int o = 16; o > 0; o >>= 1) s2 += __shfl_xor_sync(0xffffffffu, s2, o);
        __syncwarp();
        if (lane == 0) {
            __nv_bfloat16 h0 = __float2bfloat16(s0);
            wh_[0] = h0; wl_[0] = __float2bfloat16(s0 - __bfloat162float(h0));
            __nv_bfloat16 h2 = __float2bfloat16(s2);
            wh_[256] = h2; wl_[256] = __float2bfloat16(s2 - __bfloat162float(h2));
        }
    }

    // ================= PV: warp (wm2, wn4 n16, ws2 k-split) ================
    const int wm = wid >> 3;            // 0..1
    const int wn = (wid >> 1) & 3;      // 0..3
    const int ws = wid & 1;             // 0..1

    auto issue_pv = [&](int tt) {
        uint32_t dst = sb + KV_OFF + (uint32_t)((tt + 2) % 3) * KV_BUF;
        if (tt < 16) issue_tile(g_vh, g_vl, bhrow + (size_t)tt * 64, 64, dst);
        else         issue_tile(g_rvh, g_rvl, (size_t)(tt - 16) * 64,
                                (tt == 20) ? 16 : 64, dst);
    };

    float o1[2][4] = {{0.f,0.f,0.f,0.f},{0.f,0.f,0.f,0.f}};
    float o2[2][4] = {{0.f,0.f,0.f,0.f},{0.f,0.f,0.f,0.f}};
    float o3[2][4] = {{0.f,0.f,0.f,0.f},{0.f,0.f,0.f,0.f}};

    for (int vt = 0; vt < 21; vt++) {
        if (vt == 0 || vt == 20) { CP_WAIT(0); } else { CP_WAIT(1); }
        __syncthreads();
        if (vt == 0)            { issue_pv(1); issue_pv(2); }
        else if (vt + 2 <= 20)  issue_pv(vt + 2);

        const uint32_t vb = sb + KV_OFF + (uint32_t)((vt + 2) % 3) * KV_BUF;
        const int nsi = (vt == 20) ? ((ws == 0) ? 1 : 0) : 2;
        const uint32_t nrowsB = (vt == 20) ? 16u : 64u;
#pragma unroll 2
        for (int si = 0; si < nsi; si++) {
            const int s = (vt == 20) ? 0 : (ws * 2 + si);
            uint32_t awh[4], awl[4];
            if (vt < 16) {
                uint32_t aaddr = sb + SS_OFF + (uint32_t)(wm * 16 + (lane & 15)) * SSP
                               + (((lane >> 4) << 3) + vt * 64 + s * 16) * 2;
                LDMX4(awh[0], awh[1], awh[2], awh[3], aaddr);
                LDMX4(awl[0], awl[1], awl[2], awl[3], aaddr + 2064);
            } else {
                uint32_t arow = (uint32_t)(wm * 16 + (lane & 15));
                uint32_t acol = (((lane >> 4) << 3) + (vt - 16) * 64 + s * 16) * 2;
                LDMX4(awh[0], awh[1], awh[2], awh[3], sb + WRH_OFF + arow * WRP + acol);
                LDMX4(awl[0], awl[1], awl[2], awl[3], sb + WRL_OFF + arow * WRP + acol);
            }
            uint32_t baddr = vb + (uint32_t)(s * 16 + (lane & 7) + ((lane >> 3) & 1) * 8) * 144
                           + (uint32_t)(wn * 16 + ((lane >> 4) << 3)) * 2;
            uint32_t bvh[4], bvl[4];
            LDMX4T(bvh[0], bvh[1], bvh[2], bvh[3], baddr);
            LDMX4T(bvl[0], bvl[1], bvl[2], bvl[3], baddr + nrowsB * 144u);
#pragma unroll
            for (int nf = 0; nf < 2; nf++) {
                MMA16816(o1[nf], awh, (&bvh[nf * 2]));
                MMA16816(o2[nf], awh, (&bvl[nf * 2]));
                MMA16816(o3[nf], awl, (&bvh[nf * 2]));
            }
        }
    }

    // merge chains
    float of[2][4];
#pragma unroll
    for (int nf = 0; nf < 2; nf++)
#pragma unroll
        for (int r = 0; r < 4; r++)
            of[nf][r] = o1[nf][r] + o2[nf][r] + o3[nf][r];

    // cross-warp reduce over ws pairs
    __syncthreads();                       // all PV buffer reads complete
    float* red = (float*)(sm + KV_OFF);    // 8KB scratch
    const int widx = wm * 4 + wn;
    if (ws == 1) {
#pragma unroll
        for (int nf = 0; nf < 2; nf++)
            *(float4*)&red[((widx * 2 + nf) * 32 + lane) * 4] =
                make_float4(of[nf][0], of[nf][1], of[nf][2], of[nf][3]);
    }
    __syncthreads();
    if (ws == 0) {
        const int bb = bh >> 4, h = bh & 15;
        int row = i0 + wm * 16 + (lane >> 2);
#pragma unroll
        for (int nf = 0; nf < 2; nf++) {
            float4 v = *(const float4*)&red[((widx * 2 + nf) * 32 + lane) * 4];
            int d = h * 64 + wn * 16 + nf * 8 + (lane & 3) * 2;
            *(float2*)(g_attn + ((size_t)bb * 1024 + row) * 1024 + d) =
                make_float2(of[nf][0] + v.x, of[nf][1] + v.y);
            *(float2*)(g_attn + ((size_t)bb * 1024 + row + 8) * 1024 + d) =
                make_float2(of[nf][2] + v.z, of[nf][3] + v.w);
        }
    }
}

// ---------------------------------------------------------------------------
extern "C" void kernel_launch(void* const* d_in, const int* in_sizes, int n_in,
                              void* d_out, int out_size)
{
    const float* x     = (const float*)d_in[0];
    const float* Wq    = (const float*)d_in[1];
    const float* bq    = (const float*)d_in[2];
    const float* Wk    = (const float*)d_in[3];
    const float* bk    = (const float*)d_in[4];
    const float* Wv    = (const float*)d_in[5];
    const float* bv    = (const float*)d_in[6];
    const float* Wo    = (const float*)d_in[7];
    const float* bo    = (const float*)d_in[8];
    const float* rel_k = (const float*)d_in[9];
    const float* rel_v = (const float*)d_in[10];

    float *qr, *attn;
    __nv_bfloat16 *xh, *xl, *woh, *wol;
    cudaGetSymbolAddress((void**)&qr,   g_qr);
    cudaGetSymbolAddress((void**)&attn, g_attn);
    cudaGetSymbolAddress((void**)&xh,   g_xh);
    cudaGetSymbolAddress((void**)&xl,   g_xl);
    cudaGetSymbolAddress((void**)&woh,  g_wsp);
    wol = woh + 7 * (size_t)Dd * Dd;
    woh = woh + 6 * (size_t)Dd * Dd;

    cudaFuncSetAttribute(gemm_qkv, cudaFuncAttributeMaxDynamicSharedMemorySize, GEMM_SMEM);
    cudaFuncSetAttribute(gemm_mma, cudaFuncAttributeMaxDynamicSharedMemorySize, GEMM_SMEM);
    cudaFuncSetAttribute(gemm_qr,  cudaFuncAttributeMaxDynamicSharedMemorySize, QR_SMEM);
    cudaFuncSetAttribute(attn_mma, cudaFuncAttributeMaxDynamicSharedMemorySize, ATTN_SMEM);

    dim3 blk(256);

    // prep: x split, all 4 weight splits, rel tables
    split_bf16_kernel<<<2048, blk>>>(x, xh, xl, (NROW * Dd) / 4);
    split_w_kernel<<<dim3(512, 4), blk>>>(Wq, Wk, Wv, Wo);
    rel_prep<<<96, blk>>>(rel_k, rel_v);

    // merged QKV projections (768 CTAs)
    gemm_qkv<<<dim3(Dd / 128, NROW / 128, 3), blk, GEMM_SMEM>>>(bq, bk, bv);

    // qr[b,h,i,p] = q_i . rel_k[p]
    gemm_qr<<<dim3(NPP / 128, BHS / 128), blk, QR_SMEM>>>(qr);

    // attention core
    attn_mma<<<dim3(Ss / 32, Bv * Hh), 512, ATTN_SMEM>>>();

    // output projection -> d_out
    split_bf16_kernel<<<2048, blk>>>(attn, xh, xl, (NROW * Dd) / 4);
    gemm_mma<<<dim3(Dd / 128, NROW / 128), blk, GEMM_SMEM>>>(xh, xl, woh, wol, bo, (float*)d_out);
}

// round 10
// speedup vs baseline: 3.3541x; 1.0161x over previous
#include <cuda_runtime.h>
#include <cuda_bf16.h>
#include <cstdint>

#define Bv 4
#define Hh 16
#define Ss 1024
#define Dd 1024
#define HDd 64
#define NP 257
#define NPP 384
#define NROW (Bv*Ss)    // 4096
#define BHS (Bv*Hh*Ss)  // 65536

// ---------------- scratch (device globals: allocation-free) ----------------
__device__ __nv_bfloat16 g_qh[BHS * HDd];
__device__ __nv_bfloat16 g_ql[BHS * HDd];
__device__ __nv_bfloat16 g_kh[BHS * HDd];
__device__ __nv_bfloat16 g_kl[BHS * HDd];
__device__ __nv_bfloat16 g_vh[BHS * HDd];
__device__ __nv_bfloat16 g_vl[BHS * HDd];
__device__ __nv_bfloat16 g_rvh[272 * 64];
__device__ __nv_bfloat16 g_rvl[272 * 64];
__device__ __nv_bfloat16 g_rkh[NPP * 64];
__device__ __nv_bfloat16 g_rkl[NPP * 64];
__device__ __nv_bfloat16 g_xh[(size_t)NROW * Dd];
__device__ __nv_bfloat16 g_xl[(size_t)NROW * Dd];
__device__ __nv_bfloat16 g_wsp[8][(size_t)Dd * Dd];   // q,k,v,o hi/lo: [2z]=hi,[2z+1]=lo

// ====================== PTX helpers (family-portable only) ======================
__device__ __forceinline__ uint32_t smem_u32(const void* p) {
    uint32_t a;
    asm("{ .reg .u64 t; cvta.to.shared.u64 t, %1; cvt.u32.u64 %0, t; }" : "=r"(a) : "l"(p));
    return a;
}

#define LDMX4(r0, r1, r2, r3, addr) \
    asm volatile("ldmatrix.sync.aligned.m8n8.x4.shared.b16 {%0,%1,%2,%3}, [%4];" \
                 : "=r"(r0), "=r"(r1), "=r"(r2), "=r"(r3) : "r"(addr))

#define LDMX2(r0, r1, addr) \
    asm volatile("ldmatrix.sync.aligned.m8n8.x2.shared.b16 {%0,%1}, [%2];" \
                 : "=r"(r0), "=r"(r1) : "r"(addr))

#define LDMX4T(r0, r1, r2, r3, addr) \
    asm volatile("ldmatrix.sync.aligned.m8n8.x4.trans.shared.b16 {%0,%1,%2,%3}, [%4];" \
                 : "=r"(r0), "=r"(r1), "=r"(r2), "=r"(r3) : "r"(addr))

#define MMA16816(c, a, b) \
    asm volatile("mma.sync.aligned.m16n8k16.row.col.f32.bf16.bf16.f32 " \
                 "{%0,%1,%2,%3}, {%4,%5,%6,%7}, {%8,%9}, {%0,%1,%2,%3};" \
                 : "+f"((c)[0]), "+f"((c)[1]), "+f"((c)[2]), "+f"((c)[3]) \
                 : "r"((a)[0]), "r"((a)[1]), "r"((a)[2]), "r"((a)[3]), \
                   "r"((b)[0]), "r"((b)[1]))

#define CP_ASYNC16(s, g) \
    asm volatile("cp.async.cg.shared.global [%0], [%1], 16;" :: "r"(s), "l"(g))
#define CP_COMMIT() asm volatile("cp.async.commit_group;" ::: "memory")
#define CP_WAIT(n)  asm volatile("cp.async.wait_group %0;" :: "n"(n) : "memory")

// ---------------------------------------------------------------------------
// splits
// ---------------------------------------------------------------------------
__global__ void split_bf16_kernel(const float* __restrict__ in,
                                  __nv_bfloat16* __restrict__ hi,
                                  __nv_bfloat16* __restrict__ lo, int n4)
{
    int i = blockIdx.x * 512 + threadIdx.x;
#pragma unroll
    for (int rep = 0; rep < 2; rep++, i += 256) {
        if (i >= n4) return;
        float4 v = ((const float4*)in)[i];
        float vv[4] = {v.x, v.y, v.z, v.w};
        __nv_bfloat16 h[4], l[4];
#pragma unroll
        for (int j = 0; j < 4; j++) {
            h[j] = __float2bfloat16(vv[j]);
            l[j] = __float2bfloat16(vv[j] - __bfloat162float(h[j]));
        }
        ((__nv_bfloat162*)hi)[i * 2 + 0] = __nv_bfloat162(h[0], h[1]);
        ((__nv_bfloat162*)hi)[i * 2 + 1] = __nv_bfloat162(h[2], h[3]);
        ((__nv_bfloat162*)lo)[i * 2 + 0] = __nv_bfloat162(l[0], l[1]);
        ((__nv_bfloat162*)lo)[i * 2 + 1] = __nv_bfloat162(l[2], l[3]);
    }
}

__global__ void split_w_kernel(const float* __restrict__ W0, const float* __restrict__ W1,
                               const float* __restrict__ W2, const float* __restrict__ W3)
{
    int z = blockIdx.y;
    const float* in = (z == 0 ? W0 : z == 1 ? W1 : z == 2 ? W2 : W3);
    __nv_bfloat16* hi = g_wsp[2 * z];
    __nv_bfloat16* lo = g_wsp[2 * z + 1];
    int i = blockIdx.x * 512 + threadIdx.x;
#pragma unroll
    for (int rep = 0; rep < 2; rep++, i += 256) {
        float4 v = ((const float4*)in)[i];
        float vv[4] = {v.x, v.y, v.z, v.w};
        __nv_bfloat16 h[4], l[4];
#pragma unroll
        for (int j = 0; j < 4; j++) {
            h[j] = __float2bfloat16(vv[j]);
            l[j] = __float2bfloat16(vv[j] - __bfloat162float(h[j]));
        }
        ((__nv_bfloat162*)hi)[i * 2 + 0] = __nv_bfloat162(h[0], h[1]);
        ((__nv_bfloat162*)hi)[i * 2 + 1] = __nv_bfloat162(h[2], h[3]);
        ((__nv_bfloat162*)lo)[i * 2 + 0] = __nv_bfloat162(l[0], l[1]);
        ((__nv_bfloat162*)lo)[i * 2 + 1] = __nv_bfloat162(l[2], l[3]);
    }
}

__global__ void rel_prep(const float* __restrict__ rel_k, const float* __restrict__ rel_v)
{
    int idx = blockIdx.x * 256 + threadIdx.x;
    if (idx < NPP * 64) {
        int p = idx >> 6, d = idx & 63;
        float v = (p < NP) ? rel_k[p * 64 + d] : 0.f;
        __nv_bfloat16 h = __float2bfloat16(v);
        g_rkh[idx] = h;
        g_rkl[idx] = __float2bfloat16(v - __bfloat162float(h));
    }
    if (idx < 272 * 64) {
        int p = idx >> 6, d = idx & 63;
        float v = (p < NP) ? rel_v[p * 64 + d] : 0.f;
        __nv_bfloat16 h = __float2bfloat16(v);
        g_rvh[idx] = h;
        g_rvl[idx] = __float2bfloat16(v - __bfloat162float(h));
    }
}

// ---------------------------------------------------------------------------
// shared GEMM body (128x128 tile, BK=32, double buffer, 1 barrier/chunk)
// ---------------------------------------------------------------------------
#define SPB 80
#define MAT_SM (128 * SPB)
#define BUF_SM (4 * MAT_SM)
#define GEMM_SMEM (2 * BUF_SM)

__device__ __forceinline__ void gemm_body(
    char* sm,
    const __nv_bfloat16* __restrict__ Ah_, const __nv_bfloat16* __restrict__ Al_,
    const __nv_bfloat16* __restrict__ Bh_, const __nv_bfloat16* __restrict__ Bl_,
    const float* __restrict__ bias, float* __restrict__ Cf,
    __nv_bfloat16* __restrict__ Ch, __nv_bfloat16* __restrict__ Cl, int headed)
{
    const uint32_t sb = smem_u32(sm);
    const int t    = threadIdx.x;
    const int wid  = t >> 5;
    const int lane = t & 31;
    const int m0 = blockIdx.y * 128;
    const int n0 = blockIdx.x * 128;
    const int wm = wid >> 2;
    const int wn = wid & 3;

    const char* gb0 = (const char*)(Ah_ + (size_t)m0 * 1024);
    const char* gb1 = (const char*)(Al_ + (size_t)m0 * 1024);
    const char* gb2 = (const char*)(Bh_ + (size_t)n0 * 1024);
    const char* gb3 = (const char*)(Bl_ + (size_t)n0 * 1024);

    auto issue = [&](int chunk, int buf) {
#pragma unroll
        for (int it = 0; it < 8; it++) {
            int id  = t + it * 256;
            int mat = id >> 9;
            int row = (id >> 2) & 127;
            int c16 = id & 3;
            const char* g = (mat == 0 ? gb0 : mat == 1 ? gb1 : mat == 2 ? gb2 : gb3);
            uint32_t sa = sb + buf * BUF_SM + mat * MAT_SM + row * SPB + c16 * 16;
            CP_ASYNC16(sa, g + (size_t)row * 2048 + chunk * 64 + c16 * 16);
        }
        CP_COMMIT();
    };

    float acc[4][4][4];
#pragma unroll
    for (int i = 0; i < 4; i++)
#pragma unroll
        for (int j = 0; j < 4; j++)
#pragma unroll
            for (int r = 0; r < 4; r++) acc[i][j][r] = 0.f;

    issue(0, 0);
    for (int c = 0; c < 32; c++) {
        const int buf = c & 1;
        CP_WAIT(0);
        __syncthreads();
        if (c + 1 < 32) issue(c + 1, buf ^ 1);

        const uint32_t Ahb = sb + buf * BUF_SM;
        const uint32_t Alb = Ahb + MAT_SM;
        const uint32_t Bhb = Ahb + 2 * MAT_SM;
        const uint32_t Blb = Ahb + 3 * MAT_SM;

#pragma unroll
        for (int s = 0; s < 2; s++) {
            uint32_t ah[4][4], al[4][4];
            const int arow = wm * 64 + (lane & 15);
            const int acolB = (((lane >> 4) << 3) + s * 16) * 2;
#pragma unroll
            for (int mf = 0; mf < 4; mf++) {
                uint32_t ad = Ahb + (uint32_t)(arow + mf * 16) * SPB + acolB;
                LDMX4(ah[mf][0], ah[mf][1], ah[mf][2], ah[mf][3], ad);
                ad = Alb + (uint32_t)(arow + mf * 16) * SPB + acolB;
                LDMX4(al[mf][0], al[mf][1], al[mf][2], al[mf][3], ad);
            }
            uint32_t bh[4][2], bl[4][2];
            const int brow = wn * 32 + (lane & 7) + ((lane >> 4) << 3);
            const int bcolB = ((((lane >> 3) & 1) << 3) + s * 16) * 2;
#pragma unroll
            for (int g = 0; g < 2; g++) {
                uint32_t r0, r1, r2, r3;
                uint32_t bd = Bhb + (uint32_t)(brow + g * 16) * SPB + bcolB;
                LDMX4(r0, r1, r2, r3, bd);
                bh[g * 2][0] = r0; bh[g * 2][1] = r1;
                bh[g * 2 + 1][0] = r2; bh[g * 2 + 1][1] = r3;
                bd = Blb + (uint32_t)(brow + g * 16) * SPB + bcolB;
                LDMX4(r0, r1, r2, r3, bd);
                bl[g * 2][0] = r0; bl[g * 2][1] = r1;
                bl[g * 2 + 1][0] = r2; bl[g * 2 + 1][1] = r3;
            }
#pragma unroll
            for (int mf = 0; mf < 4; mf++)
#pragma unroll
                for (int nf = 0; nf < 4; nf++) {
                    MMA16816(acc[mf][nf], ah[mf], bh[nf]);
                    MMA16816(acc[mf][nf], ah[mf], bl[nf]);
                    MMA16816(acc[mf][nf], al[mf], bh[nf]);
                }
        }
    }

#pragma unroll
    for (int mf = 0; mf < 4; mf++) {
#pragma unroll
        for (int nf = 0; nf < 4; nf++) {
            int m = m0 + wm * 64 + mf * 16 + (lane >> 2);
            int n = n0 + wn * 32 + nf * 8 + (lane & 3) * 2;
            float p0 = acc[mf][nf][0] + bias[n];
            float p1 = acc[mf][nf][1] + bias[n + 1];
            float p2 = acc[mf][nf][2] + bias[n];
            float p3 = acc[mf][nf][3] + bias[n + 1];
            size_t off0, off1;
            if (headed) {
                int h = n >> 6, d = n & 63;
                int bb = m >> 10, s1 = m & 1023;
                off0 = ((((size_t)bb * Hh + h) << 10) + s1) * HDd + d;
                off1 = ((((size_t)bb * Hh + h) << 10) + s1 + 8) * HDd + d;
            } else {
                off0 = (size_t)m * 1024 + n;
                off1 = (size_t)(m + 8) * 1024 + n;
            }
            if (Cf) {
                *(float2*)(Cf + off0) = make_float2(p0, p1);
                *(float2*)(Cf + off1) = make_float2(p2, p3);
            }
            if (Ch) {
                __nv_bfloat16 h0 = __float2bfloat16(p0), h1 = __float2bfloat16(p1);
                __nv_bfloat16 h2 = __float2bfloat16(p2), h3 = __float2bfloat16(p3);
                *(__nv_bfloat162*)(Ch + off0) = __nv_bfloat162(h0, h1);
                *(__nv_bfloat162*)(Ch + off1) = __nv_bfloat162(h2, h3);
                __nv_bfloat16 l0 = __float2bfloat16(p0 - __bfloat162float(h0));
                __nv_bfloat16 l1 = __float2bfloat16(p1 - __bfloat162float(h1));
                __nv_bfloat16 l2 = __float2bfloat16(p2 - __bfloat162float(h2));
                __nv_bfloat16 l3 = __float2bfloat16(p3 - __bfloat162float(h3));
                *(__nv_bfloat162*)(Cl + off0) = __nv_bfloat162(l0, l1);
                *(__nv_bfloat162*)(Cl + off1) = __nv_bfloat162(l2, l3);
            }
        }
    }
}

__global__ __launch_bounds__(256, 2)
void gemm_qkv(const float* __restrict__ bq, const float* __restrict__ bk,
              const float* __restrict__ bv)
{
    extern __shared__ char sm[];
    int z = blockIdx.z;
    const float* bias = (z == 0 ? bq : z == 1 ? bk : bv);
    __nv_bfloat16* Ch = (z == 0 ? g_qh : z == 1 ? g_kh : g_vh);
    __nv_bfloat16* Cl = (z == 0 ? g_ql : z == 1 ? g_kl : g_vl);
    gemm_body(sm, g_xh, g_xl, g_wsp[2 * z], g_wsp[2 * z + 1], bias,
              nullptr, Ch, Cl, 1);
}

__global__ __launch_bounds__(256, 2)
void gemm_mma(const __nv_bfloat16* __restrict__ Ah_, const __nv_bfloat16* __restrict__ Al_,
              const __nv_bfloat16* __restrict__ Bh_, const __nv_bfloat16* __restrict__ Bl_,
              const float* __restrict__ bias, float* __restrict__ Cf)
{
    extern __shared__ char sm[];
    gemm_body(sm, Ah_, Al_, Bh_, Bl_, bias, Cf, nullptr, nullptr, 0);
}

// ---------------------------------------------------------------------------
// MMA attention core. Block = (bh, 32 query rows). 512 threads, 16 warps.
// Unified 21-tile pipeline: 16 K tiles (scores) + 5 rel_k tiles (bias window
// qw[32x264] computed in-CTA via MMA using cached q fragments).
// Per-row wr block (pitch 1104): fp32 qw first, overwritten by wh/wl bf16
// after warp-local reads. Output emitted as split bf16 directly to g_xh/g_xl.
// ---------------------------------------------------------------------------
#define SSP  4112u
#define WRP  1104u
#define Q_OFF   0u
#define KV_OFF  9216u
#define KV_BUF  18432u
#define SS_OFF  64512u
#define WR_OFF  196096u
#define ATTN_SMEM 231424

__global__ __launch_bounds__(512, 1)
void attn_mma()
{
    extern __shared__ char sm[];
    const uint32_t sb = smem_u32(sm);
    const int t = threadIdx.x, lane = t & 31, wid = t >> 5;
    const int bh = blockIdx.y;
    const int i0 = blockIdx.x * 32;

    auto issue_tile = [&](const __nv_bfloat16* sh, const __nv_bfloat16* sl,
                          size_t row0, int nrows, uint32_t dst) {
#pragma unroll
        for (int it = 0; it < 2; it++) {
            int id = t + it * 512;
            if (id < nrows * 16) {
                int sel = id / (nrows * 8);
                int rid = id % (nrows * 8);
                int row = rid >> 3, c16 = rid & 7;
                const __nv_bfloat16* s = (sel ? sl : sh) + (row0 + row) * 64 + c16 * 8;
                CP_ASYNC16(dst + (uint32_t)sel * (nrows * 144) + row * 144 + c16 * 16, s);
            }
        }
        CP_COMMIT();
    };

    const size_t bhrow = (size_t)bh * 1024;

    issue_tile(g_qh, g_ql, bhrow + i0, 32, sb + Q_OFF);
    issue_tile(g_kh, g_kl, bhrow, 64, sb + KV_OFF);
    issue_tile(g_kh, g_kl, bhrow + 64, 64, sb + KV_OFF + KV_BUF);

    // ========= unified scores (g<16) + bias window (g>=16) pipeline ========
    {
        const int wq = wid >> 3;        // 0..1
        const int wk = wid & 7;         // 0..7
        uint32_t qhf[4][4], qlf[4][4];

        for (int g = 0; g < 21; g++) {
            if (g < 20) { CP_WAIT(1); } else { CP_WAIT(0); }
            __syncthreads();
            if (g + 2 < 21) {
                int tt = g + 2;
                uint32_t dst = sb + KV_OFF + (uint32_t)(tt % 3) * KV_BUF;
                if (tt < 16) issue_tile(g_kh, g_kl, bhrow + (size_t)tt * 64, 64, dst);
                else         issue_tile(g_rkh, g_rkl, (size_t)(tt - 16) * 64, 64, dst);
            }

            if (g == 0) {
#pragma unroll
                for (int s = 0; s < 4; s++) {
                    uint32_t a = sb + Q_OFF + (uint32_t)(wq * 16 + (lane & 15)) * 144
                               + (((lane >> 4) << 3) + s * 16) * 2;
                    LDMX4(qhf[s][0], qhf[s][1], qhf[s][2], qhf[s][3], a);
                    LDMX4(qlf[s][0], qlf[s][1], qlf[s][2], qlf[s][3], a + 4608);
                }
            }

            float a1[4] = {0.f,0.f,0.f,0.f}, a2[4] = {0.f,0.f,0.f,0.f}, a3[4] = {0.f,0.f,0.f,0.f};
            const uint32_t kb = sb + KV_OFF + (uint32_t)(g % 3) * KV_BUF;
#pragma unroll
            for (int s = 0; s < 4; s++) {
                uint32_t addr = kb + (uint32_t)(wk * 8 + (lane & 7)) * 144
                              + ((((lane >> 3) & 1) * 8) + s * 16) * 2;
                uint32_t bh2[2], bl2[2];
                LDMX2(bh2[0], bh2[1], addr);
                LDMX2(bl2[0], bl2[1], addr + 9216);
                MMA16816(a1, qhf[s], bh2);
                MMA16816(a2, qhf[s], bl2);
                MMA16816(a3, qlf[s], bh2);
            }
            int row = wq * 16 + (lane >> 2);
            if (g < 16) {
                int col = g * 64 + wk * 8 + (lane & 3) * 2;
                *(float2*)(sm + SS_OFF + (uint32_t)row * SSP + col * 4) =
                    make_float2(a1[0] + a2[0] + a3[0], a1[1] + a2[1] + a3[1]);
                *(float2*)(sm + SS_OFF + (uint32_t)(row + 8) * SSP + col * 4) =
                    make_float2(a1[2] + a2[2] + a3[2], a1[3] + a2[3] + a3[3]);
            } else {
                int col = (g - 16) * 64 + wk * 8 + (lane & 3) * 2;
                if (col <= 274) {
                    *(float2*)(sm + WR_OFF + (uint32_t)row * WRP + col * 4) =
                        make_float2(a1[0] + a2[0] + a3[0], a1[1] + a2[1] + a3[1]);
                    *(float2*)(sm + WR_OFF + (uint32_t)(row + 8) * WRP + col * 4) =
                        make_float2(a1[2] + a2[2] + a3[2], a1[3] + a2[3] + a3[3]);
                }
            }
        }
    }
    __syncthreads();   // scores + qw visible; all KV buffer reads complete

    // prefetch v tile 0 -> buf 2 (overlaps softmax)
    issue_tile(g_vh, g_vl, bhrow, 64, sb + KV_OFF + 2u * KV_BUF);

    // ================= softmax (fused bias, reg-resident), 2 rows/warp =====
    for (int rr = 0; rr < 2; rr++) {
        const int row = wid * 2 + rr;
        const int i = i0 + row;
        const float* rp = (const float*)(sm + SS_OFF + (uint32_t)row * SSP);
        const float* qwr = (const float*)(sm + WR_OFF + (uint32_t)row * WRP);
        float tmp[32];
#pragma unroll
        for (int kk = 0; kk < 32; kk++) {
            int j = lane + kk * 32;
            int rel = j - i;
            rel = rel < -128 ? -128 : (rel > 128 ? 128 : rel);
            tmp[kk] = (rp[j] + qwr[rel + 128]) * 0.125f;
        }
        float mx = -1e30f;
#pragma unroll
        for (int kk = 0; kk < 32; kk++) mx = fmaxf(mx, tmp[kk]);
#pragma unroll
        for (int o = 16; o > 0; o >>= 1) mx = fmaxf(mx, __shfl_xor_sync(0xffffffffu, mx, o));
        float sum = 0.f;
#pragma unroll
        for (int kk = 0; kk < 32; kk++) { tmp[kk] = __expf(tmp[kk] - mx); sum += tmp[kk]; }
#pragma unroll
        for (int o = 16; o > 0; o >>= 1) sum += __shfl_xor_sync(0xffffffffu, sum, o);
        const float inv = 1.f / sum;

        __syncwarp();   // all qw reads of this row done before overwrite
        uint32_t* wrz = (uint32_t*)(sm + WR_OFF + (uint32_t)row * WRP);
        for (int idx = lane; idx < 276; idx += 32) wrz[idx] = 0u;
        __syncwarp();

        __nv_bfloat16* wh_ = (__nv_bfloat16*)wrz;          // [0,544)
        __nv_bfloat16* wl_ = wh_ + 280;                    // offset 560 bytes
        float s0 = 0.f, s2 = 0.f;
#pragma unroll
        for (int kk = 0; kk < 32; kk++) {
            int j = lane + kk * 32;
            float w = tmp[kk] * inv;
            __nv_bfloat16 h = __float2bfloat16(w);
            __nv_bfloat16 l = __float2bfloat16(w - __bfloat162float(h));
            *(__nv_bfloat16*)(sm + SS_OFF + (uint32_t)row * SSP + j * 2) = h;
            *(__nv_bfloat16*)(sm + SS_OFF + (uint32_t)row * SSP + 2064 + j * 2) = l;
            int dlt = j - i;
            if (dlt <= -128)      s0 += w;
            else if (dlt >= 128)  s2 += w;
            else { wh_[dlt + 128] = h; wl_[dlt + 128] = l; }
        }
#pragma unroll
        for (int o = 16; o > 0; o >>= 1) s0 += __shfl_xor_sync(0xffffffffu, s0, o);
#pragma unroll
        for (int o = 16; o > 0; o >>= 1) s2 += __shfl_xor_sync(0xffffffffu, s2, o);
        __syncwarp();
        if (lane == 0) {
            __nv_bfloat16 h0 = __float2bfloat16(s0);
            wh_[0] = h0; wl_[0] = __float2bfloat16(s0 - __bfloat162float(h0));
            __nv_bfloat16 h2 = __float2bfloat16(s2);
            wh_[256] = h2; wl_[256] = __float2bfloat16(s2 - __bfloat162float(h2));
        }
    }

    // ================= PV: warp (wm2, wn4 n16, ws2 k-split) ================
    const int wm = wid >> 3;            // 0..1
    const int wn = (wid >> 1) & 3;      // 0..3
    const int ws = wid & 1;             // 0..1

    auto issue_pv = [&](int tt) {
        uint32_t dst = sb + KV_OFF + (uint32_t)((tt + 2) % 3) * KV_BUF;
        if (tt < 16) issue_tile(g_vh, g_vl, bhrow + (size_t)tt * 64, 64, dst);
        else         issue_tile(g_rvh, g_rvl, (size_t)(tt - 16) * 64,
                                (tt == 20) ? 16 : 64, dst);
    };

    float o1[2][4] = {{0.f,0.f,0.f,0.f},{0.f,0.f,0.f,0.f}};
    float o2[2][4] = {{0.f,0.f,0.f,0.f},{0.f,0.f,0.f,0.f}};
    float o3[2][4] = {{0.f,0.f,0.f,0.f},{0.f,0.f,0.f,0.f}};

    for (int vt = 0; vt < 21; vt++) {
        if (vt == 0 || vt == 20) { CP_WAIT(0); } else { CP_WAIT(1); }
        __syncthreads();
        if (vt == 0)            { issue_pv(1); issue_pv(2); }
        else if (vt + 2 <= 20)  issue_pv(vt + 2);

        const uint32_t vb = sb + KV_OFF + (uint32_t)((vt + 2) % 3) * KV_BUF;
        const int nsi = (vt == 20) ? ((ws == 0) ? 1 : 0) : 2;
        const uint32_t nrowsB = (vt == 20) ? 16u : 64u;
#pragma unroll 2
        for (int si = 0; si < nsi; si++) {
            const int s = (vt == 20) ? 0 : (ws * 2 + si);
            uint32_t awh[4], awl[4];
            if (vt < 16) {
                uint32_t aaddr = sb + SS_OFF + (uint32_t)(wm * 16 + (lane & 15)) * SSP
                               + (((lane >> 4) << 3) + vt * 64 + s * 16) * 2;
                LDMX4(awh[0], awh[1], awh[2], awh[3], aaddr);
                LDMX4(awl[0], awl[1], awl[2], awl[3], aaddr + 2064);
            } else {
                uint32_t abase = sb + WR_OFF + (uint32_t)(wm * 16 + (lane & 15)) * WRP;
                uint32_t acol = (((lane >> 4) << 3) + (vt - 16) * 64 + s * 16) * 2;
                LDMX4(awh[0], awh[1], awh[2], awh[3], abase + acol);
                LDMX4(awl[0], awl[1], awl[2], awl[3], abase + 560 + acol);
            }
            uint32_t baddr = vb + (uint32_t)(s * 16 + (lane & 7) + ((lane >> 3) & 1) * 8) * 144
                           + (uint32_t)(wn * 16 + ((lane >> 4) << 3)) * 2;
            uint32_t bvh[4], bvl[4];
            LDMX4T(bvh[0], bvh[1], bvh[2], bvh[3], baddr);
            LDMX4T(bvl[0], bvl[1], bvl[2], bvl[3], baddr + nrowsB * 144u);
#pragma unroll
            for (int nf = 0; nf < 2; nf++) {
                MMA16816(o1[nf], awh, (&bvh[nf * 2]));
                MMA16816(o2[nf], awh, (&bvl[nf * 2]));
                MMA16816(o3[nf], awl, (&bvh[nf * 2]));
            }
        }
    }

    // merge chains
    float of[2][4];
#pragma unroll
    for (int nf = 0; nf < 2; nf++)
#pragma unroll
        for (int r = 0; r < 4; r++)
            of[nf][r] = o1[nf][r] + o2[nf][r] + o3[nf][r];

    // cross-warp reduce over ws pairs; emit split bf16 directly
    __syncthreads();
    float* red = (float*)(sm + KV_OFF);
    const int widx = wm * 4 + wn;
    if (ws == 1) {
#pragma unroll
        for (int nf = 0; nf < 2; nf++)
            *(float4*)&red[((widx * 2 + nf) * 32 + lane) * 4] =
                make_float4(of[nf][0], of[nf][1], of[nf][2], of[nf][3]);
    }
    __syncthreads();
    if (ws == 0) {
        const int bb = bh >> 4, h = bh & 15;
        int row = i0 + wm * 16 + (lane >> 2);
#pragma unroll
        for (int nf = 0; nf < 2; nf++) {
            float4 v = *(const float4*)&red[((widx * 2 + nf) * 32 + lane) * 4];
            float f0 = of[nf][0] + v.x, f1 = of[nf][1] + v.y;
            float f2 = of[nf][2] + v.z, f3 = of[nf][3] + v.w;
            int d = h * 64 + wn * 16 + nf * 8 + (lane & 3) * 2;
            size_t off0 = ((size_t)bb * 1024 + row) * 1024 + d;
            size_t off1 = off0 + 8 * 1024;
            __nv_bfloat16 h0 = __float2bfloat16(f0), h1 = __float2bfloat16(f1);
            __nv_bfloat16 h2 = __float2bfloat16(f2), h3 = __float2bfloat16(f3);
            *(__nv_bfloat162*)(g_xh + off0) = __nv_bfloat162(h0, h1);
            *(__nv_bfloat162*)(g_xh + off1) = __nv_bfloat162(h2, h3);
            __nv_bfloat16 l0 = __float2bfloat16(f0 - __bfloat162float(h0));
            __nv_bfloat16 l1 = __float2bfloat16(f1 - __bfloat162float(h1));
            __nv_bfloat16 l2 = __float2bfloat16(f2 - __bfloat162float(h2));
            __nv_bfloat16 l3 = __float2bfloat16(f3 - __bfloat162float(h3));
            *(__nv_bfloat162*)(g_xl + off0) = __nv_bfloat162(l0, l1);
            *(__nv_bfloat162*)(g_xl + off1) = __nv_bfloat162(l2, l3);
        }
    }
}

// ---------------------------------------------------------------------------
extern "C" void kernel_launch(void* const* d_in, const int* in_sizes, int n_in,
                              void* d_out, int out_size)
{
    const float* x     = (const float*)d_in[0];
    const float* Wq    = (const float*)d_in[1];
    const float* bq    = (const float*)d_in[2];
    const float* Wk    = (const float*)d_in[3];
    const float* bk    = (const float*)d_in[4];
    const float* Wv    = (const float*)d_in[5];
    const float* bv    = (const float*)d_in[6];
    const float* Wo    = (const float*)d_in[7];
    const float* bo    = (const float*)d_in[8];
    const float* rel_k = (const float*)d_in[9];
    const float* rel_v = (const float*)d_in[10];

    __nv_bfloat16 *xh, *xl, *woh, *wol;
    cudaGetSymbolAddress((void**)&xh,  g_xh);
    cudaGetSymbolAddress((void**)&xl,  g_xl);
    cudaGetSymbolAddress((void**)&woh, g_wsp);
    wol = woh + 7 * (size_t)Dd * Dd;
    woh = woh + 6 * (size_t)Dd * Dd;

    cudaFuncSetAttribute(gemm_qkv, cudaFuncAttributeMaxDynamicSharedMemorySize, GEMM_SMEM);
    cudaFuncSetAttribute(gemm_mma, cudaFuncAttributeMaxDynamicSharedMemorySize, GEMM_SMEM);
    cudaFuncSetAttribute(attn_mma, cudaFuncAttributeMaxDynamicSharedMemorySize, ATTN_SMEM);

    dim3 blk(256);

    // prep: x split, weight splits, rel tables
    split_bf16_kernel<<<2048, blk>>>(x, xh, xl, (NROW * Dd) / 4);
    split_w_kernel<<<dim3(512, 4), blk>>>(Wq, Wk, Wv, Wo);
    rel_prep<<<96, blk>>>(rel_k, rel_v);

    // merged QKV projections (768 CTAs)
    gemm_qkv<<<dim3(Dd / 128, NROW / 128, 3), blk, GEMM_SMEM>>>(bq, bk, bv);

    // attention core (bias window computed in-CTA; output -> g_xh/g_xl split)
    attn_mma<<<dim3(Ss / 32, Bv * Hh), 512, ATTN_SMEM>>>();

    // output projection -> d_out
    gemm_mma<<<dim3(Dd / 128, NROW / 128), blk, GEMM_SMEM>>>(xh, xl, woh, wol, bo, (float*)d_out);
}